// round 1
// baseline (speedup 1.0000x reference)
#include <cuda_runtime.h>
#include <math.h>
#include <float.h>
#include <stdint.h>

#define N_NODES 50000
#define N_EDGES 800000
#define SLOPE 0.2f

// ---------------- scratch (device globals; no allocation allowed) ----------
__device__ float g_gl[N_NODES * 128];
__device__ float g_gr[N_NODES * 128];
__device__ float g_sc[N_EDGES * 4];
__device__ float g_m[N_NODES * 4];
__device__ float g_den[N_NODES * 4];
__device__ float g_acc[N_NODES * 128];
__device__ float g_h[N_NODES * 128];

__device__ __forceinline__ void atomicMaxF(float* a, float v) {
    if (v >= 0.f) atomicMax((int*)a, __float_as_int(v));
    else          atomicMin((unsigned int*)a, __float_as_uint(v));
}

__global__ void k_init_neg(float* p, int n) {
    int i = blockIdx.x * blockDim.x + threadIdx.x;
    if (i < n) p[i] = -FLT_MAX;
}

// ---------------- SGEMM: C[M,Ncols] = A[M,128] @ W[128,Ncols] --------------
// BM=64, BN=64, BK=64 (two K stages), 256 threads, 4x4 register tile.
__global__ __launch_bounds__(256) void k_gemm128(
    const float* __restrict__ A, const float* __restrict__ W,
    float* __restrict__ C, int M, int Ncols)
{
    __shared__ float As[64][68];   // [row][k] padded, 16B-aligned rows
    __shared__ float Ws[64][64];   // [k][col]

    const int tid = threadIdx.x;
    const int tx = tid & 15;       // col group (4 cols each)
    const int ty = tid >> 4;       // row group (4 rows each)
    const int r0 = blockIdx.y * 64;
    const int c0 = blockIdx.x * 64;

    float acc[4][4] = {};

    for (int kk = 0; kk < 128; kk += 64) {
        __syncthreads();
        // load A tile: 64 rows x 64 k (float4 per thread x4)
        #pragma unroll
        for (int i = 0; i < 4; i++) {
            int f = tid + i * 256;          // 0..1023 float4s
            int row = f >> 4;               // 16 float4 per row
            int k4 = f & 15;
            float4 a = make_float4(0.f, 0.f, 0.f, 0.f);
            if (r0 + row < M)
                a = *(const float4*)(A + (size_t)(r0 + row) * 128 + kk + k4 * 4);
            *(float4*)(&As[row][k4 * 4]) = a;
        }
        // load W tile: 64 k x 64 cols
        #pragma unroll
        for (int i = 0; i < 16; i++) {
            int f = tid + i * 256;
            int k = f >> 6, c = f & 63;
            Ws[k][c] = (c0 + c < Ncols) ? W[(size_t)(kk + k) * Ncols + c0 + c] : 0.f;
        }
        __syncthreads();

        #pragma unroll 16
        for (int k = 0; k < 64; k++) {
            float4 b = *(const float4*)(&Ws[k][tx * 4]);
            float a0 = As[ty * 4 + 0][k];
            float a1 = As[ty * 4 + 1][k];
            float a2 = As[ty * 4 + 2][k];
            float a3 = As[ty * 4 + 3][k];
            acc[0][0] += a0 * b.x; acc[0][1] += a0 * b.y; acc[0][2] += a0 * b.z; acc[0][3] += a0 * b.w;
            acc[1][0] += a1 * b.x; acc[1][1] += a1 * b.y; acc[1][2] += a1 * b.z; acc[1][3] += a1 * b.w;
            acc[2][0] += a2 * b.x; acc[2][1] += a2 * b.y; acc[2][2] += a2 * b.z; acc[2][3] += a2 * b.w;
            acc[3][0] += a3 * b.x; acc[3][1] += a3 * b.y; acc[3][2] += a3 * b.z; acc[3][3] += a3 * b.w;
        }
    }

    #pragma unroll
    for (int i = 0; i < 4; i++) {
        int r = r0 + ty * 4 + i;
        if (r >= M) continue;
        #pragma unroll
        for (int j = 0; j < 4; j++) {
            int c = c0 + tx * 4 + j;
            if (c < Ncols) C[(size_t)r * Ncols + c] = acc[i][j];
        }
    }
}

// ---------------- edge pass 1 (H=4, F=32): score + segment max ------------
// warp per edge; lane l owns elements l+32j (j = head)
__global__ __launch_bounds__(256) void k_score_h4(
    const float* __restrict__ gl, const float* __restrict__ gr,
    const float* __restrict__ att,
    const int* __restrict__ src, const int* __restrict__ dst,
    float* __restrict__ sc, float* __restrict__ m)
{
    int e = blockIdx.x * 8 + (threadIdx.x >> 5);
    if (e >= N_EDGES) return;
    int l = threadIdx.x & 31;
    int s = src[e], d = dst[e];
    const float* pl = gl + (size_t)s * 128;
    const float* pr = gr + (size_t)d * 128;
    float p[4];
    #pragma unroll
    for (int j = 0; j < 4; j++) {
        float v = pl[32 * j + l] + pr[32 * j + l];
        v = v > 0.f ? v : SLOPE * v;
        p[j] = v * __ldg(&att[32 * j + l]);
    }
    #pragma unroll
    for (int off = 16; off > 0; off >>= 1) {
        #pragma unroll
        for (int j = 0; j < 4; j++) p[j] += __shfl_xor_sync(0xffffffffu, p[j], off);
    }
    if (l < 4) {
        float v = (l == 0) ? p[0] : (l == 1) ? p[1] : (l == 2) ? p[2] : p[3];
        sc[(size_t)e * 4 + l] = v;
        atomicMaxF(&m[(size_t)d * 4 + l], v);
    }
}

// ---------------- edge pass 2 (H=4): exp, denom, weighted aggregate -------
__global__ __launch_bounds__(256) void k_aggr_h4(
    const float* __restrict__ gl,
    const int* __restrict__ src, const int* __restrict__ dst,
    const float* __restrict__ sc, const float* __restrict__ m,
    float* __restrict__ den, float* __restrict__ acc)
{
    int e = blockIdx.x * 8 + (threadIdx.x >> 5);
    if (e >= N_EDGES) return;
    int l = threadIdx.x & 31;
    int s = src[e], d = dst[e];
    float w[4];
    #pragma unroll
    for (int j = 0; j < 4; j++)
        w[j] = expf(sc[(size_t)e * 4 + j] - m[(size_t)d * 4 + j]);
    if (l < 4) {
        float v = (l == 0) ? w[0] : (l == 1) ? w[1] : (l == 2) ? w[2] : w[3];
        atomicAdd(&den[(size_t)d * 4 + l], v);
    }
    const float* pl = gl + (size_t)s * 128;
    float* pa = acc + (size_t)d * 128;
    #pragma unroll
    for (int j = 0; j < 4; j++)
        atomicAdd(&pa[32 * j + l], w[j] * pl[32 * j + l]);
}

// ---------------- normalize + activation (H=4) ----------------------------
__global__ __launch_bounds__(256) void k_final_h4(
    const float* __restrict__ acc, const float* __restrict__ den,
    float* __restrict__ h, int act)
{
    int idx = blockIdx.x * blockDim.x + threadIdx.x;
    if (idx >= N_NODES * 128) return;
    int n = idx >> 7;
    int j = (idx >> 5) & 3;
    float v = acc[idx] / (den[n * 4 + j] + 1e-16f);
    h[idx] = act ? fmaxf(v, 0.f) : (v > 0.f ? v : expm1f(v));
}

// ---------------- layer 3 (H=1, F=40) --------------------------------------
__global__ __launch_bounds__(256) void k_score_h1(
    const float* __restrict__ gl, const float* __restrict__ gr,
    const float* __restrict__ att,
    const int* __restrict__ src, const int* __restrict__ dst,
    float* __restrict__ sc, float* __restrict__ m)
{
    int e = blockIdx.x * 8 + (threadIdx.x >> 5);
    if (e >= N_EDGES) return;
    int l = threadIdx.x & 31;
    int s = src[e], d = dst[e];
    const float* pl = gl + (size_t)s * 40;
    const float* pr = gr + (size_t)d * 40;
    float v = pl[l] + pr[l];
    v = v > 0.f ? v : SLOPE * v;
    float p = v * __ldg(&att[l]);
    if (l < 8) {
        float v2 = pl[32 + l] + pr[32 + l];
        v2 = v2 > 0.f ? v2 : SLOPE * v2;
        p += v2 * __ldg(&att[32 + l]);
    }
    #pragma unroll
    for (int off = 16; off > 0; off >>= 1) p += __shfl_xor_sync(0xffffffffu, p, off);
    if (l == 0) {
        sc[e] = p;
        atomicMaxF(&m[d], p);
    }
}

__global__ __launch_bounds__(256) void k_aggr_h1(
    const float* __restrict__ gl,
    const int* __restrict__ src, const int* __restrict__ dst,
    const float* __restrict__ sc, const float* __restrict__ m,
    float* __restrict__ den, float* __restrict__ acc)
{
    int e = blockIdx.x * 8 + (threadIdx.x >> 5);
    if (e >= N_EDGES) return;
    int l = threadIdx.x & 31;
    int s = src[e], d = dst[e];
    float w = expf(sc[e] - m[d]);
    if (l == 0) atomicAdd(&den[d], w);
    const float* pl = gl + (size_t)s * 40;
    float* pa = acc + (size_t)d * 40;
    atomicAdd(&pa[l], w * pl[l]);
    if (l < 8) atomicAdd(&pa[32 + l], w * pl[32 + l]);
}

// ---------------- final: normalize + log_softmax over 40 -------------------
__global__ __launch_bounds__(256) void k_final_lsm(
    const float* __restrict__ acc, const float* __restrict__ den,
    float* __restrict__ out)
{
    int n = blockIdx.x * 8 + (threadIdx.x >> 5);
    if (n >= N_NODES) return;
    int l = threadIdx.x & 31;
    float dn = den[n] + 1e-16f;
    float v0 = acc[(size_t)n * 40 + l] / dn;
    float v1 = (l < 8) ? acc[(size_t)n * 40 + 32 + l] / dn : -FLT_MAX;
    float mx = fmaxf(v0, v1);
    #pragma unroll
    for (int off = 16; off > 0; off >>= 1) mx = fmaxf(mx, __shfl_xor_sync(0xffffffffu, mx, off));
    float ss = expf(v0 - mx) + ((l < 8) ? expf(v1 - mx) : 0.f);
    #pragma unroll
    for (int off = 16; off > 0; off >>= 1) ss += __shfl_xor_sync(0xffffffffu, ss, off);
    float lse = mx + logf(ss);
    out[(size_t)n * 40 + l] = v0 - lse;
    if (l < 8) out[(size_t)n * 40 + 32 + l] = v1 - lse;
}

// ---------------- host -----------------------------------------------------
extern "C" void kernel_launch(void* const* d_in, const int* in_sizes, int n_in,
                              void* d_out, int out_size)
{
    const float* x    = (const float*)d_in[0];
    const float* Wl1  = (const float*)d_in[1];
    const float* Wr1  = (const float*)d_in[2];
    const float* att1 = (const float*)d_in[3];
    const float* Wl2  = (const float*)d_in[4];
    const float* Wr2  = (const float*)d_in[5];
    const float* att2 = (const float*)d_in[6];
    const float* Wl3  = (const float*)d_in[7];
    const float* Wr3  = (const float*)d_in[8];
    const float* att3 = (const float*)d_in[9];
    const int*   ei   = (const int*)d_in[10];
    const int* src = ei;
    const int* dst = ei + N_EDGES;
    float* out = (float*)d_out;

    float *gl, *gr, *sc, *m, *den, *acc, *h;
    cudaGetSymbolAddress((void**)&gl,  g_gl);
    cudaGetSymbolAddress((void**)&gr,  g_gr);
    cudaGetSymbolAddress((void**)&sc,  g_sc);
    cudaGetSymbolAddress((void**)&m,   g_m);
    cudaGetSymbolAddress((void**)&den, g_den);
    cudaGetSymbolAddress((void**)&acc, g_acc);
    cudaGetSymbolAddress((void**)&h,   g_h);

    const dim3 g128(2, (N_NODES + 63) / 64);
    const dim3 g40(1, (N_NODES + 63) / 64);
    const int EB = N_EDGES / 8;  // 100000 blocks, warp per edge

    // ---- Layer 1 (input x, ELU) ----
    k_gemm128<<<g128, 256>>>(x, Wl1, gl, N_NODES, 128);
    k_gemm128<<<g128, 256>>>(x, Wr1, gr, N_NODES, 128);
    cudaMemsetAsync(den, 0, (size_t)N_NODES * 4 * sizeof(float));
    cudaMemsetAsync(acc, 0, (size_t)N_NODES * 128 * sizeof(float));
    k_init_neg<<<(N_NODES * 4 + 255) / 256, 256>>>(m, N_NODES * 4);
    k_score_h4<<<EB, 256>>>(gl, gr, att1, src, dst, sc, m);
    k_aggr_h4<<<EB, 256>>>(gl, src, dst, sc, m, den, acc);
    k_final_h4<<<(N_NODES * 128 + 255) / 256, 256>>>(acc, den, h, 0);

    // ---- Layer 2 (ReLU) ----
    k_gemm128<<<g128, 256>>>(h, Wl2, gl, N_NODES, 128);
    k_gemm128<<<g128, 256>>>(h, Wr2, gr, N_NODES, 128);
    cudaMemsetAsync(den, 0, (size_t)N_NODES * 4 * sizeof(float));
    cudaMemsetAsync(acc, 0, (size_t)N_NODES * 128 * sizeof(float));
    k_init_neg<<<(N_NODES * 4 + 255) / 256, 256>>>(m, N_NODES * 4);
    k_score_h4<<<EB, 256>>>(gl, gr, att2, src, dst, sc, m);
    k_aggr_h4<<<EB, 256>>>(gl, src, dst, sc, m, den, acc);
    k_final_h4<<<(N_NODES * 128 + 255) / 256, 256>>>(acc, den, h, 1);

    // ---- Layer 3 (1 head, 40 out, log_softmax) ----
    k_gemm128<<<g40, 256>>>(h, Wl3, gl, N_NODES, 40);
    k_gemm128<<<g40, 256>>>(h, Wr3, gr, N_NODES, 40);
    cudaMemsetAsync(den, 0, (size_t)N_NODES * sizeof(float));
    cudaMemsetAsync(acc, 0, (size_t)N_NODES * 40 * sizeof(float));
    k_init_neg<<<(N_NODES + 255) / 256, 256>>>(m, N_NODES);
    k_score_h1<<<EB, 256>>>(gl, gr, att3, src, dst, sc, m);
    k_aggr_h1<<<EB, 256>>>(gl, src, dst, sc, m, den, acc);
    k_final_lsm<<<(N_NODES + 7) / 8, 256>>>(acc, den, out);
}

// round 2
// speedup vs baseline: 1.6185x; 1.6185x over previous
#include <cuda_runtime.h>
#include <math.h>
#include <float.h>
#include <stdint.h>

#define N_NODES 50000
#define N_EDGES 800000
#define SLOPE 0.2f

// ---------------- scratch (device globals; no allocation allowed) ----------
__device__ float g_gl[N_NODES * 128];
__device__ float g_gr[N_NODES * 128];
__device__ float g_den[N_NODES * 4];
__device__ float g_acc[N_NODES * 128];

// ---- packed fp32x2 helpers (Blackwell FFMA2 path) -------------------------
__device__ __forceinline__ void fma2(unsigned long long& d, unsigned long long a, unsigned long long b) {
    asm("fma.rn.f32x2 %0, %1, %2, %0;" : "+l"(d) : "l"(a), "l"(b));
}
__device__ __forceinline__ unsigned long long dup2(float a) {
    unsigned long long r;
    asm("mov.b64 %0, {%1, %1};" : "=l"(r) : "f"(a));
    return r;
}

__device__ __forceinline__ void red_v4(float* p, float a, float b, float c, float d) {
    asm volatile("red.global.add.v4.f32 [%0], {%1,%2,%3,%4};"
                 :: "l"(p), "f"(a), "f"(b), "f"(c), "f"(d) : "memory");
}

// ---- A-element transform: 0 = raw, 1 = ELU(v/den), 2 = ReLU(v/den) --------
__device__ __forceinline__ float4 xform(float4 v, float dn, int mode) {
    if (mode) {
        float inv = 1.0f / dn;
        v.x *= inv; v.y *= inv; v.z *= inv; v.w *= inv;
        if (mode == 1) {
            v.x = v.x > 0.f ? v.x : expm1f(v.x);
            v.y = v.y > 0.f ? v.y : expm1f(v.y);
            v.z = v.z > 0.f ? v.z : expm1f(v.z);
            v.w = v.w > 0.f ? v.w : expm1f(v.w);
        } else {
            v.x = fmaxf(v.x, 0.f); v.y = fmaxf(v.y, 0.f);
            v.z = fmaxf(v.z, 0.f); v.w = fmaxf(v.w, 0.f);
        }
    }
    return v;
}

// ---------------- SGEMM (Ncols=128): C = act(A) @ W, FFMA2 inner loop ------
// BM=128, BN=128, BK=16, 256 threads, 8x8 per-thread tile (cols packed x2).
__global__ __launch_bounds__(256) void k_gemm_f2(
    const float* __restrict__ Asrc, const float* __restrict__ den,
    const float* __restrict__ W, float* __restrict__ C, int M, int mode)
{
    __shared__ float As[16][132];   // [k][row], pad 4 keeps 16B align + kills store conflicts
    __shared__ float Ws[16][128];   // [k][col]

    const int tid = threadIdx.x;
    const int tx = tid & 15;        // col group: 8 cols = 4 f32x2 pairs
    const int ty = tid >> 4;        // row group: 8 rows
    const int r0 = blockIdx.x * 128;

    unsigned long long acc[8][4];
    #pragma unroll
    for (int i = 0; i < 8; i++)
        #pragma unroll
        for (int j = 0; j < 4; j++) acc[i][j] = 0ull;

    for (int kk = 0; kk < 128; kk += 16) {
        __syncthreads();
        // A tile: 128 rows x 16 k  (512 float4, 2 per thread), transposed into As
        #pragma unroll
        for (int i = 0; i < 2; i++) {
            int f = tid + i * 256;
            int row = f >> 2;
            int c4 = f & 3;
            int r = r0 + row;
            float4 v = make_float4(0.f, 0.f, 0.f, 0.f);
            if (r < M) {
                v = *(const float4*)(Asrc + (size_t)r * 128 + kk + c4 * 4);
                float dn = mode ? (den[r * 4 + ((kk + c4 * 4) >> 5)] + 1e-16f) : 1.f;
                v = xform(v, dn, mode);
            }
            As[c4 * 4 + 0][row] = v.x;
            As[c4 * 4 + 1][row] = v.y;
            As[c4 * 4 + 2][row] = v.z;
            As[c4 * 4 + 3][row] = v.w;
        }
        // W tile: 16 k x 128 cols (512 float4, 2 per thread)
        #pragma unroll
        for (int i = 0; i < 2; i++) {
            int f = tid + i * 256;
            int k = f >> 5, c4 = f & 31;
            *(float4*)(&Ws[k][c4 * 4]) = *(const float4*)(W + (size_t)(kk + k) * 128 + c4 * 4);
        }
        __syncthreads();

        #pragma unroll
        for (int k = 0; k < 16; k++) {
            float4 a0 = *(const float4*)(&As[k][ty * 8]);
            float4 a1 = *(const float4*)(&As[k][ty * 8 + 4]);
            ulonglong2 b0 = *(const ulonglong2*)(&Ws[k][tx * 8]);
            ulonglong2 b1 = *(const ulonglong2*)(&Ws[k][tx * 8 + 4]);
            float av[8] = {a0.x, a0.y, a0.z, a0.w, a1.x, a1.y, a1.z, a1.w};
            #pragma unroll
            for (int i = 0; i < 8; i++) {
                unsigned long long ad = dup2(av[i]);
                fma2(acc[i][0], ad, b0.x);
                fma2(acc[i][1], ad, b0.y);
                fma2(acc[i][2], ad, b1.x);
                fma2(acc[i][3], ad, b1.y);
            }
        }
    }

    #pragma unroll
    for (int i = 0; i < 8; i++) {
        int r = r0 + ty * 8 + i;
        if (r >= M) continue;
        unsigned long long* cp = (unsigned long long*)(C + (size_t)r * 128 + tx * 8);
        #pragma unroll
        for (int j = 0; j < 4; j++) cp[j] = acc[i][j];
    }
}

// ---------------- SGEMM (Ncols=40): C = act(A) @ W --------------------------
// BM=64, BN=64(clipped), BK=64, 256 threads, 4x4 tile. A is 128 wide.
__global__ __launch_bounds__(256) void k_gemm40(
    const float* __restrict__ Asrc, const float* __restrict__ den,
    const float* __restrict__ W, float* __restrict__ C, int M, int Ncols, int mode)
{
    __shared__ float As[64][68];
    __shared__ float Ws[64][64];

    const int tid = threadIdx.x;
    const int tx = tid & 15;
    const int ty = tid >> 4;
    const int r0 = blockIdx.y * 64;
    const int c0 = blockIdx.x * 64;

    float acc[4][4] = {};

    for (int kk = 0; kk < 128; kk += 64) {
        __syncthreads();
        #pragma unroll
        for (int i = 0; i < 4; i++) {
            int f = tid + i * 256;
            int row = f >> 4;
            int k4 = f & 15;
            float4 a = make_float4(0.f, 0.f, 0.f, 0.f);
            int r = r0 + row;
            if (r < M) {
                a = *(const float4*)(Asrc + (size_t)r * 128 + kk + k4 * 4);
                float dn = mode ? (den[r * 4 + ((kk + k4 * 4) >> 5)] + 1e-16f) : 1.f;
                a = xform(a, dn, mode);
            }
            *(float4*)(&As[row][k4 * 4]) = a;
        }
        #pragma unroll
        for (int i = 0; i < 16; i++) {
            int f = tid + i * 256;
            int k = f >> 6, c = f & 63;
            Ws[k][c] = (c0 + c < Ncols) ? W[(size_t)(kk + k) * Ncols + c0 + c] : 0.f;
        }
        __syncthreads();

        #pragma unroll 16
        for (int k = 0; k < 64; k++) {
            float4 b = *(const float4*)(&Ws[k][tx * 4]);
            float a0 = As[ty * 4 + 0][k];
            float a1 = As[ty * 4 + 1][k];
            float a2 = As[ty * 4 + 2][k];
            float a3 = As[ty * 4 + 3][k];
            acc[0][0] += a0 * b.x; acc[0][1] += a0 * b.y; acc[0][2] += a0 * b.z; acc[0][3] += a0 * b.w;
            acc[1][0] += a1 * b.x; acc[1][1] += a1 * b.y; acc[1][2] += a1 * b.z; acc[1][3] += a1 * b.w;
            acc[2][0] += a2 * b.x; acc[2][1] += a2 * b.y; acc[2][2] += a2 * b.z; acc[2][3] += a2 * b.w;
            acc[3][0] += a3 * b.x; acc[3][1] += a3 * b.y; acc[3][2] += a3 * b.z; acc[3][3] += a3 * b.w;
        }
    }

    #pragma unroll
    for (int i = 0; i < 4; i++) {
        int r = r0 + ty * 4 + i;
        if (r >= M) continue;
        #pragma unroll
        for (int j = 0; j < 4; j++) {
            int c = c0 + tx * 4 + j;
            if (c < Ncols) C[(size_t)r * Ncols + c] = acc[i][j];
        }
    }
}

// ---------------- fused edge pass (H=4, F=32) -------------------------------
// warp per edge, lane l owns feats 4l..4l+3 (head = l>>3).
// score -> exp(score) -> vector RED of denom + weighted message. No max pass:
// softmax is shift-invariant and scores are O(10), safe in fp32.
__global__ __launch_bounds__(256) void k_edge_h4(
    const float4* __restrict__ gl4, const float4* __restrict__ gr4,
    const float* __restrict__ att,
    const int* __restrict__ src, const int* __restrict__ dst,
    float* __restrict__ den, float* __restrict__ acc)
{
    int e = blockIdx.x * 8 + (threadIdx.x >> 5);
    if (e >= N_EDGES) return;
    int l = threadIdx.x & 31;
    int s = src[e], d = dst[e];

    float4 a = __ldg(&gl4[(size_t)s * 32 + l]);
    float4 b = __ldg(&gr4[(size_t)d * 32 + l]);
    float4 t = __ldg(&((const float4*)att)[l]);

    float vx = a.x + b.x; vx = vx > 0.f ? vx : SLOPE * vx;
    float vy = a.y + b.y; vy = vy > 0.f ? vy : SLOPE * vy;
    float vz = a.z + b.z; vz = vz > 0.f ? vz : SLOPE * vz;
    float vw = a.w + b.w; vw = vw > 0.f ? vw : SLOPE * vw;
    float p = vx * t.x + vy * t.y + vz * t.z + vw * t.w;

    // reduce within each 8-lane head group
    p += __shfl_xor_sync(0xffffffffu, p, 4);
    p += __shfl_xor_sync(0xffffffffu, p, 2);
    p += __shfl_xor_sync(0xffffffffu, p, 1);
    float w = __expf(p);

    // denom: lane 0 gathers the 4 head weights, one 16B RED
    float w1 = __shfl_sync(0xffffffffu, w, 8);
    float w2 = __shfl_sync(0xffffffffu, w, 16);
    float w3 = __shfl_sync(0xffffffffu, w, 24);
    if (l == 0) red_v4(den + (size_t)d * 4, w, w1, w2, w3);

    red_v4(acc + (size_t)d * 128 + 4 * l, w * a.x, w * a.y, w * a.z, w * a.w);
}

// ---------------- fused edge pass (H=1, F=40): 16 lanes per edge ------------
__global__ __launch_bounds__(256) void k_edge_h1(
    const float4* __restrict__ gl4, const float4* __restrict__ gr4,
    const float* __restrict__ att,
    const int* __restrict__ src, const int* __restrict__ dst,
    float* __restrict__ den, float* __restrict__ acc)
{
    int l = threadIdx.x & 31;
    int sub = l >> 4;          // 2 edges per warp
    int ll = l & 15;
    int e = blockIdx.x * 16 + (threadIdx.x >> 5) * 2 + sub;
    if (e >= N_EDGES) return;
    int s = src[e], d = dst[e];

    float4 a = make_float4(0.f, 0.f, 0.f, 0.f);
    float p = 0.f;
    if (ll < 10) {
        a = __ldg(&gl4[(size_t)s * 10 + ll]);
        float4 b = __ldg(&gr4[(size_t)d * 10 + ll]);
        float4 t = __ldg(&((const float4*)att)[ll]);
        float vx = a.x + b.x; vx = vx > 0.f ? vx : SLOPE * vx;
        float vy = a.y + b.y; vy = vy > 0.f ? vy : SLOPE * vy;
        float vz = a.z + b.z; vz = vz > 0.f ? vz : SLOPE * vz;
        float vw = a.w + b.w; vw = vw > 0.f ? vw : SLOPE * vw;
        p = vx * t.x + vy * t.y + vz * t.z + vw * t.w;
    }
    p += __shfl_xor_sync(0xffffffffu, p, 8, 16);
    p += __shfl_xor_sync(0xffffffffu, p, 4, 16);
    p += __shfl_xor_sync(0xffffffffu, p, 2, 16);
    p += __shfl_xor_sync(0xffffffffu, p, 1, 16);
    float w = __expf(p);

    if (ll == 0) atomicAdd(den + d, w);
    if (ll < 10) red_v4(acc + (size_t)d * 40 + 4 * ll, w * a.x, w * a.y, w * a.z, w * a.w);
}

// ---------------- final: normalize + log_softmax over 40 --------------------
__global__ __launch_bounds__(256) void k_final_lsm(
    const float* __restrict__ acc, const float* __restrict__ den,
    float* __restrict__ out)
{
    int n = blockIdx.x * 8 + (threadIdx.x >> 5);
    if (n >= N_NODES) return;
    int l = threadIdx.x & 31;
    float dn = den[n] + 1e-16f;
    float v0 = acc[(size_t)n * 40 + l] / dn;
    float v1 = (l < 8) ? acc[(size_t)n * 40 + 32 + l] / dn : -FLT_MAX;
    float mx = fmaxf(v0, v1);
    #pragma unroll
    for (int off = 16; off > 0; off >>= 1) mx = fmaxf(mx, __shfl_xor_sync(0xffffffffu, mx, off));
    float ss = expf(v0 - mx) + ((l < 8) ? expf(v1 - mx) : 0.f);
    #pragma unroll
    for (int off = 16; off > 0; off >>= 1) ss += __shfl_xor_sync(0xffffffffu, ss, off);
    float lse = mx + logf(ss);
    out[(size_t)n * 40 + l] = v0 - lse;
    if (l < 8) out[(size_t)n * 40 + 32 + l] = v1 - lse;
}

// ---------------- host -------------------------------------------------------
extern "C" void kernel_launch(void* const* d_in, const int* in_sizes, int n_in,
                              void* d_out, int out_size)
{
    const float* x    = (const float*)d_in[0];
    const float* Wl1  = (const float*)d_in[1];
    const float* Wr1  = (const float*)d_in[2];
    const float* att1 = (const float*)d_in[3];
    const float* Wl2  = (const float*)d_in[4];
    const float* Wr2  = (const float*)d_in[5];
    const float* att2 = (const float*)d_in[6];
    const float* Wl3  = (const float*)d_in[7];
    const float* Wr3  = (const float*)d_in[8];
    const float* att3 = (const float*)d_in[9];
    const int*   ei   = (const int*)d_in[10];
    const int* src = ei;
    const int* dst = ei + N_EDGES;
    float* out = (float*)d_out;

    float *gl, *gr, *den, *acc;
    cudaGetSymbolAddress((void**)&gl,  g_gl);
    cudaGetSymbolAddress((void**)&gr,  g_gr);
    cudaGetSymbolAddress((void**)&den, g_den);
    cudaGetSymbolAddress((void**)&acc, g_acc);

    const int GB = (N_NODES + 127) / 128;       // 391 blocks for Ncols=128 GEMM
    const dim3 g40(1, (N_NODES + 63) / 64);
    const int EB4 = N_EDGES / 8;                // warp per edge
    const int EB1 = N_EDGES / 16;               // 16 lanes per edge

    // ---- Layer 1 (input x raw) ----
    k_gemm_f2<<<GB, 256>>>(x, nullptr, Wl1, gl, N_NODES, 0);
    k_gemm_f2<<<GB, 256>>>(x, nullptr, Wr1, gr, N_NODES, 0);
    cudaMemsetAsync(den, 0, (size_t)N_NODES * 4 * sizeof(float));
    cudaMemsetAsync(acc, 0, (size_t)N_NODES * 128 * sizeof(float));
    k_edge_h4<<<EB4, 256>>>((const float4*)gl, (const float4*)gr, att1, src, dst, den, acc);

    // ---- Layer 2 (A = ELU(acc/den)) ----
    k_gemm_f2<<<GB, 256>>>(acc, den, Wl2, gl, N_NODES, 1);
    k_gemm_f2<<<GB, 256>>>(acc, den, Wr2, gr, N_NODES, 1);
    cudaMemsetAsync(den, 0, (size_t)N_NODES * 4 * sizeof(float));
    cudaMemsetAsync(acc, 0, (size_t)N_NODES * 128 * sizeof(float));
    k_edge_h4<<<EB4, 256>>>((const float4*)gl, (const float4*)gr, att2, src, dst, den, acc);

    // ---- Layer 3 (A = ReLU(acc/den), 1 head, 40 out) ----
    k_gemm40<<<g40, 256>>>(acc, den, Wl3, gl, N_NODES, 40, 2);
    k_gemm40<<<g40, 256>>>(acc, den, Wr3, gr, N_NODES, 40, 2);
    cudaMemsetAsync(den, 0, (size_t)N_NODES * sizeof(float));
    cudaMemsetAsync(acc, 0, (size_t)N_NODES * 40 * sizeof(float));
    k_edge_h1<<<EB1, 256>>>((const float4*)gl, (const float4*)gr, att3, src, dst, den, acc);
    k_final_lsm<<<(N_NODES + 7) / 8, 256>>>(acc, den, out);
}

// round 3
// speedup vs baseline: 1.7522x; 1.0827x over previous
#include <cuda_runtime.h>
#include <math.h>
#include <float.h>
#include <stdint.h>

#define N_NODES 50000
#define N_EDGES 800000
#define SLOPE 0.2f

// ---------------- scratch (device globals; no allocation allowed) ----------
__device__ float g_gl[N_NODES * 128];
__device__ float g_gr[N_NODES * 128];
__device__ float g_den[N_NODES * 4];
__device__ float g_acc[N_NODES * 128];

// ---- packed fp32x2 helpers -------------------------------------------------
__device__ __forceinline__ void fma2(unsigned long long& d, unsigned long long a, unsigned long long b) {
    asm("fma.rn.f32x2 %0, %1, %2, %0;" : "+l"(d) : "l"(a), "l"(b));
}
__device__ __forceinline__ void red_v4(float* p, float a, float b, float c, float d) {
    asm volatile("red.global.add.v4.f32 [%0], {%1,%2,%3,%4};"
                 :: "l"(p), "f"(a), "f"(b), "f"(c), "f"(d) : "memory");
}

// ---- A-element transform: 0 = raw, 1 = ELU(v/den), 2 = ReLU(v/den) --------
__device__ __forceinline__ float4 xform(float4 v, float dn, int mode) {
    if (mode) {
        float inv = 1.0f / dn;
        v.x *= inv; v.y *= inv; v.z *= inv; v.w *= inv;
        if (mode == 1) {
            v.x = v.x > 0.f ? v.x : expm1f(v.x);
            v.y = v.y > 0.f ? v.y : expm1f(v.y);
            v.z = v.z > 0.f ? v.z : expm1f(v.z);
            v.w = v.w > 0.f ? v.w : expm1f(v.w);
        } else {
            v.x = fmaxf(v.x, 0.f); v.y = fmaxf(v.y, 0.f);
            v.z = fmaxf(v.z, 0.f); v.w = fmaxf(v.w, 0.f);
        }
    }
    return v;
}

// ---------------- dual SGEMM: C1 = act(A)@W1, C2 = act(A)@W2 ---------------
// A:[M,128], W:[128,128]. BM=64, BK=16, dual-N=256, 256 threads, dbl-buffered.
// Inner loop: A as duplicated f32x2 pairs (broadcast LDS), B as natural col
// pairs (lane-consecutive LDS.128), pure FFMA2, zero MOVs.
__global__ __launch_bounds__(256, 2) void k_gemm_dual(
    const float* __restrict__ Asrc, const float* __restrict__ den,
    const float* __restrict__ W1, const float* __restrict__ W2,
    float* __restrict__ C1, float* __restrict__ C2, int M, int mode)
{
    __shared__ float As[2][16][128];   // [stage][k][2*row {dup pair}], 64 rows
    __shared__ float Ws[2][16][256];   // [stage][k][col] (0-127: W1, 128-255: W2)

    const int tid = threadIdx.x;
    const int tx = tid & 31;           // col group: 4 cols per half
    const int ty = tid >> 5;           // row group: 8 rows
    const int r0 = blockIdx.x * 64;

    // A load mapping: one float4 per thread per tile
    const int arow = tid >> 2;         // 0..63
    const int ak4  = tid & 3;          // k quad

    unsigned long long acc1[8][2], acc2[8][2];
    #pragma unroll
    for (int i = 0; i < 8; i++) {
        acc1[i][0] = acc1[i][1] = 0ull;
        acc2[i][0] = acc2[i][1] = 0ull;
    }

    float4 aPre;
    float4 wPre[4];

    auto loadG = [&](int t) {
        int kk = t * 16;
        int r = r0 + arow;
        aPre = make_float4(0.f, 0.f, 0.f, 0.f);
        if (r < M) {
            aPre = *(const float4*)(Asrc + (size_t)r * 128 + kk + ak4 * 4);
            float dn = mode ? (den[r * 4 + ((kk + ak4 * 4) >> 5)] + 1e-16f) : 1.f;
            aPre = xform(aPre, dn, mode);
        }
        #pragma unroll
        for (int i = 0; i < 4; i++) {
            int f = tid + i * 256;
            int k = f >> 6, c4 = f & 63;
            wPre[i] = (c4 < 32)
                ? *(const float4*)(W1 + (size_t)(kk + k) * 128 + c4 * 4)
                : *(const float4*)(W2 + (size_t)(kk + k) * 128 + (c4 - 32) * 4);
        }
    };
    auto stsTo = [&](int s) {
        float av[4] = {aPre.x, aPre.y, aPre.z, aPre.w};
        #pragma unroll
        for (int j = 0; j < 4; j++) {
            float2 d2 = make_float2(av[j], av[j]);
            *(float2*)(&As[s][ak4 * 4 + j][2 * arow]) = d2;
        }
        #pragma unroll
        for (int i = 0; i < 4; i++) {
            int f = tid + i * 256;
            int k = f >> 6, c4 = f & 63;
            *(float4*)(&Ws[s][k][c4 * 4]) = wPre[i];
        }
    };

    loadG(0);
    stsTo(0);

    for (int t = 0; t < 8; t++) {
        __syncthreads();
        if (t < 7) loadG(t + 1);
        const int s = t & 1;
        #pragma unroll
        for (int k = 0; k < 16; k++) {
            ulonglong2 a01 = *(const ulonglong2*)(&As[s][k][16 * ty + 0]);
            ulonglong2 a23 = *(const ulonglong2*)(&As[s][k][16 * ty + 4]);
            ulonglong2 a45 = *(const ulonglong2*)(&As[s][k][16 * ty + 8]);
            ulonglong2 a67 = *(const ulonglong2*)(&As[s][k][16 * ty + 12]);
            ulonglong2 b1  = *(const ulonglong2*)(&Ws[s][k][tx * 4]);
            ulonglong2 b2  = *(const ulonglong2*)(&Ws[s][k][128 + tx * 4]);
            unsigned long long av[8] = {a01.x, a01.y, a23.x, a23.y,
                                        a45.x, a45.y, a67.x, a67.y};
            #pragma unroll
            for (int i = 0; i < 8; i++) {
                fma2(acc1[i][0], av[i], b1.x);
                fma2(acc1[i][1], av[i], b1.y);
                fma2(acc2[i][0], av[i], b2.x);
                fma2(acc2[i][1], av[i], b2.y);
            }
        }
        if (t < 7) stsTo((t + 1) & 1);
    }

    #pragma unroll
    for (int i = 0; i < 8; i++) {
        int r = r0 + ty * 8 + i;
        if (r >= M) continue;
        ulonglong2 o1; o1.x = acc1[i][0]; o1.y = acc1[i][1];
        ulonglong2 o2; o2.x = acc2[i][0]; o2.y = acc2[i][1];
        *(ulonglong2*)(C1 + (size_t)r * 128 + tx * 4) = o1;
        *(ulonglong2*)(C2 + (size_t)r * 128 + tx * 4) = o2;
    }
}

// ---------------- dual SGEMM (Ncols=40): blockIdx.x picks W/C --------------
__global__ __launch_bounds__(256) void k_gemm40_dual(
    const float* __restrict__ Asrc, const float* __restrict__ den,
    const float* __restrict__ Wa, const float* __restrict__ Wb,
    float* __restrict__ Ca, float* __restrict__ Cb, int M, int Ncols, int mode)
{
    const float* W = blockIdx.x ? Wb : Wa;
    float* C = blockIdx.x ? Cb : Ca;

    __shared__ float As[64][68];
    __shared__ float Ws[64][64];

    const int tid = threadIdx.x;
    const int tx = tid & 15;
    const int ty = tid >> 4;
    const int r0 = blockIdx.y * 64;

    float acc[4][4] = {};

    for (int kk = 0; kk < 128; kk += 64) {
        __syncthreads();
        #pragma unroll
        for (int i = 0; i < 4; i++) {
            int f = tid + i * 256;
            int row = f >> 4;
            int k4 = f & 15;
            float4 a = make_float4(0.f, 0.f, 0.f, 0.f);
            int r = r0 + row;
            if (r < M) {
                a = *(const float4*)(Asrc + (size_t)r * 128 + kk + k4 * 4);
                float dn = mode ? (den[r * 4 + ((kk + k4 * 4) >> 5)] + 1e-16f) : 1.f;
                a = xform(a, dn, mode);
            }
            *(float4*)(&As[row][k4 * 4]) = a;
        }
        #pragma unroll
        for (int i = 0; i < 16; i++) {
            int f = tid + i * 256;
            int k = f >> 6, c = f & 63;
            Ws[k][c] = (c < Ncols) ? W[(size_t)(kk + k) * Ncols + c] : 0.f;
        }
        __syncthreads();

        #pragma unroll 16
        for (int k = 0; k < 64; k++) {
            float4 b = *(const float4*)(&Ws[k][tx * 4]);
            float a0 = As[ty * 4 + 0][k];
            float a1 = As[ty * 4 + 1][k];
            float a2 = As[ty * 4 + 2][k];
            float a3 = As[ty * 4 + 3][k];
            acc[0][0] += a0 * b.x; acc[0][1] += a0 * b.y; acc[0][2] += a0 * b.z; acc[0][3] += a0 * b.w;
            acc[1][0] += a1 * b.x; acc[1][1] += a1 * b.y; acc[1][2] += a1 * b.z; acc[1][3] += a1 * b.w;
            acc[2][0] += a2 * b.x; acc[2][1] += a2 * b.y; acc[2][2] += a2 * b.z; acc[2][3] += a2 * b.w;
            acc[3][0] += a3 * b.x; acc[3][1] += a3 * b.y; acc[3][2] += a3 * b.z; acc[3][3] += a3 * b.w;
        }
    }

    #pragma unroll
    for (int i = 0; i < 4; i++) {
        int r = r0 + ty * 4 + i;
        if (r >= M) continue;
        #pragma unroll
        for (int j = 0; j < 4; j++) {
            int c = tx * 4 + j;
            if (c < Ncols) C[(size_t)r * Ncols + c] = acc[i][j];
        }
    }
}

// ---------------- fused edge pass (H=4, F=32) -------------------------------
__global__ __launch_bounds__(256) void k_edge_h4(
    const float4* __restrict__ gl4, const float4* __restrict__ gr4,
    const float* __restrict__ att,
    const int* __restrict__ src, const int* __restrict__ dst,
    float* __restrict__ den, float* __restrict__ acc)
{
    int e = blockIdx.x * 8 + (threadIdx.x >> 5);
    if (e >= N_EDGES) return;
    int l = threadIdx.x & 31;
    int s = src[e], d = dst[e];

    float4 a = __ldg(&gl4[(size_t)s * 32 + l]);
    float4 b = __ldg(&gr4[(size_t)d * 32 + l]);
    float4 t = __ldg(&((const float4*)att)[l]);

    float vx = a.x + b.x; vx = vx > 0.f ? vx : SLOPE * vx;
    float vy = a.y + b.y; vy = vy > 0.f ? vy : SLOPE * vy;
    float vz = a.z + b.z; vz = vz > 0.f ? vz : SLOPE * vz;
    float vw = a.w + b.w; vw = vw > 0.f ? vw : SLOPE * vw;
    float p = vx * t.x + vy * t.y + vz * t.z + vw * t.w;

    p += __shfl_xor_sync(0xffffffffu, p, 4);
    p += __shfl_xor_sync(0xffffffffu, p, 2);
    p += __shfl_xor_sync(0xffffffffu, p, 1);
    float w = __expf(p);

    float w1 = __shfl_sync(0xffffffffu, w, 8);
    float w2 = __shfl_sync(0xffffffffu, w, 16);
    float w3 = __shfl_sync(0xffffffffu, w, 24);
    if (l == 0) red_v4(den + (size_t)d * 4, w, w1, w2, w3);

    red_v4(acc + (size_t)d * 128 + 4 * l, w * a.x, w * a.y, w * a.z, w * a.w);
}

// ---------------- fused edge pass (H=1, F=40): 16 lanes per edge ------------
__global__ __launch_bounds__(256) void k_edge_h1(
    const float4* __restrict__ gl4, const float4* __restrict__ gr4,
    const float* __restrict__ att,
    const int* __restrict__ src, const int* __restrict__ dst,
    float* __restrict__ den, float* __restrict__ acc)
{
    int l = threadIdx.x & 31;
    int sub = l >> 4;
    int ll = l & 15;
    int e = blockIdx.x * 16 + (threadIdx.x >> 5) * 2 + sub;
    if (e >= N_EDGES) return;
    int s = src[e], d = dst[e];

    float4 a = make_float4(0.f, 0.f, 0.f, 0.f);
    float p = 0.f;
    if (ll < 10) {
        a = __ldg(&gl4[(size_t)s * 10 + ll]);
        float4 b = __ldg(&gr4[(size_t)d * 10 + ll]);
        float4 t = __ldg(&((const float4*)att)[ll]);
        float vx = a.x + b.x; vx = vx > 0.f ? vx : SLOPE * vx;
        float vy = a.y + b.y; vy = vy > 0.f ? vy : SLOPE * vy;
        float vz = a.z + b.z; vz = vz > 0.f ? vz : SLOPE * vz;
        float vw = a.w + b.w; vw = vw > 0.f ? vw : SLOPE * vw;
        p = vx * t.x + vy * t.y + vz * t.z + vw * t.w;
    }
    p += __shfl_xor_sync(0xffffffffu, p, 8, 16);
    p += __shfl_xor_sync(0xffffffffu, p, 4, 16);
    p += __shfl_xor_sync(0xffffffffu, p, 2, 16);
    p += __shfl_xor_sync(0xffffffffu, p, 1, 16);
    float w = __expf(p);

    if (ll == 0) atomicAdd(den + d, w);
    if (ll < 10) red_v4(acc + (size_t)d * 40 + 4 * ll, w * a.x, w * a.y, w * a.z, w * a.w);
}

// ---------------- final: normalize + log_softmax over 40 --------------------
__global__ __launch_bounds__(256) void k_final_lsm(
    const float* __restrict__ acc, const float* __restrict__ den,
    float* __restrict__ out)
{
    int n = blockIdx.x * 8 + (threadIdx.x >> 5);
    if (n >= N_NODES) return;
    int l = threadIdx.x & 31;
    float dn = den[n] + 1e-16f;
    float v0 = acc[(size_t)n * 40 + l] / dn;
    float v1 = (l < 8) ? acc[(size_t)n * 40 + 32 + l] / dn : -FLT_MAX;
    float mx = fmaxf(v0, v1);
    #pragma unroll
    for (int off = 16; off > 0; off >>= 1) mx = fmaxf(mx, __shfl_xor_sync(0xffffffffu, mx, off));
    float ss = expf(v0 - mx) + ((l < 8) ? expf(v1 - mx) : 0.f);
    #pragma unroll
    for (int off = 16; off > 0; off >>= 1) ss += __shfl_xor_sync(0xffffffffu, ss, off);
    float lse = mx + logf(ss);
    out[(size_t)n * 40 + l] = v0 - lse;
    if (l < 8) out[(size_t)n * 40 + 32 + l] = v1 - lse;
}

// ---------------- host -------------------------------------------------------
extern "C" void kernel_launch(void* const* d_in, const int* in_sizes, int n_in,
                              void* d_out, int out_size)
{
    const float* x    = (const float*)d_in[0];
    const float* Wl1  = (const float*)d_in[1];
    const float* Wr1  = (const float*)d_in[2];
    const float* att1 = (const float*)d_in[3];
    const float* Wl2  = (const float*)d_in[4];
    const float* Wr2  = (const float*)d_in[5];
    const float* att2 = (const float*)d_in[6];
    const float* Wl3  = (const float*)d_in[7];
    const float* Wr3  = (const float*)d_in[8];
    const float* att3 = (const float*)d_in[9];
    const int*   ei   = (const int*)d_in[10];
    const int* src = ei;
    const int* dst = ei + N_EDGES;
    float* out = (float*)d_out;

    float *gl, *gr, *den, *acc;
    cudaGetSymbolAddress((void**)&gl,  g_gl);
    cudaGetSymbolAddress((void**)&gr,  g_gr);
    cudaGetSymbolAddress((void**)&den, g_den);
    cudaGetSymbolAddress((void**)&acc, g_acc);

    const int GB = (N_NODES + 63) / 64;         // 782 blocks
    const dim3 g40(2, (N_NODES + 63) / 64);
    const int EB4 = N_EDGES / 8;
    const int EB1 = N_EDGES / 16;

    // ---- Layer 1 (input x raw) ----
    k_gemm_dual<<<GB, 256>>>(x, nullptr, Wl1, Wr1, gl, gr, N_NODES, 0);
    cudaMemsetAsync(den, 0, (size_t)N_NODES * 4 * sizeof(float));
    cudaMemsetAsync(acc, 0, (size_t)N_NODES * 128 * sizeof(float));
    k_edge_h4<<<EB4, 256>>>((const float4*)gl, (const float4*)gr, att1, src, dst, den, acc);

    // ---- Layer 2 (A = ELU(acc/den)) ----
    k_gemm_dual<<<GB, 256>>>(acc, den, Wl2, Wr2, gl, gr, N_NODES, 1);
    cudaMemsetAsync(den, 0, (size_t)N_NODES * 4 * sizeof(float));
    cudaMemsetAsync(acc, 0, (size_t)N_NODES * 128 * sizeof(float));
    k_edge_h4<<<EB4, 256>>>((const float4*)gl, (const float4*)gr, att2, src, dst, den, acc);

    // ---- Layer 3 (A = ReLU(acc/den), 1 head, 40 out) ----
    k_gemm40_dual<<<g40, 256>>>(acc, den, Wl3, Wr3, gl, gr, N_NODES, 40, 2);
    cudaMemsetAsync(den, 0, (size_t)N_NODES * sizeof(float));
    cudaMemsetAsync(acc, 0, (size_t)N_NODES * 40 * sizeof(float));
    k_edge_h1<<<EB1, 256>>>((const float4*)gl, (const float4*)gr, att3, src, dst, den, acc);
    k_final_lsm<<<(N_NODES + 7) / 8, 256>>>(acc, den, out);
}

// round 5
// speedup vs baseline: 2.3726x; 1.3540x over previous
#include <cuda_runtime.h>
#include <math.h>
#include <float.h>
#include <stdint.h>

#define N_NODES 50000
#define N_EDGES 800000
#define SLOPE 0.2f

// ---------------- scratch (device globals; no allocation allowed) ----------
__device__ float g_gl[N_NODES * 128];
__device__ float g_gr[N_NODES * 128];
__device__ float g_h[N_NODES * 128];
__device__ int   g_deg[N_NODES];
__device__ int   g_off[N_NODES];
__device__ int   g_cur[N_NODES];
__device__ int   g_bsum[64];
__device__ int   g_eidx[N_EDGES];

// ---- packed fp32x2 helpers -------------------------------------------------
__device__ __forceinline__ void fma2(unsigned long long& d, unsigned long long a, unsigned long long b) {
    asm("fma.rn.f32x2 %0, %1, %2, %0;" : "+l"(d) : "l"(a), "l"(b));
}

// ================= CSR construction ==========================================
__global__ void k_hist(const int* __restrict__ dst, int* __restrict__ deg) {
    int e = blockIdx.x * blockDim.x + threadIdx.x;
    if (e < N_EDGES) atomicAdd(&deg[dst[e]], 1);
}

// block-wise inclusive scan (1024 per block) -> exclusive offsets
__global__ __launch_bounds__(1024) void k_scan_part(
    const int* __restrict__ deg, int* __restrict__ off, int* __restrict__ bsum)
{
    __shared__ int sh[1024];
    int t = threadIdx.x;
    int i = blockIdx.x * 1024 + t;
    int v = (i < N_NODES) ? deg[i] : 0;
    sh[t] = v;
    __syncthreads();
    #pragma unroll
    for (int o = 1; o < 1024; o <<= 1) {
        int u = (t >= o) ? sh[t - o] : 0;
        __syncthreads();
        sh[t] += u;
        __syncthreads();
    }
    if (i < N_NODES) off[i] = sh[t] - v;
    if (t == 1023) bsum[blockIdx.x] = sh[t];
}

__global__ __launch_bounds__(64) void k_scan_top(int* __restrict__ bsum, int nb) {
    __shared__ int sh[64];
    int t = threadIdx.x;
    int v = (t < nb) ? bsum[t] : 0;
    sh[t] = v;
    __syncthreads();
    #pragma unroll
    for (int o = 1; o < 64; o <<= 1) {
        int u = (t >= o) ? sh[t - o] : 0;
        __syncthreads();
        sh[t] += u;
        __syncthreads();
    }
    if (t < nb) bsum[t] = sh[t];   // inclusive
}

__global__ void k_scan_add(int* __restrict__ off, int* __restrict__ cur,
                           const int* __restrict__ bsum)
{
    int i = blockIdx.x * blockDim.x + threadIdx.x;
    if (i >= N_NODES) return;
    int b = i >> 10;
    int base = b ? bsum[b - 1] : 0;
    int o = off[i] + base;
    off[i] = o;
    cur[i] = o;
}

__global__ void k_scatter(const int* __restrict__ src, const int* __restrict__ dst,
                          int* __restrict__ cur, int* __restrict__ eidx)
{
    int e = blockIdx.x * blockDim.x + threadIdx.x;
    if (e >= N_EDGES) return;
    int p = atomicAdd(&cur[dst[e]], 1);
    eidx[p] = src[e];
}

// ================= dual SGEMM: C1 = A@W1, C2 = A@W2 ========================
__global__ __launch_bounds__(256, 2) void k_gemm_dual(
    const float* __restrict__ Asrc,
    const float* __restrict__ W1, const float* __restrict__ W2,
    float* __restrict__ C1, float* __restrict__ C2, int M)
{
    __shared__ float As[2][16][128];
    __shared__ float Ws[2][16][256];

    const int tid = threadIdx.x;
    const int tx = tid & 31;
    const int ty = tid >> 5;
    const int r0 = blockIdx.x * 64;

    const int arow = tid >> 2;
    const int ak4  = tid & 3;

    unsigned long long acc1[8][2], acc2[8][2];
    #pragma unroll
    for (int i = 0; i < 8; i++) {
        acc1[i][0] = acc1[i][1] = 0ull;
        acc2[i][0] = acc2[i][1] = 0ull;
    }

    float4 aPre;
    float4 wPre[4];

    auto loadG = [&](int t) {
        int kk = t * 16;
        int r = r0 + arow;
        aPre = make_float4(0.f, 0.f, 0.f, 0.f);
        if (r < M)
            aPre = *(const float4*)(Asrc + (size_t)r * 128 + kk + ak4 * 4);
        #pragma unroll
        for (int i = 0; i < 4; i++) {
            int f = tid + i * 256;
            int k = f >> 6, c4 = f & 63;
            wPre[i] = (c4 < 32)
                ? *(const float4*)(W1 + (size_t)(kk + k) * 128 + c4 * 4)
                : *(const float4*)(W2 + (size_t)(kk + k) * 128 + (c4 - 32) * 4);
        }
    };
    auto stsTo = [&](int s) {
        float av[4] = {aPre.x, aPre.y, aPre.z, aPre.w};
        #pragma unroll
        for (int j = 0; j < 4; j++)
            *(float2*)(&As[s][ak4 * 4 + j][2 * arow]) = make_float2(av[j], av[j]);
        #pragma unroll
        for (int i = 0; i < 4; i++) {
            int f = tid + i * 256;
            int k = f >> 6, c4 = f & 63;
            *(float4*)(&Ws[s][k][c4 * 4]) = wPre[i];
        }
    };

    loadG(0);
    stsTo(0);

    for (int t = 0; t < 8; t++) {
        __syncthreads();
        if (t < 7) loadG(t + 1);
        const int s = t & 1;
        #pragma unroll
        for (int k = 0; k < 16; k++) {
            ulonglong2 a01 = *(const ulonglong2*)(&As[s][k][16 * ty + 0]);
            ulonglong2 a23 = *(const ulonglong2*)(&As[s][k][16 * ty + 4]);
            ulonglong2 a45 = *(const ulonglong2*)(&As[s][k][16 * ty + 8]);
            ulonglong2 a67 = *(const ulonglong2*)(&As[s][k][16 * ty + 12]);
            ulonglong2 b1  = *(const ulonglong2*)(&Ws[s][k][tx * 4]);
            ulonglong2 b2  = *(const ulonglong2*)(&Ws[s][k][128 + tx * 4]);
            unsigned long long av[8] = {a01.x, a01.y, a23.x, a23.y,
                                        a45.x, a45.y, a67.x, a67.y};
            #pragma unroll
            for (int i = 0; i < 8; i++) {
                fma2(acc1[i][0], av[i], b1.x);
                fma2(acc1[i][1], av[i], b1.y);
                fma2(acc2[i][0], av[i], b2.x);
                fma2(acc2[i][1], av[i], b2.y);
            }
        }
        if (t < 7) stsTo((t + 1) & 1);
    }

    #pragma unroll
    for (int i = 0; i < 8; i++) {
        int r = r0 + ty * 8 + i;
        if (r >= M) continue;
        ulonglong2 o1; o1.x = acc1[i][0]; o1.y = acc1[i][1];
        ulonglong2 o2; o2.x = acc2[i][0]; o2.y = acc2[i][1];
        *(ulonglong2*)(C1 + (size_t)r * 128 + tx * 4) = o1;
        *(ulonglong2*)(C2 + (size_t)r * 128 + tx * 4) = o2;
    }
}

// ================= dual SGEMM (Ncols=40) =====================================
__global__ __launch_bounds__(256) void k_gemm40_dual(
    const float* __restrict__ Asrc,
    const float* __restrict__ Wa, const float* __restrict__ Wb,
    float* __restrict__ Ca, float* __restrict__ Cb, int M, int Ncols)
{
    const float* W = blockIdx.x ? Wb : Wa;
    float* C = blockIdx.x ? Cb : Ca;

    __shared__ float As[64][68];
    __shared__ float Ws[64][64];

    const int tid = threadIdx.x;
    const int tx = tid & 15;
    const int ty = tid >> 4;
    const int r0 = blockIdx.y * 64;

    float acc[4][4] = {};

    for (int kk = 0; kk < 128; kk += 64) {
        __syncthreads();
        #pragma unroll
        for (int i = 0; i < 4; i++) {
            int f = tid + i * 256;
            int row = f >> 4;
            int k4 = f & 15;
            float4 a = make_float4(0.f, 0.f, 0.f, 0.f);
            int r = r0 + row;
            if (r < M)
                a = *(const float4*)(Asrc + (size_t)r * 128 + kk + k4 * 4);
            *(float4*)(&As[row][k4 * 4]) = a;
        }
        #pragma unroll
        for (int i = 0; i < 16; i++) {
            int f = tid + i * 256;
            int k = f >> 6, c = f & 63;
            Ws[k][c] = (c < Ncols) ? W[(size_t)(kk + k) * Ncols + c] : 0.f;
        }
        __syncthreads();

        #pragma unroll 16
        for (int k = 0; k < 64; k++) {
            float4 b = *(const float4*)(&Ws[k][tx * 4]);
            float a0 = As[ty * 4 + 0][k];
            float a1 = As[ty * 4 + 1][k];
            float a2 = As[ty * 4 + 2][k];
            float a3 = As[ty * 4 + 3][k];
            acc[0][0] += a0 * b.x; acc[0][1] += a0 * b.y; acc[0][2] += a0 * b.z; acc[0][3] += a0 * b.w;
            acc[1][0] += a1 * b.x; acc[1][1] += a1 * b.y; acc[1][2] += a1 * b.z; acc[1][3] += a1 * b.w;
            acc[2][0] += a2 * b.x; acc[2][1] += a2 * b.y; acc[2][2] += a2 * b.z; acc[2][3] += a2 * b.w;
            acc[3][0] += a3 * b.x; acc[3][1] += a3 * b.y; acc[3][2] += a3 * b.z; acc[3][3] += a3 * b.w;
        }
    }

    #pragma unroll
    for (int i = 0; i < 4; i++) {
        int r = r0 + ty * 4 + i;
        if (r >= M) continue;
        #pragma unroll
        for (int j = 0; j < 4; j++) {
            int c = tx * 4 + j;
            if (c < Ncols) C[(size_t)r * Ncols + c] = acc[i][j];
        }
    }
}

// ================= node-centric aggregation (H=4, F=32) =====================
// warp per dst node -> loop trip count is warp-uniform, full-mask shfls safe.
__global__ __launch_bounds__(256) void k_node_h4(
    const float4* __restrict__ gl4, const float4* __restrict__ gr4,
    const float* __restrict__ att,
    const int* __restrict__ off, const int* __restrict__ deg,
    const int* __restrict__ eidx, float4* __restrict__ hout, int mode)
{
    int n = blockIdx.x * 8 + (threadIdx.x >> 5);
    if (n >= N_NODES) return;
    int l = threadIdx.x & 31;

    float4 b = gr4[(size_t)n * 32 + l];
    float4 t = __ldg(&((const float4*)att)[l]);

    float ax = 0.f, ay = 0.f, az = 0.f, aw = 0.f, dw = 0.f;

    int start = off[n], cnt = deg[n];
    for (int base = 0; base < cnt; base += 32) {
        int rem = cnt - base;
        int m = rem < 32 ? rem : 32;
        int eld = (l < m) ? __ldg(&eidx[start + base + l]) : 0;
        for (int j = 0; j < m; j++) {
            int s = __shfl_sync(0xffffffffu, eld, j);
            float4 a = __ldg(&gl4[(size_t)s * 32 + l]);
            float vx = a.x + b.x; vx = vx > 0.f ? vx : SLOPE * vx;
            float vy = a.y + b.y; vy = vy > 0.f ? vy : SLOPE * vy;
            float vz = a.z + b.z; vz = vz > 0.f ? vz : SLOPE * vz;
            float vw = a.w + b.w; vw = vw > 0.f ? vw : SLOPE * vw;
            float p = vx * t.x + vy * t.y + vz * t.z + vw * t.w;
            p += __shfl_xor_sync(0xffffffffu, p, 4);
            p += __shfl_xor_sync(0xffffffffu, p, 2);
            p += __shfl_xor_sync(0xffffffffu, p, 1);
            float w = __expf(p);
            ax += w * a.x; ay += w * a.y; az += w * a.z; aw += w * a.w;
            dw += w;
        }
    }

    float inv = 1.0f / (dw + 1e-16f);
    float4 v = make_float4(ax * inv, ay * inv, az * inv, aw * inv);
    if (mode == 1) {
        v.x = v.x > 0.f ? v.x : expm1f(v.x);
        v.y = v.y > 0.f ? v.y : expm1f(v.y);
        v.z = v.z > 0.f ? v.z : expm1f(v.z);
        v.w = v.w > 0.f ? v.w : expm1f(v.w);
    } else {
        v.x = fmaxf(v.x, 0.f); v.y = fmaxf(v.y, 0.f);
        v.z = fmaxf(v.z, 0.f); v.w = fmaxf(v.w, 0.f);
    }
    hout[(size_t)n * 32 + l] = v;
}

// ================= node-centric layer 3 + log_softmax (H=1, F=40) ===========
// 2 nodes per warp, 16 lanes each. Degree loop trip count DIFFERS between the
// two halves -> every shfl here uses the per-half mask (full-mask was the
// round-4 crash).
__global__ __launch_bounds__(256) void k_node_h1_lsm(
    const float4* __restrict__ gl4, const float4* __restrict__ gr4,
    const float* __restrict__ att,
    const int* __restrict__ off, const int* __restrict__ deg,
    const int* __restrict__ eidx, float* __restrict__ out)
{
    int l = threadIdx.x & 31;
    int sub = l >> 4;
    int ll = l & 15;
    unsigned mask = 0xFFFFu << (sub * 16);
    int n = blockIdx.x * 16 + (threadIdx.x >> 5) * 2 + sub;
    if (n >= N_NODES) return;

    float4 b = make_float4(0.f, 0.f, 0.f, 0.f), t = b;
    if (ll < 10) {
        b = gr4[(size_t)n * 10 + ll];
        t = __ldg(&((const float4*)att)[ll]);
    }

    float ax = 0.f, ay = 0.f, az = 0.f, aw = 0.f, dw = 0.f;

    int start = off[n], cnt = deg[n];
    for (int base = 0; base < cnt; base += 16) {
        int rem = cnt - base;
        int m = rem < 16 ? rem : 16;
        int eld = (ll < m) ? __ldg(&eidx[start + base + ll]) : 0;
        for (int j = 0; j < m; j++) {
            int s = __shfl_sync(mask, eld, j, 16);
            float4 a = make_float4(0.f, 0.f, 0.f, 0.f);
            float p = 0.f;
            if (ll < 10) {
                a = __ldg(&gl4[(size_t)s * 10 + ll]);
                float vx = a.x + b.x; vx = vx > 0.f ? vx : SLOPE * vx;
                float vy = a.y + b.y; vy = vy > 0.f ? vy : SLOPE * vy;
                float vz = a.z + b.z; vz = vz > 0.f ? vz : SLOPE * vz;
                float vw = a.w + b.w; vw = vw > 0.f ? vw : SLOPE * vw;
                p = vx * t.x + vy * t.y + vz * t.z + vw * t.w;
            }
            p += __shfl_xor_sync(mask, p, 8, 16);
            p += __shfl_xor_sync(mask, p, 4, 16);
            p += __shfl_xor_sync(mask, p, 2, 16);
            p += __shfl_xor_sync(mask, p, 1, 16);
            float w = __expf(p);
            ax += w * a.x; ay += w * a.y; az += w * a.z; aw += w * a.w;
            dw += w;
        }
    }

    float inv = 1.0f / (dw + 1e-16f);
    float4 v = make_float4(ax * inv, ay * inv, az * inv, aw * inv);

    // log_softmax over this node's 40 values (lanes ll<10)
    float mx = (ll < 10) ? fmaxf(fmaxf(v.x, v.y), fmaxf(v.z, v.w)) : -FLT_MAX;
    #pragma unroll
    for (int o = 8; o > 0; o >>= 1) mx = fmaxf(mx, __shfl_xor_sync(mask, mx, o, 16));
    float ss = (ll < 10)
        ? (expf(v.x - mx) + expf(v.y - mx) + expf(v.z - mx) + expf(v.w - mx)) : 0.f;
    #pragma unroll
    for (int o = 8; o > 0; o >>= 1) ss += __shfl_xor_sync(mask, ss, o, 16);
    float lse = mx + logf(ss);
    if (ll < 10) {
        float4 r = make_float4(v.x - lse, v.y - lse, v.z - lse, v.w - lse);
        *(float4*)(out + (size_t)n * 40 + 4 * ll) = r;
    }
}

// ---------------- host -------------------------------------------------------
extern "C" void kernel_launch(void* const* d_in, const int* in_sizes, int n_in,
                              void* d_out, int out_size)
{
    const float* x    = (const float*)d_in[0];
    const float* Wl1  = (const float*)d_in[1];
    const float* Wr1  = (const float*)d_in[2];
    const float* att1 = (const float*)d_in[3];
    const float* Wl2  = (const float*)d_in[4];
    const float* Wr2  = (const float*)d_in[5];
    const float* att2 = (const float*)d_in[6];
    const float* Wl3  = (const float*)d_in[7];
    const float* Wr3  = (const float*)d_in[8];
    const float* att3 = (const float*)d_in[9];
    const int*   ei   = (const int*)d_in[10];
    const int* src = ei;
    const int* dst = ei + N_EDGES;
    float* out = (float*)d_out;

    float *gl, *gr, *h;
    int *deg, *off, *cur, *bsum, *eidx;
    cudaGetSymbolAddress((void**)&gl,   g_gl);
    cudaGetSymbolAddress((void**)&gr,   g_gr);
    cudaGetSymbolAddress((void**)&h,    g_h);
    cudaGetSymbolAddress((void**)&deg,  g_deg);
    cudaGetSymbolAddress((void**)&off,  g_off);
    cudaGetSymbolAddress((void**)&cur,  g_cur);
    cudaGetSymbolAddress((void**)&bsum, g_bsum);
    cudaGetSymbolAddress((void**)&eidx, g_eidx);

    const int GB = (N_NODES + 63) / 64;
    const dim3 g40(2, (N_NODES + 63) / 64);
    const int NB4 = (N_NODES + 7) / 8;
    const int NB1 = (N_NODES + 15) / 16;
    const int NSCAN = (N_NODES + 1023) / 1024;   // 49

    // ---- CSR build (once; reused by all layers) ----
    cudaMemsetAsync(deg, 0, N_NODES * sizeof(int));
    k_hist<<<(N_EDGES + 255) / 256, 256>>>(dst, deg);
    k_scan_part<<<NSCAN, 1024>>>(deg, off, bsum);
    k_scan_top<<<1, 64>>>(bsum, NSCAN);
    k_scan_add<<<(N_NODES + 255) / 256, 256>>>(off, cur, bsum);
    k_scatter<<<(N_EDGES + 255) / 256, 256>>>(src, dst, cur, eidx);

    // ---- Layer 1 ----
    k_gemm_dual<<<GB, 256>>>(x, Wl1, Wr1, gl, gr, N_NODES);
    k_node_h4<<<NB4, 256>>>((const float4*)gl, (const float4*)gr, att1,
                            off, deg, eidx, (float4*)h, 1);
    // ---- Layer 2 ----
    k_gemm_dual<<<GB, 256>>>(h, Wl2, Wr2, gl, gr, N_NODES);
    k_node_h4<<<NB4, 256>>>((const float4*)gl, (const float4*)gr, att2,
                            off, deg, eidx, (float4*)h, 2);
    // ---- Layer 3 ----
    k_gemm40_dual<<<g40, 256>>>(h, Wl3, Wr3, gl, gr, N_NODES, 40);
    k_node_h1_lsm<<<NB1, 256>>>((const float4*)gl, (const float4*)gr, att3,
                                off, deg, eidx, out);
}

// round 6
// speedup vs baseline: 3.0740x; 1.2956x over previous
#include <cuda_runtime.h>
#include <cuda_bf16.h>
#include <math.h>
#include <float.h>
#include <stdint.h>

#define N_NODES 50000
#define N_EDGES 800000
#define SLOPE 0.2f

// ---------------- scratch (device globals; no allocation allowed) ----------
__device__ float g_gl[N_NODES * 128];
__device__ float g_gr[N_NODES * 128];
__device__ float g_h[N_NODES * 128];
__device__ int   g_deg[N_NODES];
__device__ int   g_off[N_NODES];
__device__ int   g_cur[N_NODES];
__device__ int   g_bsum[64];
__device__ int   g_eidx[N_EDGES];

// ================= CSR construction ==========================================
__global__ void k_hist(const int* __restrict__ dst, int* __restrict__ deg) {
    int e = blockIdx.x * blockDim.x + threadIdx.x;
    if (e < N_EDGES) atomicAdd(&deg[dst[e]], 1);
}

__global__ __launch_bounds__(1024) void k_scan_part(
    const int* __restrict__ deg, int* __restrict__ off, int* __restrict__ bsum)
{
    __shared__ int sh[1024];
    int t = threadIdx.x;
    int i = blockIdx.x * 1024 + t;
    int v = (i < N_NODES) ? deg[i] : 0;
    sh[t] = v;
    __syncthreads();
    #pragma unroll
    for (int o = 1; o < 1024; o <<= 1) {
        int u = (t >= o) ? sh[t - o] : 0;
        __syncthreads();
        sh[t] += u;
        __syncthreads();
    }
    if (i < N_NODES) off[i] = sh[t] - v;
    if (t == 1023) bsum[blockIdx.x] = sh[t];
}

__global__ __launch_bounds__(64) void k_scan_top(int* __restrict__ bsum, int nb) {
    __shared__ int sh[64];
    int t = threadIdx.x;
    int v = (t < nb) ? bsum[t] : 0;
    sh[t] = v;
    __syncthreads();
    #pragma unroll
    for (int o = 1; o < 64; o <<= 1) {
        int u = (t >= o) ? sh[t - o] : 0;
        __syncthreads();
        sh[t] += u;
        __syncthreads();
    }
    if (t < nb) bsum[t] = sh[t];
}

__global__ void k_scan_add(int* __restrict__ off, int* __restrict__ cur,
                           const int* __restrict__ bsum)
{
    int i = blockIdx.x * blockDim.x + threadIdx.x;
    if (i >= N_NODES) return;
    int b = i >> 10;
    int base = b ? bsum[b - 1] : 0;
    int o = off[i] + base;
    off[i] = o;
    cur[i] = o;
}

__global__ void k_scatter(const int* __restrict__ src, const int* __restrict__ dst,
                          int* __restrict__ cur, int* __restrict__ eidx)
{
    int e = blockIdx.x * blockDim.x + threadIdx.x;
    if (e >= N_EDGES) return;
    int p = atomicAdd(&cur[dst[e]], 1);
    eidx[p] = src[e];
}

// ================= tensor-core helpers =======================================
__device__ __forceinline__ uint32_t smem_u32(const void* p) {
    return (uint32_t)__cvta_generic_to_shared(p);
}
__device__ __forceinline__ void ldsm_x4(uint32_t& r0, uint32_t& r1, uint32_t& r2, uint32_t& r3, uint32_t addr) {
    asm volatile("ldmatrix.sync.aligned.m8n8.x4.shared.b16 {%0,%1,%2,%3},[%4];"
                 : "=r"(r0), "=r"(r1), "=r"(r2), "=r"(r3) : "r"(addr));
}
__device__ __forceinline__ void ldsm_x2_t(uint32_t& r0, uint32_t& r1, uint32_t addr) {
    asm volatile("ldmatrix.sync.aligned.m8n8.x2.trans.shared.b16 {%0,%1},[%2];"
                 : "=r"(r0), "=r"(r1) : "r"(addr));
}
__device__ __forceinline__ void mma_bf16(float* d, const uint32_t* a, const uint32_t* b) {
    asm volatile("mma.sync.aligned.m16n8k16.row.col.f32.bf16.bf16.f32 "
                 "{%0,%1,%2,%3},{%4,%5,%6,%7},{%8,%9},{%0,%1,%2,%3};"
                 : "+f"(d[0]), "+f"(d[1]), "+f"(d[2]), "+f"(d[3])
                 : "r"(a[0]), "r"(a[1]), "r"(a[2]), "r"(a[3]), "r"(b[0]), "r"(b[1]));
}

// ================= tensor-core dual GEMM (bf16x2-split, 3 products) =========
// C = A[M,128] @ W[128,128]; blockIdx.y selects (W1,C1)/(W2,C2).
// Block: 128x128 C tile, 8 warps as 2(m) x 4(n), warp tile 64x32.
__global__ __launch_bounds__(256, 2) void k_gemm_tc(
    const float* __restrict__ A,
    const float* __restrict__ W1, const float* __restrict__ W2,
    float* __restrict__ C1, float* __restrict__ C2, int M)
{
    const float* W = blockIdx.y ? W2 : W1;
    float* C = blockIdx.y ? C2 : C1;

    __shared__ __nv_bfloat16 Ah[128][40];   // 32 k + pad 8 (80B rows, conflict-free ldmatrix)
    __shared__ __nv_bfloat16 Al[128][40];
    __shared__ __nv_bfloat16 Wh[32][136];   // 128 n + pad 8 (272B rows)
    __shared__ __nv_bfloat16 Wl[32][136];

    const int tid = threadIdx.x, lane = tid & 31, wid = tid >> 5;
    const int wm = wid & 1;      // 64 rows per m-warp
    const int wn = wid >> 1;     // 32 cols per n-warp
    const int r0 = blockIdx.x * 128;

    float d[4][4][4];
    #pragma unroll
    for (int i = 0; i < 4; i++)
        #pragma unroll
        for (int j = 0; j < 4; j++)
            #pragma unroll
            for (int k = 0; k < 4; k++) d[i][j][k] = 0.f;

    for (int kt = 0; kt < 4; kt++) {
        // A tile: 128 rows x 32 k fp32 -> hi/lo bf16
        #pragma unroll
        for (int i = 0; i < 4; i++) {
            int idx = tid + i * 256;       // 0..1023 float4
            int row = idx >> 3, q = idx & 7;
            float4 v = make_float4(0.f, 0.f, 0.f, 0.f);
            if (r0 + row < M)
                v = *(const float4*)(A + (size_t)(r0 + row) * 128 + kt * 32 + q * 4);
            float ar[4] = {v.x, v.y, v.z, v.w};
            __nv_bfloat16 h[4], lo[4];
            #pragma unroll
            for (int j = 0; j < 4; j++) {
                h[j] = __float2bfloat16(ar[j]);
                lo[j] = __float2bfloat16(ar[j] - __bfloat162float(h[j]));
            }
            *(uint2*)&Ah[row][q * 4] = *(uint2*)h;
            *(uint2*)&Al[row][q * 4] = *(uint2*)lo;
        }
        // W tile: 32 k x 128 n fp32 -> hi/lo bf16
        #pragma unroll
        for (int i = 0; i < 4; i++) {
            int idx = tid + i * 256;
            int k = idx >> 5, q = idx & 31;
            float4 v = *(const float4*)(W + (size_t)(kt * 32 + k) * 128 + q * 4);
            float ar[4] = {v.x, v.y, v.z, v.w};
            __nv_bfloat16 h[4], lo[4];
            #pragma unroll
            for (int j = 0; j < 4; j++) {
                h[j] = __float2bfloat16(ar[j]);
                lo[j] = __float2bfloat16(ar[j] - __bfloat162float(h[j]));
            }
            *(uint2*)&Wh[k][q * 4] = *(uint2*)h;
            *(uint2*)&Wl[k][q * 4] = *(uint2*)lo;
        }
        __syncthreads();

        // 3 products: ah*wh, al*wh, ah*wl
        #pragma unroll
        for (int ph = 0; ph < 3; ph++) {
            const __nv_bfloat16 (*Asm)[40]  = (ph == 1) ? Al : Ah;
            const __nv_bfloat16 (*Wsm)[136] = (ph == 2) ? Wl : Wh;
            #pragma unroll
            for (int k16 = 0; k16 < 2; k16++) {
                uint32_t af[4][4], bf[4][2];
                #pragma unroll
                for (int mf = 0; mf < 4; mf++) {
                    uint32_t addr = smem_u32(
                        &Asm[wm * 64 + mf * 16 + (lane & 15)][k16 * 16 + (lane >> 4) * 8]);
                    ldsm_x4(af[mf][0], af[mf][1], af[mf][2], af[mf][3], addr);
                }
                #pragma unroll
                for (int nf = 0; nf < 4; nf++) {
                    uint32_t addr = smem_u32(
                        &Wsm[k16 * 16 + (lane & 15)][wn * 32 + nf * 8]);
                    ldsm_x2_t(bf[nf][0], bf[nf][1], addr);
                }
                #pragma unroll
                for (int mf = 0; mf < 4; mf++)
                    #pragma unroll
                    for (int nf = 0; nf < 4; nf++)
                        mma_bf16(d[mf][nf], af[mf], bf[nf]);
            }
        }
        __syncthreads();
    }

    // epilogue: m16n8 frag -> (row g / g+8, col t*2..t*2+1)
    const int g = lane >> 2, t = lane & 3;
    #pragma unroll
    for (int mf = 0; mf < 4; mf++) {
        #pragma unroll
        for (int nf = 0; nf < 4; nf++) {
            int row0 = r0 + wm * 64 + mf * 16 + g;
            int col = wn * 32 + nf * 8 + t * 2;
            if (row0 < M)
                *(float2*)(C + (size_t)row0 * 128 + col) = make_float2(d[mf][nf][0], d[mf][nf][1]);
            if (row0 + 8 < M)
                *(float2*)(C + (size_t)(row0 + 8) * 128 + col) = make_float2(d[mf][nf][2], d[mf][nf][3]);
        }
    }
}

// ================= dual SGEMM (Ncols=40, FFMA) ===============================
__global__ __launch_bounds__(256) void k_gemm40_dual(
    const float* __restrict__ Asrc,
    const float* __restrict__ Wa, const float* __restrict__ Wb,
    float* __restrict__ Ca, float* __restrict__ Cb, int M, int Ncols)
{
    const float* W = blockIdx.x ? Wb : Wa;
    float* C = blockIdx.x ? Cb : Ca;

    __shared__ float As[64][68];
    __shared__ float Ws[64][64];

    const int tid = threadIdx.x;
    const int tx = tid & 15;
    const int ty = tid >> 4;
    const int r0 = blockIdx.y * 64;

    float acc[4][4] = {};

    for (int kk = 0; kk < 128; kk += 64) {
        __syncthreads();
        #pragma unroll
        for (int i = 0; i < 4; i++) {
            int f = tid + i * 256;
            int row = f >> 4;
            int k4 = f & 15;
            float4 a = make_float4(0.f, 0.f, 0.f, 0.f);
            int r = r0 + row;
            if (r < M)
                a = *(const float4*)(Asrc + (size_t)r * 128 + kk + k4 * 4);
            *(float4*)(&As[row][k4 * 4]) = a;
        }
        #pragma unroll
        for (int i = 0; i < 16; i++) {
            int f = tid + i * 256;
            int k = f >> 6, c = f & 63;
            Ws[k][c] = (c < Ncols) ? W[(size_t)(kk + k) * Ncols + c] : 0.f;
        }
        __syncthreads();

        #pragma unroll 16
        for (int k = 0; k < 64; k++) {
            float4 b = *(const float4*)(&Ws[k][tx * 4]);
            float a0 = As[ty * 4 + 0][k];
            float a1 = As[ty * 4 + 1][k];
            float a2 = As[ty * 4 + 2][k];
            float a3 = As[ty * 4 + 3][k];
            acc[0][0] += a0 * b.x; acc[0][1] += a0 * b.y; acc[0][2] += a0 * b.z; acc[0][3] += a0 * b.w;
            acc[1][0] += a1 * b.x; acc[1][1] += a1 * b.y; acc[1][2] += a1 * b.z; acc[1][3] += a1 * b.w;
            acc[2][0] += a2 * b.x; acc[2][1] += a2 * b.y; acc[2][2] += a2 * b.z; acc[2][3] += a2 * b.w;
            acc[3][0] += a3 * b.x; acc[3][1] += a3 * b.y; acc[3][2] += a3 * b.z; acc[3][3] += a3 * b.w;
        }
    }

    #pragma unroll
    for (int i = 0; i < 4; i++) {
        int r = r0 + ty * 4 + i;
        if (r >= M) continue;
        #pragma unroll
        for (int j = 0; j < 4; j++) {
            int c = tx * 4 + j;
            if (c < Ncols) C[(size_t)r * Ncols + c] = acc[i][j];
        }
    }
}

// ================= node-centric aggregation (H=4, F=32) =====================
__global__ __launch_bounds__(256) void k_node_h4(
    const float4* __restrict__ gl4, const float4* __restrict__ gr4,
    const float* __restrict__ att,
    const int* __restrict__ off, const int* __restrict__ deg,
    const int* __restrict__ eidx, float4* __restrict__ hout, int mode)
{
    int n = blockIdx.x * 8 + (threadIdx.x >> 5);
    if (n >= N_NODES) return;
    int l = threadIdx.x & 31;

    float4 b = gr4[(size_t)n * 32 + l];
    float4 t = __ldg(&((const float4*)att)[l]);

    float ax = 0.f, ay = 0.f, az = 0.f, aw = 0.f, dw = 0.f;

    int start = off[n], cnt = deg[n];
    for (int base = 0; base < cnt; base += 32) {
        int rem = cnt - base;
        int m = rem < 32 ? rem : 32;
        int eld = (l < m) ? __ldg(&eidx[start + base + l]) : 0;
        for (int j = 0; j < m; j++) {
            int s = __shfl_sync(0xffffffffu, eld, j);
            float4 a = __ldg(&gl4[(size_t)s * 32 + l]);
            float vx = a.x + b.x; vx = vx > 0.f ? vx : SLOPE * vx;
            float vy = a.y + b.y; vy = vy > 0.f ? vy : SLOPE * vy;
            float vz = a.z + b.z; vz = vz > 0.f ? vz : SLOPE * vz;
            float vw = a.w + b.w; vw = vw > 0.f ? vw : SLOPE * vw;
            float p = vx * t.x + vy * t.y + vz * t.z + vw * t.w;
            p += __shfl_xor_sync(0xffffffffu, p, 4);
            p += __shfl_xor_sync(0xffffffffu, p, 2);
            p += __shfl_xor_sync(0xffffffffu, p, 1);
            float w = __expf(p);
            ax += w * a.x; ay += w * a.y; az += w * a.z; aw += w * a.w;
            dw += w;
        }
    }

    float inv = 1.0f / (dw + 1e-16f);
    float4 v = make_float4(ax * inv, ay * inv, az * inv, aw * inv);
    if (mode == 1) {
        v.x = v.x > 0.f ? v.x : expm1f(v.x);
        v.y = v.y > 0.f ? v.y : expm1f(v.y);
        v.z = v.z > 0.f ? v.z : expm1f(v.z);
        v.w = v.w > 0.f ? v.w : expm1f(v.w);
    } else {
        v.x = fmaxf(v.x, 0.f); v.y = fmaxf(v.y, 0.f);
        v.z = fmaxf(v.z, 0.f); v.w = fmaxf(v.w, 0.f);
    }
    hout[(size_t)n * 32 + l] = v;
}

// ================= node-centric layer 3 + log_softmax (H=1, F=40) ===========
__global__ __launch_bounds__(256) void k_node_h1_lsm(
    const float4* __restrict__ gl4, const float4* __restrict__ gr4,
    const float* __restrict__ att,
    const int* __restrict__ off, const int* __restrict__ deg,
    const int* __restrict__ eidx, float* __restrict__ out)
{
    int l = threadIdx.x & 31;
    int sub = l >> 4;
    int ll = l & 15;
    unsigned mask = 0xFFFFu << (sub * 16);
    int n = blockIdx.x * 16 + (threadIdx.x >> 5) * 2 + sub;
    if (n >= N_NODES) return;

    float4 b = make_float4(0.f, 0.f, 0.f, 0.f), t = b;
    if (ll < 10) {
        b = gr4[(size_t)n * 10 + ll];
        t = __ldg(&((const float4*)att)[ll]);
    }

    float ax = 0.f, ay = 0.f, az = 0.f, aw = 0.f, dw = 0.f;

    int start = off[n], cnt = deg[n];
    for (int base = 0; base < cnt; base += 16) {
        int rem = cnt - base;
        int m = rem < 16 ? rem : 16;
        int eld = (ll < m) ? __ldg(&eidx[start + base + ll]) : 0;
        for (int j = 0; j < m; j++) {
            int s = __shfl_sync(mask, eld, j, 16);
            float4 a = make_float4(0.f, 0.f, 0.f, 0.f);
            float p = 0.f;
            if (ll < 10) {
                a = __ldg(&gl4[(size_t)s * 10 + ll]);
                float vx = a.x + b.x; vx = vx > 0.f ? vx : SLOPE * vx;
                float vy = a.y + b.y; vy = vy > 0.f ? vy : SLOPE * vy;
                float vz = a.z + b.z; vz = vz > 0.f ? vz : SLOPE * vz;
                float vw = a.w + b.w; vw = vw > 0.f ? vw : SLOPE * vw;
                p = vx * t.x + vy * t.y + vz * t.z + vw * t.w;
            }
            p += __shfl_xor_sync(mask, p, 8, 16);
            p += __shfl_xor_sync(mask, p, 4, 16);
            p += __shfl_xor_sync(mask, p, 2, 16);
            p += __shfl_xor_sync(mask, p, 1, 16);
            float w = __expf(p);
            ax += w * a.x; ay += w * a.y; az += w * a.z; aw += w * a.w;
            dw += w;
        }
    }

    float inv = 1.0f / (dw + 1e-16f);
    float4 v = make_float4(ax * inv, ay * inv, az * inv, aw * inv);

    float mx = (ll < 10) ? fmaxf(fmaxf(v.x, v.y), fmaxf(v.z, v.w)) : -FLT_MAX;
    #pragma unroll
    for (int o = 8; o > 0; o >>= 1) mx = fmaxf(mx, __shfl_xor_sync(mask, mx, o, 16));
    float ss = (ll < 10)
        ? (expf(v.x - mx) + expf(v.y - mx) + expf(v.z - mx) + expf(v.w - mx)) : 0.f;
    #pragma unroll
    for (int o = 8; o > 0; o >>= 1) ss += __shfl_xor_sync(mask, ss, o, 16);
    float lse = mx + logf(ss);
    if (ll < 10) {
        float4 r = make_float4(v.x - lse, v.y - lse, v.z - lse, v.w - lse);
        *(float4*)(out + (size_t)n * 40 + 4 * ll) = r;
    }
}

// ---------------- host -------------------------------------------------------
extern "C" void kernel_launch(void* const* d_in, const int* in_sizes, int n_in,
                              void* d_out, int out_size)
{
    const float* x    = (const float*)d_in[0];
    const float* Wl1  = (const float*)d_in[1];
    const float* Wr1  = (const float*)d_in[2];
    const float* att1 = (const float*)d_in[3];
    const float* Wl2  = (const float*)d_in[4];
    const float* Wr2  = (const float*)d_in[5];
    const float* att2 = (const float*)d_in[6];
    const float* Wl3  = (const float*)d_in[7];
    const float* Wr3  = (const float*)d_in[8];
    const float* att3 = (const float*)d_in[9];
    const int*   ei   = (const int*)d_in[10];
    const int* src = ei;
    const int* dst = ei + N_EDGES;
    float* out = (float*)d_out;

    float *gl, *gr, *h;
    int *deg, *off, *cur, *bsum, *eidx;
    cudaGetSymbolAddress((void**)&gl,   g_gl);
    cudaGetSymbolAddress((void**)&gr,   g_gr);
    cudaGetSymbolAddress((void**)&h,    g_h);
    cudaGetSymbolAddress((void**)&deg,  g_deg);
    cudaGetSymbolAddress((void**)&off,  g_off);
    cudaGetSymbolAddress((void**)&cur,  g_cur);
    cudaGetSymbolAddress((void**)&bsum, g_bsum);
    cudaGetSymbolAddress((void**)&eidx, g_eidx);

    const dim3 gTC((N_NODES + 127) / 128, 2);   // 391 x 2
    const dim3 g40(2, (N_NODES + 63) / 64);
    const int NB4 = (N_NODES + 7) / 8;
    const int NB1 = (N_NODES + 15) / 16;
    const int NSCAN = (N_NODES + 1023) / 1024;

    // ---- CSR build (once; reused by all layers) ----
    cudaMemsetAsync(deg, 0, N_NODES * sizeof(int));
    k_hist<<<(N_EDGES + 255) / 256, 256>>>(dst, deg);
    k_scan_part<<<NSCAN, 1024>>>(deg, off, bsum);
    k_scan_top<<<1, 64>>>(bsum, NSCAN);
    k_scan_add<<<(N_NODES + 255) / 256, 256>>>(off, cur, bsum);
    k_scatter<<<(N_EDGES + 255) / 256, 256>>>(src, dst, cur, eidx);

    // ---- Layer 1 ----
    k_gemm_tc<<<gTC, 256>>>(x, Wl1, Wr1, gl, gr, N_NODES);
    k_node_h4<<<NB4, 256>>>((const float4*)gl, (const float4*)gr, att1,
                            off, deg, eidx, (float4*)h, 1);
    // ---- Layer 2 ----
    k_gemm_tc<<<gTC, 256>>>(h, Wl2, Wr2, gl, gr, N_NODES);
    k_node_h4<<<NB4, 256>>>((const float4*)gl, (const float4*)gr, att2,
                            off, deg, eidx, (float4*)h, 2);
    // ---- Layer 3 ----
    k_gemm40_dual<<<g40, 256>>>(h, Wl3, Wr3, gl, gr, N_NODES, 40);
    k_node_h1_lsm<<<NB1, 256>>>((const float4*)gl, (const float4*)gr, att3,
                                off, deg, eidx, out);
}

// round 7
// speedup vs baseline: 3.0788x; 1.0016x over previous
#include <cuda_runtime.h>
#include <cuda_bf16.h>
#include <math.h>
#include <float.h>
#include <stdint.h>

#define N_NODES 50000
#define N_EDGES 800000
#define SLOPE 0.2f

// ---------------- scratch (device globals; no allocation allowed) ----------
__device__ float    g_gl[N_NODES * 128];
__device__ float    g_gr[N_NODES * 128];
__device__ uint32_t g_xs[N_NODES * 128];   // packed (hi,lo) bf16 split of x
__device__ uint32_t g_hs[N_NODES * 128];   // packed split of hidden h
__device__ uint32_t g_ws[4 * 16384];       // packed splits of Wl1,Wr1,Wl2,Wr2
__device__ int      g_deg[N_NODES];
__device__ int      g_off[N_NODES];
__device__ int      g_cur[N_NODES];
__device__ int      g_bsum[64];
__device__ int      g_eidx[N_EDGES];

// ---- bf16 hi/lo split pack -------------------------------------------------
__device__ __forceinline__ uint32_t packsplit(float x) {
    __nv_bfloat16 h = __float2bfloat16(x);
    __nv_bfloat16 l = __float2bfloat16(x - __bfloat162float(h));
    return ((uint32_t)__bfloat16_as_ushort(h) << 16) | (uint32_t)__bfloat16_as_ushort(l);
}
__device__ __forceinline__ float unpacksplit(uint32_t v) {
    __nv_bfloat16 h = __ushort_as_bfloat16((unsigned short)(v >> 16));
    __nv_bfloat16 l = __ushort_as_bfloat16((unsigned short)(v & 0xffff));
    return __bfloat162float(h) + __bfloat162float(l);
}

__global__ void k_split(const float* __restrict__ in, uint32_t* __restrict__ outp, int n) {
    int i = (blockIdx.x * blockDim.x + threadIdx.x) * 4;
    if (i >= n) return;
    float4 v = *(const float4*)(in + i);
    uint4 o;
    o.x = packsplit(v.x); o.y = packsplit(v.y);
    o.z = packsplit(v.z); o.w = packsplit(v.w);
    *(uint4*)(outp + i) = o;
}

// ================= CSR construction ==========================================
__global__ void k_hist(const int* __restrict__ dst, int* __restrict__ deg) {
    int e = blockIdx.x * blockDim.x + threadIdx.x;
    if (e < N_EDGES) atomicAdd(&deg[dst[e]], 1);
}

__global__ __launch_bounds__(1024) void k_scan_part(
    const int* __restrict__ deg, int* __restrict__ off, int* __restrict__ bsum)
{
    __shared__ int sh[1024];
    int t = threadIdx.x;
    int i = blockIdx.x * 1024 + t;
    int v = (i < N_NODES) ? deg[i] : 0;
    sh[t] = v;
    __syncthreads();
    #pragma unroll
    for (int o = 1; o < 1024; o <<= 1) {
        int u = (t >= o) ? sh[t - o] : 0;
        __syncthreads();
        sh[t] += u;
        __syncthreads();
    }
    if (i < N_NODES) off[i] = sh[t] - v;
    if (t == 1023) bsum[blockIdx.x] = sh[t];
}

__global__ __launch_bounds__(64) void k_scan_top(int* __restrict__ bsum, int nb) {
    __shared__ int sh[64];
    int t = threadIdx.x;
    int v = (t < nb) ? bsum[t] : 0;
    sh[t] = v;
    __syncthreads();
    #pragma unroll
    for (int o = 1; o < 64; o <<= 1) {
        int u = (t >= o) ? sh[t - o] : 0;
        __syncthreads();
        sh[t] += u;
        __syncthreads();
    }
    if (t < nb) bsum[t] = sh[t];
}

__global__ void k_scan_add(int* __restrict__ off, int* __restrict__ cur,
                           const int* __restrict__ bsum)
{
    int i = blockIdx.x * blockDim.x + threadIdx.x;
    if (i >= N_NODES) return;
    int b = i >> 10;
    int base = b ? bsum[b - 1] : 0;
    int o = off[i] + base;
    off[i] = o;
    cur[i] = o;
}

__global__ void k_scatter(const int* __restrict__ src, const int* __restrict__ dst,
                          int* __restrict__ cur, int* __restrict__ eidx)
{
    int e = blockIdx.x * blockDim.x + threadIdx.x;
    if (e >= N_EDGES) return;
    int p = atomicAdd(&cur[dst[e]], 1);
    eidx[p] = src[e];
}

// ================= tensor-core helpers =======================================
__device__ __forceinline__ uint32_t smem_u32(const void* p) {
    return (uint32_t)__cvta_generic_to_shared(p);
}
__device__ __forceinline__ void ldsm_x4(uint32_t& r0, uint32_t& r1, uint32_t& r2, uint32_t& r3, uint32_t addr) {
    asm volatile("ldmatrix.sync.aligned.m8n8.x4.shared.b16 {%0,%1,%2,%3},[%4];"
                 : "=r"(r0), "=r"(r1), "=r"(r2), "=r"(r3) : "r"(addr));
}
__device__ __forceinline__ void ldsm_x2_t(uint32_t& r0, uint32_t& r1, uint32_t addr) {
    asm volatile("ldmatrix.sync.aligned.m8n8.x2.trans.shared.b16 {%0,%1},[%2];"
                 : "=r"(r0), "=r"(r1) : "r"(addr));
}
__device__ __forceinline__ void mma_bf16(float* d, const uint32_t* a, const uint32_t* b) {
    asm volatile("mma.sync.aligned.m16n8k16.row.col.f32.bf16.bf16.f32 "
                 "{%0,%1,%2,%3},{%4,%5,%6,%7},{%8,%9},{%0,%1,%2,%3};"
                 : "+f"(d[0]), "+f"(d[1]), "+f"(d[2]), "+f"(d[3])
                 : "r"(a[0]), "r"(a[1]), "r"(a[2]), "r"(b[0]), "r"(b[1]), "r"(a[3]));
}
// NOTE: operand order matters; use explicit correct version below.
__device__ __forceinline__ void mma_bf16c(float* d, const uint32_t* a, const uint32_t* b) {
    asm volatile("mma.sync.aligned.m16n8k16.row.col.f32.bf16.bf16.f32 "
                 "{%0,%1,%2,%3},{%4,%5,%6,%7},{%8,%9},{%0,%1,%2,%3};"
                 : "+f"(d[0]), "+f"(d[1]), "+f"(d[2]), "+f"(d[3])
                 : "r"(a[0]), "r"(a[1]), "r"(a[2]), "r"(a[3]), "r"(b[0]), "r"(b[1]));
}

// ================= TC dual GEMM on pre-split inputs ==========================
// C1 = A@W1, C2 = A@W2 in ONE CTA. A:[M,128] packed, W:[128,128] packed.
// BM=64, dual-N=256. 8 warps: wm in {0,1} (32 rows), wn in {0..3} (64 cols).
// 3 error-compensated products: ah*wh + al*wh + ah*wl.
__global__ __launch_bounds__(256, 2) void k_gemm_tc2(
    const uint32_t* __restrict__ Ap,
    const uint32_t* __restrict__ W1p, const uint32_t* __restrict__ W2p,
    float* __restrict__ C1, float* __restrict__ C2, int M)
{
    __shared__ __nv_bfloat16 Ah[64][40];     // 32 k + pad 8
    __shared__ __nv_bfloat16 Al[64][40];
    __shared__ __nv_bfloat16 Wh[32][264];    // 256 n + pad 8
    __shared__ __nv_bfloat16 Wl[32][264];

    const int tid = threadIdx.x, lane = tid & 31, wid = tid >> 5;
    const int wm = wid & 1;       // 32-row group
    const int wn = wid >> 1;      // 64-col group within 256
    const int r0 = blockIdx.x * 64;

    float d[2][8][4];
    #pragma unroll
    for (int i = 0; i < 2; i++)
        #pragma unroll
        for (int j = 0; j < 8; j++)
            #pragma unroll
            for (int k = 0; k < 4; k++) d[i][j][k] = 0.f;

    for (int kt = 0; kt < 4; kt++) {
        // A tile: 64 rows x 32 k packed -> 512 uint4, 2 per thread
        #pragma unroll
        for (int i = 0; i < 2; i++) {
            int idx = tid + i * 256;
            int row = idx >> 3, q = idx & 7;
            uint4 p = make_uint4(0u, 0u, 0u, 0u);
            if (r0 + row < M)
                p = *(const uint4*)(Ap + (size_t)(r0 + row) * 128 + kt * 32 + q * 4);
            uint2 hi, lo;
            hi.x = __byte_perm(p.x, p.y, 0x7632); hi.y = __byte_perm(p.z, p.w, 0x7632);
            lo.x = __byte_perm(p.x, p.y, 0x5410); lo.y = __byte_perm(p.z, p.w, 0x5410);
            *(uint2*)&Ah[row][q * 4] = hi;
            *(uint2*)&Al[row][q * 4] = lo;
        }
        // W tile: 32 k x 256 n packed -> 2048 uint4, 8 per thread
        #pragma unroll
        for (int i = 0; i < 8; i++) {
            int idx = tid + i * 256;
            int k = idx >> 6, q = idx & 63;
            uint4 p = (q < 32)
                ? *(const uint4*)(W1p + (size_t)(kt * 32 + k) * 128 + q * 4)
                : *(const uint4*)(W2p + (size_t)(kt * 32 + k) * 128 + (q - 32) * 4);
            uint2 hi, lo;
            hi.x = __byte_perm(p.x, p.y, 0x7632); hi.y = __byte_perm(p.z, p.w, 0x7632);
            lo.x = __byte_perm(p.x, p.y, 0x5410); lo.y = __byte_perm(p.z, p.w, 0x5410);
            *(uint2*)&Wh[k][q * 4] = hi;
            *(uint2*)&Wl[k][q * 4] = lo;
        }
        __syncthreads();

        #pragma unroll
        for (int ph = 0; ph < 3; ph++) {
            const __nv_bfloat16 (*Asm)[40]  = (ph == 1) ? Al : Ah;
            const __nv_bfloat16 (*Wsm)[264] = (ph == 2) ? Wl : Wh;
            #pragma unroll
            for (int k16 = 0; k16 < 2; k16++) {
                uint32_t af[2][4], bfr[8][2];
                #pragma unroll
                for (int mf = 0; mf < 2; mf++) {
                    uint32_t addr = smem_u32(
                        &Asm[wm * 32 + mf * 16 + (lane & 15)][k16 * 16 + (lane >> 4) * 8]);
                    ldsm_x4(af[mf][0], af[mf][1], af[mf][2], af[mf][3], addr);
                }
                #pragma unroll
                for (int nf = 0; nf < 8; nf++) {
                    uint32_t addr = smem_u32(
                        &Wsm[k16 * 16 + (lane & 15)][wn * 64 + nf * 8]);
                    ldsm_x2_t(bfr[nf][0], bfr[nf][1], addr);
                }
                #pragma unroll
                for (int mf = 0; mf < 2; mf++)
                    #pragma unroll
                    for (int nf = 0; nf < 8; nf++)
                        mma_bf16c(d[mf][nf], af[mf], bfr[nf]);
            }
        }
        __syncthreads();
    }

    const int g = lane >> 2, t = lane & 3;
    float* Cp = (wn < 2) ? C1 : C2;
    int cbase = (wn < 2) ? wn * 64 : (wn - 2) * 64;
    #pragma unroll
    for (int mf = 0; mf < 2; mf++) {
        #pragma unroll
        for (int nf = 0; nf < 8; nf++) {
            int row0 = r0 + wm * 32 + mf * 16 + g;
            int col = cbase + nf * 8 + t * 2;
            if (row0 < M)
                *(float2*)(Cp + (size_t)row0 * 128 + col) = make_float2(d[mf][nf][0], d[mf][nf][1]);
            if (row0 + 8 < M)
                *(float2*)(Cp + (size_t)(row0 + 8) * 128 + col) = make_float2(d[mf][nf][2], d[mf][nf][3]);
        }
    }
}

// ================= dual SGEMM (Ncols=40, FFMA, packed A) =====================
__global__ __launch_bounds__(256) void k_gemm40_dual(
    const uint32_t* __restrict__ Ap,
    const float* __restrict__ Wa, const float* __restrict__ Wb,
    float* __restrict__ Ca, float* __restrict__ Cb, int M, int Ncols)
{
    const float* W = blockIdx.x ? Wb : Wa;
    float* C = blockIdx.x ? Cb : Ca;

    __shared__ float As[64][68];
    __shared__ float Ws[64][64];

    const int tid = threadIdx.x;
    const int tx = tid & 15;
    const int ty = tid >> 4;
    const int r0 = blockIdx.y * 64;

    float acc[4][4] = {};

    for (int kk = 0; kk < 128; kk += 64) {
        __syncthreads();
        #pragma unroll
        for (int i = 0; i < 4; i++) {
            int f = tid + i * 256;
            int row = f >> 4;
            int k4 = f & 15;
            float4 a = make_float4(0.f, 0.f, 0.f, 0.f);
            int r = r0 + row;
            if (r < M) {
                uint4 p = *(const uint4*)(Ap + (size_t)r * 128 + kk + k4 * 4);
                a.x = unpacksplit(p.x); a.y = unpacksplit(p.y);
                a.z = unpacksplit(p.z); a.w = unpacksplit(p.w);
            }
            *(float4*)(&As[row][k4 * 4]) = a;
        }
        #pragma unroll
        for (int i = 0; i < 16; i++) {
            int f = tid + i * 256;
            int k = f >> 6, c = f & 63;
            Ws[k][c] = (c < Ncols) ? W[(size_t)(kk + k) * Ncols + c] : 0.f;
        }
        __syncthreads();

        #pragma unroll 16
        for (int k = 0; k < 64; k++) {
            float4 b = *(const float4*)(&Ws[k][tx * 4]);
            float a0 = As[ty * 4 + 0][k];
            float a1 = As[ty * 4 + 1][k];
            float a2 = As[ty * 4 + 2][k];
            float a3 = As[ty * 4 + 3][k];
            acc[0][0] += a0 * b.x; acc[0][1] += a0 * b.y; acc[0][2] += a0 * b.z; acc[0][3] += a0 * b.w;
            acc[1][0] += a1 * b.x; acc[1][1] += a1 * b.y; acc[1][2] += a1 * b.z; acc[1][3] += a1 * b.w;
            acc[2][0] += a2 * b.x; acc[2][1] += a2 * b.y; acc[2][2] += a2 * b.z; acc[2][3] += a2 * b.w;
            acc[3][0] += a3 * b.x; acc[3][1] += a3 * b.y; acc[3][2] += a3 * b.z; acc[3][3] += a3 * b.w;
        }
    }

    #pragma unroll
    for (int i = 0; i < 4; i++) {
        int r = r0 + ty * 4 + i;
        if (r >= M) continue;
        #pragma unroll
        for (int j = 0; j < 4; j++) {
            int c = tx * 4 + j;
            if (c < Ncols) C[(size_t)r * Ncols + c] = acc[i][j];
        }
    }
}

// ================= node-centric aggregation (H=4, F=32) =====================
// warp per dst node; writes PACKED split output. 2-edge unroll for MLP.
__global__ __launch_bounds__(256) void k_node_h4(
    const float4* __restrict__ gl4, const float4* __restrict__ gr4,
    const float* __restrict__ att,
    const int* __restrict__ off, const int* __restrict__ deg,
    const int* __restrict__ eidx, uint4* __restrict__ houtp, int mode)
{
    int n = blockIdx.x * 8 + (threadIdx.x >> 5);
    if (n >= N_NODES) return;
    int l = threadIdx.x & 31;

    float4 b = gr4[(size_t)n * 32 + l];
    float4 t = __ldg(&((const float4*)att)[l]);

    float ax = 0.f, ay = 0.f, az = 0.f, aw = 0.f, dw = 0.f;

    int start = off[n], cnt = deg[n];
    for (int base = 0; base < cnt; base += 32) {
        int rem = cnt - base;
        int m = rem < 32 ? rem : 32;
        int eld = (l < m) ? __ldg(&eidx[start + base + l]) : 0;
        int j = 0;
        for (; j + 1 < m; j += 2) {
            int s0 = __shfl_sync(0xffffffffu, eld, j);
            int s1 = __shfl_sync(0xffffffffu, eld, j + 1);
            float4 a0 = __ldg(&gl4[(size_t)s0 * 32 + l]);
            float4 a1 = __ldg(&gl4[(size_t)s1 * 32 + l]);

            float v0x = a0.x + b.x; v0x = v0x > 0.f ? v0x : SLOPE * v0x;
            float v0y = a0.y + b.y; v0y = v0y > 0.f ? v0y : SLOPE * v0y;
            float v0z = a0.z + b.z; v0z = v0z > 0.f ? v0z : SLOPE * v0z;
            float v0w = a0.w + b.w; v0w = v0w > 0.f ? v0w : SLOPE * v0w;
            float p0 = v0x * t.x + v0y * t.y + v0z * t.z + v0w * t.w;

            float v1x = a1.x + b.x; v1x = v1x > 0.f ? v1x : SLOPE * v1x;
            float v1y = a1.y + b.y; v1y = v1y > 0.f ? v1y : SLOPE * v1y;
            float v1z = a1.z + b.z; v1z = v1z > 0.f ? v1z : SLOPE * v1z;
            float v1w = a1.w + b.w; v1w = v1w > 0.f ? v1w : SLOPE * v1w;
            float p1 = v1x * t.x + v1y * t.y + v1z * t.z + v1w * t.w;

            p0 += __shfl_xor_sync(0xffffffffu, p0, 4);
            p1 += __shfl_xor_sync(0xffffffffu, p1, 4);
            p0 += __shfl_xor_sync(0xffffffffu, p0, 2);
            p1 += __shfl_xor_sync(0xffffffffu, p1, 2);
            p0 += __shfl_xor_sync(0xffffffffu, p0, 1);
            p1 += __shfl_xor_sync(0xffffffffu, p1, 1);
            float w0 = __expf(p0), w1 = __expf(p1);

            ax += w0 * a0.x + w1 * a1.x;
            ay += w0 * a0.y + w1 * a1.y;
            az += w0 * a0.z + w1 * a1.z;
            aw += w0 * a0.w + w1 * a1.w;
            dw += w0 + w1;
        }
        if (j < m) {
            int s = __shfl_sync(0xffffffffu, eld, j);
            float4 a = __ldg(&gl4[(size_t)s * 32 + l]);
            float vx = a.x + b.x; vx = vx > 0.f ? vx : SLOPE * vx;
            float vy = a.y + b.y; vy = vy > 0.f ? vy : SLOPE * vy;
            float vz = a.z + b.z; vz = vz > 0.f ? vz : SLOPE * vz;
            float vw = a.w + b.w; vw = vw > 0.f ? vw : SLOPE * vw;
            float p = vx * t.x + vy * t.y + vz * t.z + vw * t.w;
            p += __shfl_xor_sync(0xffffffffu, p, 4);
            p += __shfl_xor_sync(0xffffffffu, p, 2);
            p += __shfl_xor_sync(0xffffffffu, p, 1);
            float w = __expf(p);
            ax += w * a.x; ay += w * a.y; az += w * a.z; aw += w * a.w;
            dw += w;
        }
    }

    float inv = 1.0f / (dw + 1e-16f);
    float4 v = make_float4(ax * inv, ay * inv, az * inv, aw * inv);
    if (mode == 1) {
        v.x = v.x > 0.f ? v.x : expm1f(v.x);
        v.y = v.y > 0.f ? v.y : expm1f(v.y);
        v.z = v.z > 0.f ? v.z : expm1f(v.z);
        v.w = v.w > 0.f ? v.w : expm1f(v.w);
    } else {
        v.x = fmaxf(v.x, 0.f); v.y = fmaxf(v.y, 0.f);
        v.z = fmaxf(v.z, 0.f); v.w = fmaxf(v.w, 0.f);
    }
    uint4 o;
    o.x = packsplit(v.x); o.y = packsplit(v.y);
    o.z = packsplit(v.z); o.w = packsplit(v.w);
    houtp[(size_t)n * 32 + l] = o;
}

// ================= node-centric layer 3 + log_softmax (H=1, F=40) ===========
__global__ __launch_bounds__(256) void k_node_h1_lsm(
    const float4* __restrict__ gl4, const float4* __restrict__ gr4,
    const float* __restrict__ att,
    const int* __restrict__ off, const int* __restrict__ deg,
    const int* __restrict__ eidx, float* __restrict__ out)
{
    int l = threadIdx.x & 31;
    int sub = l >> 4;
    int ll = l & 15;
    unsigned mask = 0xFFFFu << (sub * 16);
    int n = blockIdx.x * 16 + (threadIdx.x >> 5) * 2 + sub;
    if (n >= N_NODES) return;

    float4 b = make_float4(0.f, 0.f, 0.f, 0.f), t = b;
    if (ll < 10) {
        b = gr4[(size_t)n * 10 + ll];
        t = __ldg(&((const float4*)att)[ll]);
    }

    float ax = 0.f, ay = 0.f, az = 0.f, aw = 0.f, dw = 0.f;

    int start = off[n], cnt = deg[n];
    for (int base = 0; base < cnt; base += 16) {
        int rem = cnt - base;
        int m = rem < 16 ? rem : 16;
        int eld = (ll < m) ? __ldg(&eidx[start + base + ll]) : 0;
        for (int j = 0; j < m; j++) {
            int s = __shfl_sync(mask, eld, j, 16);
            float4 a = make_float4(0.f, 0.f, 0.f, 0.f);
            float p = 0.f;
            if (ll < 10) {
                a = __ldg(&gl4[(size_t)s * 10 + ll]);
                float vx = a.x + b.x; vx = vx > 0.f ? vx : SLOPE * vx;
                float vy = a.y + b.y; vy = vy > 0.f ? vy : SLOPE * vy;
                float vz = a.z + b.z; vz = vz > 0.f ? vz : SLOPE * vz;
                float vw = a.w + b.w; vw = vw > 0.f ? vw : SLOPE * vw;
                p = vx * t.x + vy * t.y + vz * t.z + vw * t.w;
            }
            p += __shfl_xor_sync(mask, p, 8, 16);
            p += __shfl_xor_sync(mask, p, 4, 16);
            p += __shfl_xor_sync(mask, p, 2, 16);
            p += __shfl_xor_sync(mask, p, 1, 16);
            float w = __expf(p);
            ax += w * a.x; ay += w * a.y; az += w * a.z; aw += w * a.w;
            dw += w;
        }
    }

    float inv = 1.0f / (dw + 1e-16f);
    float4 v = make_float4(ax * inv, ay * inv, az * inv, aw * inv);

    float mx = (ll < 10) ? fmaxf(fmaxf(v.x, v.y), fmaxf(v.z, v.w)) : -FLT_MAX;
    #pragma unroll
    for (int o = 8; o > 0; o >>= 1) mx = fmaxf(mx, __shfl_xor_sync(mask, mx, o, 16));
    float ss = (ll < 10)
        ? (expf(v.x - mx) + expf(v.y - mx) + expf(v.z - mx) + expf(v.w - mx)) : 0.f;
    #pragma unroll
    for (int o = 8; o > 0; o >>= 1) ss += __shfl_xor_sync(mask, ss, o, 16);
    float lse = mx + logf(ss);
    if (ll < 10) {
        float4 r = make_float4(v.x - lse, v.y - lse, v.z - lse, v.w - lse);
        *(float4*)(out + (size_t)n * 40 + 4 * ll) = r;
    }
}

// ---------------- host -------------------------------------------------------
extern "C" void kernel_launch(void* const* d_in, const int* in_sizes, int n_in,
                              void* d_out, int out_size)
{
    const float* x    = (const float*)d_in[0];
    const float* Wl1  = (const float*)d_in[1];
    const float* Wr1  = (const float*)d_in[2];
    const float* att1 = (const float*)d_in[3];
    const float* Wl2  = (const float*)d_in[4];
    const float* Wr2  = (const float*)d_in[5];
    const float* att2 = (const float*)d_in[6];
    const float* Wl3  = (const float*)d_in[7];
    const float* Wr3  = (const float*)d_in[8];
    const float* att3 = (const float*)d_in[9];
    const int*   ei   = (const int*)d_in[10];
    const int* src = ei;
    const int* dst = ei + N_EDGES;
    float* out = (float*)d_out;

    float *gl, *gr;
    uint32_t *xs, *hs, *ws;
    int *deg, *off, *cur, *bsum, *eidx;
    cudaGetSymbolAddress((void**)&gl,   g_gl);
    cudaGetSymbolAddress((void**)&gr,   g_gr);
    cudaGetSymbolAddress((void**)&xs,   g_xs);
    cudaGetSymbolAddress((void**)&hs,   g_hs);
    cudaGetSymbolAddress((void**)&ws,   g_ws);
    cudaGetSymbolAddress((void**)&deg,  g_deg);
    cudaGetSymbolAddress((void**)&off,  g_off);
    cudaGetSymbolAddress((void**)&cur,  g_cur);
    cudaGetSymbolAddress((void**)&bsum, g_bsum);
    cudaGetSymbolAddress((void**)&eidx, g_eidx);

    const int GB = (N_NODES + 63) / 64;         // 782
    const dim3 g40(2, (N_NODES + 63) / 64);
    const int NB4 = (N_NODES + 7) / 8;
    const int NB1 = (N_NODES + 15) / 16;
    const int NSCAN = (N_NODES + 1023) / 1024;

    // ---- one-time splits ----
    k_split<<<(N_NODES * 128 / 4 + 255) / 256, 256>>>(x, xs, N_NODES * 128);
    k_split<<<(16384 / 4 + 255) / 256, 256>>>(Wl1, ws + 0 * 16384, 16384);
    k_split<<<(16384 / 4 + 255) / 256, 256>>>(Wr1, ws + 1 * 16384, 16384);
    k_split<<<(16384 / 4 + 255) / 256, 256>>>(Wl2, ws + 2 * 16384, 16384);
    k_split<<<(16384 / 4 + 255) / 256, 256>>>(Wr2, ws + 3 * 16384, 16384);

    // ---- CSR build (once) ----
    cudaMemsetAsync(deg, 0, N_NODES * sizeof(int));
    k_hist<<<(N_EDGES + 255) / 256, 256>>>(dst, deg);
    k_scan_part<<<NSCAN, 1024>>>(deg, off, bsum);
    k_scan_top<<<1, 64>>>(bsum, NSCAN);
    k_scan_add<<<(N_NODES + 255) / 256, 256>>>(off, cur, bsum);
    k_scatter<<<(N_EDGES + 255) / 256, 256>>>(src, dst, cur, eidx);

    // ---- Layer 1 ----
    k_gemm_tc2<<<GB, 256>>>(xs, ws + 0 * 16384, ws + 1 * 16384, gl, gr, N_NODES);
    k_node_h4<<<NB4, 256>>>((const float4*)gl, (const float4*)gr, att1,
                            off, deg, eidx, (uint4*)hs, 1);
    // ---- Layer 2 ----
    k_gemm_tc2<<<GB, 256>>>(hs, ws + 2 * 16384, ws + 3 * 16384, gl, gr, N_NODES);
    k_node_h4<<<NB4, 256>>>((const float4*)gl, (const float4*)gr, att2,
                            off, deg, eidx, (uint4*)hs, 2);
    // ---- Layer 3 ----
    k_gemm40_dual<<<g40, 256>>>(hs, Wl3, Wr3, gl, gr, N_NODES, 40);
    k_node_h1_lsm<<<NB1, 256>>>((const float4*)gl, (const float4*)gr, att3,
                                off, deg, eidx, out);
}

// round 8
// speedup vs baseline: 3.1204x; 1.0135x over previous
#include <cuda_runtime.h>
#include <cuda_bf16.h>
#include <math.h>
#include <float.h>
#include <stdint.h>

#define N_NODES 50000
#define N_EDGES 800000
#define SLOPE 0.2f

// ---------------- scratch (device globals; no allocation allowed) ----------
__device__ float    g_gl[N_NODES * 128];
__device__ float    g_gr[N_NODES * 128];
__device__ uint32_t g_xs[N_NODES * 128];   // packed (hi,lo) bf16 split of x
__device__ uint32_t g_hs[N_NODES * 128];   // packed split of hidden h
__device__ uint32_t g_ws[4 * 16384];       // packed splits of Wl1,Wr1,Wl2,Wr2
__device__ int      g_deg[N_NODES];
__device__ int      g_off[N_NODES];
__device__ int      g_cur[N_NODES];
__device__ int      g_bsum[64];
__device__ int      g_eidx[N_EDGES];

// ---- bf16 hi/lo split pack -------------------------------------------------
__device__ __forceinline__ uint32_t packsplit(float x) {
    __nv_bfloat16 h = __float2bfloat16(x);
    __nv_bfloat16 l = __float2bfloat16(x - __bfloat162float(h));
    return ((uint32_t)__bfloat16_as_ushort(h) << 16) | (uint32_t)__bfloat16_as_ushort(l);
}
__device__ __forceinline__ float unpacksplit(uint32_t v) {
    __nv_bfloat16 h = __ushort_as_bfloat16((unsigned short)(v >> 16));
    __nv_bfloat16 l = __ushort_as_bfloat16((unsigned short)(v & 0xffff));
    return __bfloat162float(h) + __bfloat162float(l);
}

__global__ void k_split(const float* __restrict__ in, uint32_t* __restrict__ outp, int n) {
    int i = (blockIdx.x * blockDim.x + threadIdx.x) * 4;
    if (i >= n) return;
    float4 v = *(const float4*)(in + i);
    uint4 o;
    o.x = packsplit(v.x); o.y = packsplit(v.y);
    o.z = packsplit(v.z); o.w = packsplit(v.w);
    *(uint4*)(outp + i) = o;
}

// fused split of all four 128x128 weights into g_ws
__global__ void k_split_w(const float* __restrict__ w0, const float* __restrict__ w1,
                          const float* __restrict__ w2, const float* __restrict__ w3,
                          uint32_t* __restrict__ outp) {
    int i = (blockIdx.x * blockDim.x + threadIdx.x) * 4;   // 0..65532
    int sel = i >> 14;                                      // which weight
    int o4 = i & 16383;
    const float* w = (sel == 0) ? w0 : (sel == 1) ? w1 : (sel == 2) ? w2 : w3;
    float4 v = *(const float4*)(w + o4);
    uint4 o;
    o.x = packsplit(v.x); o.y = packsplit(v.y);
    o.z = packsplit(v.z); o.w = packsplit(v.w);
    *(uint4*)(outp + i) = o;
}

// ================= CSR construction ==========================================
__global__ void k_hist(const int* __restrict__ dst, int* __restrict__ deg) {
    int e = blockIdx.x * blockDim.x + threadIdx.x;
    if (e < N_EDGES) atomicAdd(&deg[dst[e]], 1);
}

__global__ __launch_bounds__(1024) void k_scan_part(
    const int* __restrict__ deg, int* __restrict__ off, int* __restrict__ bsum)
{
    __shared__ int sh[1024];
    int t = threadIdx.x;
    int i = blockIdx.x * 1024 + t;
    int v = (i < N_NODES) ? deg[i] : 0;
    sh[t] = v;
    __syncthreads();
    #pragma unroll
    for (int o = 1; o < 1024; o <<= 1) {
        int u = (t >= o) ? sh[t - o] : 0;
        __syncthreads();
        sh[t] += u;
        __syncthreads();
    }
    if (i < N_NODES) off[i] = sh[t] - v;
    if (t == 1023) bsum[blockIdx.x] = sh[t];
}

// adds block-prefix base; computes it in-kernel from raw partials (no scan_top)
__global__ void k_scan_add(int* __restrict__ off, int* __restrict__ cur,
                           const int* __restrict__ bsum)
{
    __shared__ int base_sh;
    int i = blockIdx.x * blockDim.x + threadIdx.x;
    int b = (blockIdx.x * blockDim.x) >> 10;     // constant within block
    if (threadIdx.x == 0) {
        int s = 0;
        for (int j = 0; j < b; j++) s += bsum[j];
        base_sh = s;
    }
    __syncthreads();
    if (i >= N_NODES) return;
    int o = off[i] + base_sh;
    off[i] = o;
    cur[i] = o;
}

__global__ void k_scatter(const int* __restrict__ src, const int* __restrict__ dst,
                          int* __restrict__ cur, int* __restrict__ eidx)
{
    int e = blockIdx.x * blockDim.x + threadIdx.x;
    if (e >= N_EDGES) return;
    int p = atomicAdd(&cur[dst[e]], 1);
    eidx[p] = src[e];
}

// ================= tensor-core helpers =======================================
__device__ __forceinline__ uint32_t smem_u32(const void* p) {
    return (uint32_t)__cvta_generic_to_shared(p);
}
__device__ __forceinline__ void ldsm_x4(uint32_t& r0, uint32_t& r1, uint32_t& r2, uint32_t& r3, uint32_t addr) {
    asm volatile("ldmatrix.sync.aligned.m8n8.x4.shared.b16 {%0,%1,%2,%3},[%4];"
                 : "=r"(r0), "=r"(r1), "=r"(r2), "=r"(r3) : "r"(addr));
}
__device__ __forceinline__ void ldsm_x2_t(uint32_t& r0, uint32_t& r1, uint32_t addr) {
    asm volatile("ldmatrix.sync.aligned.m8n8.x2.trans.shared.b16 {%0,%1},[%2];"
                 : "=r"(r0), "=r"(r1) : "r"(addr));
}
__device__ __forceinline__ void mma_bf16c(float* d, const uint32_t* a, const uint32_t* b) {
    asm volatile("mma.sync.aligned.m16n8k16.row.col.f32.bf16.bf16.f32 "
                 "{%0,%1,%2,%3},{%4,%5,%6,%7},{%8,%9},{%0,%1,%2,%3};"
                 : "+f"(d[0]), "+f"(d[1]), "+f"(d[2]), "+f"(d[3])
                 : "r"(a[0]), "r"(a[1]), "r"(a[2]), "r"(a[3]), "r"(b[0]), "r"(b[1]));
}

// ================= TC dual GEMM on pre-split inputs ==========================
__global__ __launch_bounds__(256, 2) void k_gemm_tc2(
    const uint32_t* __restrict__ Ap,
    const uint32_t* __restrict__ W1p, const uint32_t* __restrict__ W2p,
    float* __restrict__ C1, float* __restrict__ C2, int M)
{
    __shared__ __nv_bfloat16 Ah[64][40];     // 32 k + pad 8
    __shared__ __nv_bfloat16 Al[64][40];
    __shared__ __nv_bfloat16 Wh[32][264];    // 256 n + pad 8
    __shared__ __nv_bfloat16 Wl[32][264];

    const int tid = threadIdx.x, lane = tid & 31, wid = tid >> 5;
    const int wm = wid & 1;
    const int wn = wid >> 1;
    const int r0 = blockIdx.x * 64;

    float d[2][8][4];
    #pragma unroll
    for (int i = 0; i < 2; i++)
        #pragma unroll
        for (int j = 0; j < 8; j++)
            #pragma unroll
            for (int k = 0; k < 4; k++) d[i][j][k] = 0.f;

    for (int kt = 0; kt < 4; kt++) {
        #pragma unroll
        for (int i = 0; i < 2; i++) {
            int idx = tid + i * 256;
            int row = idx >> 3, q = idx & 7;
            uint4 p = make_uint4(0u, 0u, 0u, 0u);
            if (r0 + row < M)
                p = *(const uint4*)(Ap + (size_t)(r0 + row) * 128 + kt * 32 + q * 4);
            uint2 hi, lo;
            hi.x = __byte_perm(p.x, p.y, 0x7632); hi.y = __byte_perm(p.z, p.w, 0x7632);
            lo.x = __byte_perm(p.x, p.y, 0x5410); lo.y = __byte_perm(p.z, p.w, 0x5410);
            *(uint2*)&Ah[row][q * 4] = hi;
            *(uint2*)&Al[row][q * 4] = lo;
        }
        #pragma unroll
        for (int i = 0; i < 8; i++) {
            int idx = tid + i * 256;
            int k = idx >> 6, q = idx & 63;
            uint4 p = (q < 32)
                ? *(const uint4*)(W1p + (size_t)(kt * 32 + k) * 128 + q * 4)
                : *(const uint4*)(W2p + (size_t)(kt * 32 + k) * 128 + (q - 32) * 4);
            uint2 hi, lo;
            hi.x = __byte_perm(p.x, p.y, 0x7632); hi.y = __byte_perm(p.z, p.w, 0x7632);
            lo.x = __byte_perm(p.x, p.y, 0x5410); lo.y = __byte_perm(p.z, p.w, 0x5410);
            *(uint2*)&Wh[k][q * 4] = hi;
            *(uint2*)&Wl[k][q * 4] = lo;
        }
        __syncthreads();

        #pragma unroll
        for (int ph = 0; ph < 3; ph++) {
            const __nv_bfloat16 (*Asm)[40]  = (ph == 1) ? Al : Ah;
            const __nv_bfloat16 (*Wsm)[264] = (ph == 2) ? Wl : Wh;
            #pragma unroll
            for (int k16 = 0; k16 < 2; k16++) {
                uint32_t af[2][4], bfr[8][2];
                #pragma unroll
                for (int mf = 0; mf < 2; mf++) {
                    uint32_t addr = smem_u32(
                        &Asm[wm * 32 + mf * 16 + (lane & 15)][k16 * 16 + (lane >> 4) * 8]);
                    ldsm_x4(af[mf][0], af[mf][1], af[mf][2], af[mf][3], addr);
                }
                #pragma unroll
                for (int nf = 0; nf < 8; nf++) {
                    uint32_t addr = smem_u32(
                        &Wsm[k16 * 16 + (lane & 15)][wn * 64 + nf * 8]);
                    ldsm_x2_t(bfr[nf][0], bfr[nf][1], addr);
                }
                #pragma unroll
                for (int mf = 0; mf < 2; mf++)
                    #pragma unroll
                    for (int nf = 0; nf < 8; nf++)
                        mma_bf16c(d[mf][nf], af[mf], bfr[nf]);
            }
        }
        __syncthreads();
    }

    const int g = lane >> 2, t = lane & 3;
    float* Cp = (wn < 2) ? C1 : C2;
    int cbase = (wn < 2) ? wn * 64 : (wn - 2) * 64;
    #pragma unroll
    for (int mf = 0; mf < 2; mf++) {
        #pragma unroll
        for (int nf = 0; nf < 8; nf++) {
            int row0 = r0 + wm * 32 + mf * 16 + g;
            int col = cbase + nf * 8 + t * 2;
            if (row0 < M)
                *(float2*)(Cp + (size_t)row0 * 128 + col) = make_float2(d[mf][nf][0], d[mf][nf][1]);
            if (row0 + 8 < M)
                *(float2*)(Cp + (size_t)(row0 + 8) * 128 + col) = make_float2(d[mf][nf][2], d[mf][nf][3]);
        }
    }
}

// ================= dual SGEMM (Ncols=40, FFMA, packed A) =====================
__global__ __launch_bounds__(256) void k_gemm40_dual(
    const uint32_t* __restrict__ Ap,
    const float* __restrict__ Wa, const float* __restrict__ Wb,
    float* __restrict__ Ca, float* __restrict__ Cb, int M, int Ncols)
{
    const float* W = blockIdx.x ? Wb : Wa;
    float* C = blockIdx.x ? Cb : Ca;

    __shared__ float As[64][68];
    __shared__ float Ws[64][64];

    const int tid = threadIdx.x;
    const int tx = tid & 15;
    const int ty = tid >> 4;
    const int r0 = blockIdx.y * 64;

    float acc[4][4] = {};

    for (int kk = 0; kk < 128; kk += 64) {
        __syncthreads();
        #pragma unroll
        for (int i = 0; i < 4; i++) {
            int f = tid + i * 256;
            int row = f >> 4;
            int k4 = f & 15;
            float4 a = make_float4(0.f, 0.f, 0.f, 0.f);
            int r = r0 + row;
            if (r < M) {
                uint4 p = *(const uint4*)(Ap + (size_t)r * 128 + kk + k4 * 4);
                a.x = unpacksplit(p.x); a.y = unpacksplit(p.y);
                a.z = unpacksplit(p.z); a.w = unpacksplit(p.w);
            }
            *(float4*)(&As[row][k4 * 4]) = a;
        }
        #pragma unroll
        for (int i = 0; i < 16; i++) {
            int f = tid + i * 256;
            int k = f >> 6, c = f & 63;
            Ws[k][c] = (c < Ncols) ? W[(size_t)(kk + k) * Ncols + c] : 0.f;
        }
        __syncthreads();

        #pragma unroll 16
        for (int k = 0; k < 64; k++) {
            float4 b = *(const float4*)(&Ws[k][tx * 4]);
            float a0 = As[ty * 4 + 0][k];
            float a1 = As[ty * 4 + 1][k];
            float a2 = As[ty * 4 + 2][k];
            float a3 = As[ty * 4 + 3][k];
            acc[0][0] += a0 * b.x; acc[0][1] += a0 * b.y; acc[0][2] += a0 * b.z; acc[0][3] += a0 * b.w;
            acc[1][0] += a1 * b.x; acc[1][1] += a1 * b.y; acc[1][2] += a1 * b.z; acc[1][3] += a1 * b.w;
            acc[2][0] += a2 * b.x; acc[2][1] += a2 * b.y; acc[2][2] += a2 * b.z; acc[2][3] += a2 * b.w;
            acc[3][0] += a3 * b.x; acc[3][1] += a3 * b.y; acc[3][2] += a3 * b.z; acc[3][3] += a3 * b.w;
        }
    }

    #pragma unroll
    for (int i = 0; i < 4; i++) {
        int r = r0 + ty * 4 + i;
        if (r >= M) continue;
        #pragma unroll
        for (int j = 0; j < 4; j++) {
            int c = tx * 4 + j;
            if (c < Ncols) C[(size_t)r * Ncols + c] = acc[i][j];
        }
    }
}

// ================= node-centric aggregation (H=4, F=32) =====================
__global__ __launch_bounds__(256) void k_node_h4(
    const float4* __restrict__ gl4, const float4* __restrict__ gr4,
    const float* __restrict__ att,
    const int* __restrict__ off, const int* __restrict__ deg,
    const int* __restrict__ eidx, uint4* __restrict__ houtp, int mode)
{
    int n = blockIdx.x * 8 + (threadIdx.x >> 5);
    if (n >= N_NODES) return;
    int l = threadIdx.x & 31;

    float4 b = gr4[(size_t)n * 32 + l];
    float4 t = __ldg(&((const float4*)att)[l]);

    float ax = 0.f, ay = 0.f, az = 0.f, aw = 0.f, dw = 0.f;

    int start = off[n], cnt = deg[n];
    for (int base = 0; base < cnt; base += 32) {
        int rem = cnt - base;
        int m = rem < 32 ? rem : 32;
        int eld = (l < m) ? __ldg(&eidx[start + base + l]) : 0;
        int j = 0;
        for (; j + 1 < m; j += 2) {
            int s0 = __shfl_sync(0xffffffffu, eld, j);
            int s1 = __shfl_sync(0xffffffffu, eld, j + 1);
            float4 a0 = __ldg(&gl4[(size_t)s0 * 32 + l]);
            float4 a1 = __ldg(&gl4[(size_t)s1 * 32 + l]);

            float v0x = a0.x + b.x; v0x = v0x > 0.f ? v0x : SLOPE * v0x;
            float v0y = a0.y + b.y; v0y = v0y > 0.f ? v0y : SLOPE * v0y;
            float v0z = a0.z + b.z; v0z = v0z > 0.f ? v0z : SLOPE * v0z;
            float v0w = a0.w + b.w; v0w = v0w > 0.f ? v0w : SLOPE * v0w;
            float p0 = v0x * t.x + v0y * t.y + v0z * t.z + v0w * t.w;

            float v1x = a1.x + b.x; v1x = v1x > 0.f ? v1x : SLOPE * v1x;
            float v1y = a1.y + b.y; v1y = v1y > 0.f ? v1y : SLOPE * v1y;
            float v1z = a1.z + b.z; v1z = v1z > 0.f ? v1z : SLOPE * v1z;
            float v1w = a1.w + b.w; v1w = v1w > 0.f ? v1w : SLOPE * v1w;
            float p1 = v1x * t.x + v1y * t.y + v1z * t.z + v1w * t.w;

            p0 += __shfl_xor_sync(0xffffffffu, p0, 4);
            p1 += __shfl_xor_sync(0xffffffffu, p1, 4);
            p0 += __shfl_xor_sync(0xffffffffu, p0, 2);
            p1 += __shfl_xor_sync(0xffffffffu, p1, 2);
            p0 += __shfl_xor_sync(0xffffffffu, p0, 1);
            p1 += __shfl_xor_sync(0xffffffffu, p1, 1);
            float w0 = __expf(p0), w1 = __expf(p1);

            ax += w0 * a0.x + w1 * a1.x;
            ay += w0 * a0.y + w1 * a1.y;
            az += w0 * a0.z + w1 * a1.z;
            aw += w0 * a0.w + w1 * a1.w;
            dw += w0 + w1;
        }
        if (j < m) {
            int s = __shfl_sync(0xffffffffu, eld, j);
            float4 a = __ldg(&gl4[(size_t)s * 32 + l]);
            float vx = a.x + b.x; vx = vx > 0.f ? vx : SLOPE * vx;
            float vy = a.y + b.y; vy = vy > 0.f ? vy : SLOPE * vy;
            float vz = a.z + b.z; vz = vz > 0.f ? vz : SLOPE * vz;
            float vw = a.w + b.w; vw = vw > 0.f ? vw : SLOPE * vw;
            float p = vx * t.x + vy * t.y + vz * t.z + vw * t.w;
            p += __shfl_xor_sync(0xffffffffu, p, 4);
            p += __shfl_xor_sync(0xffffffffu, p, 2);
            p += __shfl_xor_sync(0xffffffffu, p, 1);
            float w = __expf(p);
            ax += w * a.x; ay += w * a.y; az += w * a.z; aw += w * a.w;
            dw += w;
        }
    }

    float inv = 1.0f / (dw + 1e-16f);
    float4 v = make_float4(ax * inv, ay * inv, az * inv, aw * inv);
    if (mode == 1) {
        v.x = v.x > 0.f ? v.x : expm1f(v.x);
        v.y = v.y > 0.f ? v.y : expm1f(v.y);
        v.z = v.z > 0.f ? v.z : expm1f(v.z);
        v.w = v.w > 0.f ? v.w : expm1f(v.w);
    } else {
        v.x = fmaxf(v.x, 0.f); v.y = fmaxf(v.y, 0.f);
        v.z = fmaxf(v.z, 0.f); v.w = fmaxf(v.w, 0.f);
    }
    uint4 o;
    o.x = packsplit(v.x); o.y = packsplit(v.y);
    o.z = packsplit(v.z); o.w = packsplit(v.w);
    houtp[(size_t)n * 32 + l] = o;
}

// ================= node-centric layer 3 + log_softmax (H=1, F=40) ===========
__global__ __launch_bounds__(256) void k_node_h1_lsm(
    const float4* __restrict__ gl4, const float4* __restrict__ gr4,
    const float* __restrict__ att,
    const int* __restrict__ off, const int* __restrict__ deg,
    const int* __restrict__ eidx, float* __restrict__ out)
{
    int l = threadIdx.x & 31;
    int sub = l >> 4;
    int ll = l & 15;
    unsigned mask = 0xFFFFu << (sub * 16);
    int n = blockIdx.x * 16 + (threadIdx.x >> 5) * 2 + sub;
    if (n >= N_NODES) return;

    float4 b = make_float4(0.f, 0.f, 0.f, 0.f), t = b;
    if (ll < 10) {
        b = gr4[(size_t)n * 10 + ll];
        t = __ldg(&((const float4*)att)[ll]);
    }

    float ax = 0.f, ay = 0.f, az = 0.f, aw = 0.f, dw = 0.f;

    int start = off[n], cnt = deg[n];
    for (int base = 0; base < cnt; base += 16) {
        int rem = cnt - base;
        int m = rem < 16 ? rem : 16;
        int eld = (ll < m) ? __ldg(&eidx[start + base + ll]) : 0;
        for (int j = 0; j < m; j++) {
            int s = __shfl_sync(mask, eld, j, 16);
            float4 a = make_float4(0.f, 0.f, 0.f, 0.f);
            float p = 0.f;
            if (ll < 10) {
                a = __ldg(&gl4[(size_t)s * 10 + ll]);
                float vx = a.x + b.x; vx = vx > 0.f ? vx : SLOPE * vx;
                float vy = a.y + b.y; vy = vy > 0.f ? vy : SLOPE * vy;
                float vz = a.z + b.z; vz = vz > 0.f ? vz : SLOPE * vz;
                float vw = a.w + b.w; vw = vw > 0.f ? vw : SLOPE * vw;
                p = vx * t.x + vy * t.y + vz * t.z + vw * t.w;
            }
            p += __shfl_xor_sync(mask, p, 8, 16);
            p += __shfl_xor_sync(mask, p, 4, 16);
            p += __shfl_xor_sync(mask, p, 2, 16);
            p += __shfl_xor_sync(mask, p, 1, 16);
            float w = __expf(p);
            ax += w * a.x; ay += w * a.y; az += w * a.z; aw += w * a.w;
            dw += w;
        }
    }

    float inv = 1.0f / (dw + 1e-16f);
    float4 v = make_float4(ax * inv, ay * inv, az * inv, aw * inv);

    float mx = (ll < 10) ? fmaxf(fmaxf(v.x, v.y), fmaxf(v.z, v.w)) : -FLT_MAX;
    #pragma unroll
    for (int o = 8; o > 0; o >>= 1) mx = fmaxf(mx, __shfl_xor_sync(mask, mx, o, 16));
    float ss = (ll < 10)
        ? (expf(v.x - mx) + expf(v.y - mx) + expf(v.z - mx) + expf(v.w - mx)) : 0.f;
    #pragma unroll
    for (int o = 8; o > 0; o >>= 1) ss += __shfl_xor_sync(mask, ss, o, 16);
    float lse = mx + logf(ss);
    if (ll < 10) {
        float4 r = make_float4(v.x - lse, v.y - lse, v.z - lse, v.w - lse);
        *(float4*)(out + (size_t)n * 40 + 4 * ll) = r;
    }
}

// ---------------- host -------------------------------------------------------
extern "C" void kernel_launch(void* const* d_in, const int* in_sizes, int n_in,
                              void* d_out, int out_size)
{
    const float* x    = (const float*)d_in[0];
    const float* Wl1  = (const float*)d_in[1];
    const float* Wr1  = (const float*)d_in[2];
    const float* att1 = (const float*)d_in[3];
    const float* Wl2  = (const float*)d_in[4];
    const float* Wr2  = (const float*)d_in[5];
    const float* att2 = (const float*)d_in[6];
    const float* Wl3  = (const float*)d_in[7];
    const float* Wr3  = (const float*)d_in[8];
    const float* att3 = (const float*)d_in[9];
    const int*   ei   = (const int*)d_in[10];
    const int* src = ei;
    const int* dst = ei + N_EDGES;
    float* out = (float*)d_out;

    float *gl, *gr;
    uint32_t *xs, *hs, *ws;
    int *deg, *off, *cur, *bsum, *eidx;
    cudaGetSymbolAddress((void**)&gl,   g_gl);
    cudaGetSymbolAddress((void**)&gr,   g_gr);
    cudaGetSymbolAddress((void**)&xs,   g_xs);
    cudaGetSymbolAddress((void**)&hs,   g_hs);
    cudaGetSymbolAddress((void**)&ws,   g_ws);
    cudaGetSymbolAddress((void**)&deg,  g_deg);
    cudaGetSymbolAddress((void**)&off,  g_off);
    cudaGetSymbolAddress((void**)&cur,  g_cur);
    cudaGetSymbolAddress((void**)&bsum, g_bsum);
    cudaGetSymbolAddress((void**)&eidx, g_eidx);

    const int GB = (N_NODES + 63) / 64;         // 782
    const dim3 g40(2, (N_NODES + 63) / 64);
    const int NB4 = (N_NODES + 7) / 8;
    const int NB1 = (N_NODES + 15) / 16;
    const int NSCAN = (N_NODES + 1023) / 1024;

    // launch order chosen so launch #5 (ncu -s 5 -c 1) is k_gemm_tc2.
    // 0: split all weights   1: split x
    k_split_w<<<64, 256>>>(Wl1, Wr1, Wl2, Wr2, ws);
    k_split<<<(N_NODES * 128 / 4 + 255) / 256, 256>>>(x, xs, N_NODES * 128);
    // 2-4: CSR front half (independent of GEMM)
    cudaMemsetAsync(deg, 0, N_NODES * sizeof(int));
    k_hist<<<(N_EDGES + 255) / 256, 256>>>(dst, deg);
    k_scan_part<<<NSCAN, 1024>>>(deg, off, bsum);
    // 5: layer-1 GEMM (depends only on xs/ws)
    k_gemm_tc2<<<GB, 256>>>(xs, ws + 0 * 16384, ws + 1 * 16384, gl, gr, N_NODES);
    // 6-7: CSR back half
    k_scan_add<<<(N_NODES + 255) / 256, 256>>>(off, cur, bsum);
    k_scatter<<<(N_EDGES + 255) / 256, 256>>>(src, dst, cur, eidx);

    // ---- Layer 1 aggregate ----
    k_node_h4<<<NB4, 256>>>((const float4*)gl, (const float4*)gr, att1,
                            off, deg, eidx, (uint4*)hs, 1);
    // ---- Layer 2 ----
    k_gemm_tc2<<<GB, 256>>>(hs, ws + 2 * 16384, ws + 3 * 16384, gl, gr, N_NODES);
    k_node_h4<<<NB4, 256>>>((const float4*)gl, (const float4*)gr, att2,
                            off, deg, eidx, (uint4*)hs, 2);
    // ---- Layer 3 ----
    k_gemm40_dual<<<g40, 256>>>(hs, Wl3, Wr3, gl, gr, N_NODES, 40);
    k_node_h1_lsm<<<NB1, 256>>>((const float4*)gl, (const float4*)gr, att3,
                                off, deg, eidx, out);
}

// round 9
// speedup vs baseline: 3.1857x; 1.0209x over previous
#include <cuda_runtime.h>
#include <cuda_bf16.h>
#include <cuda_fp16.h>
#include <math.h>
#include <float.h>
#include <stdint.h>

#define N_NODES 50000
#define N_EDGES 800000
#define SLOPE 0.2f

// ---------------- scratch (device globals; no allocation allowed) ----------
__device__ float    g_gl[N_NODES * 128];   // fp32 view (layer 3) / fp16 view (layers 1-2)
__device__ float    g_gr[N_NODES * 128];
__device__ uint32_t g_xs[N_NODES * 128];   // packed (hi,lo) bf16 split of x
__device__ uint32_t g_hs[N_NODES * 128];   // packed split of hidden h
__device__ uint32_t g_ws[4 * 16384];       // packed splits of Wl1,Wr1,Wl2,Wr2
__device__ int      g_deg[N_NODES];
__device__ int      g_off[N_NODES];
__device__ int      g_cur[N_NODES];
__device__ int      g_bsum[64];
__device__ int      g_eidx[N_EDGES];

// ---- bf16 hi/lo split pack -------------------------------------------------
__device__ __forceinline__ uint32_t packsplit(float x) {
    __nv_bfloat16 h = __float2bfloat16(x);
    __nv_bfloat16 l = __float2bfloat16(x - __bfloat162float(h));
    return ((uint32_t)__bfloat16_as_ushort(h) << 16) | (uint32_t)__bfloat16_as_ushort(l);
}
__device__ __forceinline__ float unpacksplit(uint32_t v) {
    __nv_bfloat16 h = __ushort_as_bfloat16((unsigned short)(v >> 16));
    __nv_bfloat16 l = __ushort_as_bfloat16((unsigned short)(v & 0xffff));
    return __bfloat162float(h) + __bfloat162float(l);
}
// 4 halfs (uint2) -> float4
__device__ __forceinline__ float4 h4tof4(uint2 r) {
    __half2 h0 = *reinterpret_cast<__half2*>(&r.x);
    __half2 h1 = *reinterpret_cast<__half2*>(&r.y);
    float2 f0 = __half22float2(h0), f1 = __half22float2(h1);
    return make_float4(f0.x, f0.y, f1.x, f1.y);
}

__global__ void k_split(const float* __restrict__ in, uint32_t* __restrict__ outp, int n) {
    int i = (blockIdx.x * blockDim.x + threadIdx.x) * 4;
    if (i >= n) return;
    float4 v = *(const float4*)(in + i);
    uint4 o;
    o.x = packsplit(v.x); o.y = packsplit(v.y);
    o.z = packsplit(v.z); o.w = packsplit(v.w);
    *(uint4*)(outp + i) = o;
}

__global__ void k_split_w(const float* __restrict__ w0, const float* __restrict__ w1,
                          const float* __restrict__ w2, const float* __restrict__ w3,
                          uint32_t* __restrict__ outp) {
    int i = (blockIdx.x * blockDim.x + threadIdx.x) * 4;
    int sel = i >> 14;
    int o4 = i & 16383;
    const float* w = (sel == 0) ? w0 : (sel == 1) ? w1 : (sel == 2) ? w2 : w3;
    float4 v = *(const float4*)(w + o4);
    uint4 o;
    o.x = packsplit(v.x); o.y = packsplit(v.y);
    o.z = packsplit(v.z); o.w = packsplit(v.w);
    *(uint4*)(outp + i) = o;
}

// ================= CSR construction ==========================================
__global__ void k_hist(const int* __restrict__ dst, int* __restrict__ deg) {
    int e = blockIdx.x * blockDim.x + threadIdx.x;
    if (e < N_EDGES) atomicAdd(&deg[dst[e]], 1);
}

__global__ __launch_bounds__(1024) void k_scan_part(
    const int* __restrict__ deg, int* __restrict__ off, int* __restrict__ bsum)
{
    __shared__ int sh[1024];
    int t = threadIdx.x;
    int i = blockIdx.x * 1024 + t;
    int v = (i < N_NODES) ? deg[i] : 0;
    sh[t] = v;
    __syncthreads();
    #pragma unroll
    for (int o = 1; o < 1024; o <<= 1) {
        int u = (t >= o) ? sh[t - o] : 0;
        __syncthreads();
        sh[t] += u;
        __syncthreads();
    }
    if (i < N_NODES) off[i] = sh[t] - v;
    if (t == 1023) bsum[blockIdx.x] = sh[t];
}

__global__ void k_scan_add(int* __restrict__ off, int* __restrict__ cur,
                           const int* __restrict__ bsum)
{
    __shared__ int base_sh;
    int i = blockIdx.x * blockDim.x + threadIdx.x;
    int b = (blockIdx.x * blockDim.x) >> 10;
    if (threadIdx.x == 0) {
        int s = 0;
        for (int j = 0; j < b; j++) s += bsum[j];
        base_sh = s;
    }
    __syncthreads();
    if (i >= N_NODES) return;
    int o = off[i] + base_sh;
    off[i] = o;
    cur[i] = o;
}

__global__ void k_scatter(const int* __restrict__ src, const int* __restrict__ dst,
                          int* __restrict__ cur, int* __restrict__ eidx)
{
    int e = blockIdx.x * blockDim.x + threadIdx.x;
    if (e >= N_EDGES) return;
    int p = atomicAdd(&cur[dst[e]], 1);
    eidx[p] = src[e];
}

// ================= tensor-core helpers =======================================
__device__ __forceinline__ uint32_t smem_u32(const void* p) {
    return (uint32_t)__cvta_generic_to_shared(p);
}
__device__ __forceinline__ void ldsm_x4(uint32_t& r0, uint32_t& r1, uint32_t& r2, uint32_t& r3, uint32_t addr) {
    asm volatile("ldmatrix.sync.aligned.m8n8.x4.shared.b16 {%0,%1,%2,%3},[%4];"
                 : "=r"(r0), "=r"(r1), "=r"(r2), "=r"(r3) : "r"(addr));
}
__device__ __forceinline__ void ldsm_x2_t(uint32_t& r0, uint32_t& r1, uint32_t addr) {
    asm volatile("ldmatrix.sync.aligned.m8n8.x2.trans.shared.b16 {%0,%1},[%2];"
                 : "=r"(r0), "=r"(r1) : "r"(addr));
}
__device__ __forceinline__ void mma_bf16c(float* d, const uint32_t* a, const uint32_t* b) {
    asm volatile("mma.sync.aligned.m16n8k16.row.col.f32.bf16.bf16.f32 "
                 "{%0,%1,%2,%3},{%4,%5,%6,%7},{%8,%9},{%0,%1,%2,%3};"
                 : "+f"(d[0]), "+f"(d[1]), "+f"(d[2]), "+f"(d[3])
                 : "r"(a[0]), "r"(a[1]), "r"(a[2]), "r"(a[3]), "r"(b[0]), "r"(b[1]));
}

// ================= TC dual GEMM, fp16 output =================================
// C1 = A@W1, C2 = A@W2, outputs stored as __half (for the edge phase).
__global__ __launch_bounds__(256, 2) void k_gemm_tc2(
    const uint32_t* __restrict__ Ap,
    const uint32_t* __restrict__ W1p, const uint32_t* __restrict__ W2p,
    __half* __restrict__ C1, __half* __restrict__ C2, int M)
{
    __shared__ __nv_bfloat16 Ah[64][40];
    __shared__ __nv_bfloat16 Al[64][40];
    __shared__ __nv_bfloat16 Wh[32][264];
    __shared__ __nv_bfloat16 Wl[32][264];

    const int tid = threadIdx.x, lane = tid & 31, wid = tid >> 5;
    const int wm = wid & 1;
    const int wn = wid >> 1;
    const int r0 = blockIdx.x * 64;

    float d[2][8][4];
    #pragma unroll
    for (int i = 0; i < 2; i++)
        #pragma unroll
        for (int j = 0; j < 8; j++)
            #pragma unroll
            for (int k = 0; k < 4; k++) d[i][j][k] = 0.f;

    for (int kt = 0; kt < 4; kt++) {
        #pragma unroll
        for (int i = 0; i < 2; i++) {
            int idx = tid + i * 256;
            int row = idx >> 3, q = idx & 7;
            uint4 p = make_uint4(0u, 0u, 0u, 0u);
            if (r0 + row < M)
                p = *(const uint4*)(Ap + (size_t)(r0 + row) * 128 + kt * 32 + q * 4);
            uint2 hi, lo;
            hi.x = __byte_perm(p.x, p.y, 0x7632); hi.y = __byte_perm(p.z, p.w, 0x7632);
            lo.x = __byte_perm(p.x, p.y, 0x5410); lo.y = __byte_perm(p.z, p.w, 0x5410);
            *(uint2*)&Ah[row][q * 4] = hi;
            *(uint2*)&Al[row][q * 4] = lo;
        }
        #pragma unroll
        for (int i = 0; i < 8; i++) {
            int idx = tid + i * 256;
            int k = idx >> 6, q = idx & 63;
            uint4 p = (q < 32)
                ? *(const uint4*)(W1p + (size_t)(kt * 32 + k) * 128 + q * 4)
                : *(const uint4*)(W2p + (size_t)(kt * 32 + k) * 128 + (q - 32) * 4);
            uint2 hi, lo;
            hi.x = __byte_perm(p.x, p.y, 0x7632); hi.y = __byte_perm(p.z, p.w, 0x7632);
            lo.x = __byte_perm(p.x, p.y, 0x5410); lo.y = __byte_perm(p.z, p.w, 0x5410);
            *(uint2*)&Wh[k][q * 4] = hi;
            *(uint2*)&Wl[k][q * 4] = lo;
        }
        __syncthreads();

        #pragma unroll
        for (int ph = 0; ph < 3; ph++) {
            const __nv_bfloat16 (*Asm)[40]  = (ph == 1) ? Al : Ah;
            const __nv_bfloat16 (*Wsm)[264] = (ph == 2) ? Wl : Wh;
            #pragma unroll
            for (int k16 = 0; k16 < 2; k16++) {
                uint32_t af[2][4], bfr[8][2];
                #pragma unroll
                for (int mf = 0; mf < 2; mf++) {
                    uint32_t addr = smem_u32(
                        &Asm[wm * 32 + mf * 16 + (lane & 15)][k16 * 16 + (lane >> 4) * 8]);
                    ldsm_x4(af[mf][0], af[mf][1], af[mf][2], af[mf][3], addr);
                }
                #pragma unroll
                for (int nf = 0; nf < 8; nf++) {
                    uint32_t addr = smem_u32(
                        &Wsm[k16 * 16 + (lane & 15)][wn * 64 + nf * 8]);
                    ldsm_x2_t(bfr[nf][0], bfr[nf][1], addr);
                }
                #pragma unroll
                for (int mf = 0; mf < 2; mf++)
                    #pragma unroll
                    for (int nf = 0; nf < 8; nf++)
                        mma_bf16c(d[mf][nf], af[mf], bfr[nf]);
            }
        }
        __syncthreads();
    }

    const int g = lane >> 2, t = lane & 3;
    __half* Cp = (wn < 2) ? C1 : C2;
    int cbase = (wn < 2) ? wn * 64 : (wn - 2) * 64;
    #pragma unroll
    for (int mf = 0; mf < 2; mf++) {
        #pragma unroll
        for (int nf = 0; nf < 8; nf++) {
            int row0 = r0 + wm * 32 + mf * 16 + g;
            int col = cbase + nf * 8 + t * 2;
            if (row0 < M)
                *(__half2*)(Cp + (size_t)row0 * 128 + col) =
                    __floats2half2_rn(d[mf][nf][0], d[mf][nf][1]);
            if (row0 + 8 < M)
                *(__half2*)(Cp + (size_t)(row0 + 8) * 128 + col) =
                    __floats2half2_rn(d[mf][nf][2], d[mf][nf][3]);
        }
    }
}

// ================= dual SGEMM (Ncols=40, FFMA, packed A, fp32 out) ==========
__global__ __launch_bounds__(256) void k_gemm40_dual(
    const uint32_t* __restrict__ Ap,
    const float* __restrict__ Wa, const float* __restrict__ Wb,
    float* __restrict__ Ca, float* __restrict__ Cb, int M, int Ncols)
{
    const float* W = blockIdx.x ? Wb : Wa;
    float* C = blockIdx.x ? Cb : Ca;

    __shared__ float As[64][68];
    __shared__ float Ws[64][64];

    const int tid = threadIdx.x;
    const int tx = tid & 15;
    const int ty = tid >> 4;
    const int r0 = blockIdx.y * 64;

    float acc[4][4] = {};

    for (int kk = 0; kk < 128; kk += 64) {
        __syncthreads();
        #pragma unroll
        for (int i = 0; i < 4; i++) {
            int f = tid + i * 256;
            int row = f >> 4;
            int k4 = f & 15;
            float4 a = make_float4(0.f, 0.f, 0.f, 0.f);
            int r = r0 + row;
            if (r < M) {
                uint4 p = *(const uint4*)(Ap + (size_t)r * 128 + kk + k4 * 4);
                a.x = unpacksplit(p.x); a.y = unpacksplit(p.y);
                a.z = unpacksplit(p.z); a.w = unpacksplit(p.w);
            }
            *(float4*)(&As[row][k4 * 4]) = a;
        }
        #pragma unroll
        for (int i = 0; i < 16; i++) {
            int f = tid + i * 256;
            int k = f >> 6, c = f & 63;
            Ws[k][c] = (c < Ncols) ? W[(size_t)(kk + k) * Ncols + c] : 0.f;
        }
        __syncthreads();

        #pragma unroll 16
        for (int k = 0; k < 64; k++) {
            float4 b = *(const float4*)(&Ws[k][tx * 4]);
            float a0 = As[ty * 4 + 0][k];
            float a1 = As[ty * 4 + 1][k];
            float a2 = As[ty * 4 + 2][k];
            float a3 = As[ty * 4 + 3][k];
            acc[0][0] += a0 * b.x; acc[0][1] += a0 * b.y; acc[0][2] += a0 * b.z; acc[0][3] += a0 * b.w;
            acc[1][0] += a1 * b.x; acc[1][1] += a1 * b.y; acc[1][2] += a1 * b.z; acc[1][3] += a1 * b.w;
            acc[2][0] += a2 * b.x; acc[2][1] += a2 * b.y; acc[2][2] += a2 * b.z; acc[2][3] += a2 * b.w;
            acc[3][0] += a3 * b.x; acc[3][1] += a3 * b.y; acc[3][2] += a3 * b.z; acc[3][3] += a3 * b.w;
        }
    }

    #pragma unroll
    for (int i = 0; i < 4; i++) {
        int r = r0 + ty * 4 + i;
        if (r >= M) continue;
        #pragma unroll
        for (int j = 0; j < 4; j++) {
            int c = tx * 4 + j;
            if (c < Ncols) C[(size_t)r * Ncols + c] = acc[i][j];
        }
    }
}

// ================= node aggregation (H=4, F=32), fp16 inputs ================
// warp per dst node; lane l owns feats 4l..4l+3. Gathers 256B/edge (half).
__global__ __launch_bounds__(256) void k_node_h4(
    const uint2* __restrict__ glh, const uint2* __restrict__ grh,
    const float* __restrict__ att,
    const int* __restrict__ off, const int* __restrict__ deg,
    const int* __restrict__ eidx, uint4* __restrict__ houtp, int mode)
{
    int n = blockIdx.x * 8 + (threadIdx.x >> 5);
    if (n >= N_NODES) return;
    int l = threadIdx.x & 31;

    float4 b = h4tof4(grh[(size_t)n * 32 + l]);
    float4 t = __ldg(&((const float4*)att)[l]);

    float ax = 0.f, ay = 0.f, az = 0.f, aw = 0.f, dw = 0.f;

    int start = off[n], cnt = deg[n];
    for (int base = 0; base < cnt; base += 32) {
        int rem = cnt - base;
        int m = rem < 32 ? rem : 32;
        int eld = (l < m) ? __ldg(&eidx[start + base + l]) : 0;
        int j = 0;
        for (; j + 1 < m; j += 2) {
            int s0 = __shfl_sync(0xffffffffu, eld, j);
            int s1 = __shfl_sync(0xffffffffu, eld, j + 1);
            float4 a0 = h4tof4(__ldg(&glh[(size_t)s0 * 32 + l]));
            float4 a1 = h4tof4(__ldg(&glh[(size_t)s1 * 32 + l]));

            float v0x = a0.x + b.x; v0x = v0x > 0.f ? v0x : SLOPE * v0x;
            float v0y = a0.y + b.y; v0y = v0y > 0.f ? v0y : SLOPE * v0y;
            float v0z = a0.z + b.z; v0z = v0z > 0.f ? v0z : SLOPE * v0z;
            float v0w = a0.w + b.w; v0w = v0w > 0.f ? v0w : SLOPE * v0w;
            float p0 = v0x * t.x + v0y * t.y + v0z * t.z + v0w * t.w;

            float v1x = a1.x + b.x; v1x = v1x > 0.f ? v1x : SLOPE * v1x;
            float v1y = a1.y + b.y; v1y = v1y > 0.f ? v1y : SLOPE * v1y;
            float v1z = a1.z + b.z; v1z = v1z > 0.f ? v1z : SLOPE * v1z;
            float v1w = a1.w + b.w; v1w = v1w > 0.f ? v1w : SLOPE * v1w;
            float p1 = v1x * t.x + v1y * t.y + v1z * t.z + v1w * t.w;

            p0 += __shfl_xor_sync(0xffffffffu, p0, 4);
            p1 += __shfl_xor_sync(0xffffffffu, p1, 4);
            p0 += __shfl_xor_sync(0xffffffffu, p0, 2);
            p1 += __shfl_xor_sync(0xffffffffu, p1, 2);
            p0 += __shfl_xor_sync(0xffffffffu, p0, 1);
            p1 += __shfl_xor_sync(0xffffffffu, p1, 1);
            float w0 = __expf(p0), w1 = __expf(p1);

            ax += w0 * a0.x + w1 * a1.x;
            ay += w0 * a0.y + w1 * a1.y;
            az += w0 * a0.z + w1 * a1.z;
            aw += w0 * a0.w + w1 * a1.w;
            dw += w0 + w1;
        }
        if (j < m) {
            int s = __shfl_sync(0xffffffffu, eld, j);
            float4 a = h4tof4(__ldg(&glh[(size_t)s * 32 + l]));
            float vx = a.x + b.x; vx = vx > 0.f ? vx : SLOPE * vx;
            float vy = a.y + b.y; vy = vy > 0.f ? vy : SLOPE * vy;
            float vz = a.z + b.z; vz = vz > 0.f ? vz : SLOPE * vz;
            float vw = a.w + b.w; vw = vw > 0.f ? vw : SLOPE * vw;
            float p = vx * t.x + vy * t.y + vz * t.z + vw * t.w;
            p += __shfl_xor_sync(0xffffffffu, p, 4);
            p += __shfl_xor_sync(0xffffffffu, p, 2);
            p += __shfl_xor_sync(0xffffffffu, p, 1);
            float w = __expf(p);
            ax += w * a.x; ay += w * a.y; az += w * a.z; aw += w * a.w;
            dw += w;
        }
    }

    float inv = 1.0f / (dw + 1e-16f);
    float4 v = make_float4(ax * inv, ay * inv, az * inv, aw * inv);
    if (mode == 1) {
        v.x = v.x > 0.f ? v.x : expm1f(v.x);
        v.y = v.y > 0.f ? v.y : expm1f(v.y);
        v.z = v.z > 0.f ? v.z : expm1f(v.z);
        v.w = v.w > 0.f ? v.w : expm1f(v.w);
    } else {
        v.x = fmaxf(v.x, 0.f); v.y = fmaxf(v.y, 0.f);
        v.z = fmaxf(v.z, 0.f); v.w = fmaxf(v.w, 0.f);
    }
    uint4 o;
    o.x = packsplit(v.x); o.y = packsplit(v.y);
    o.z = packsplit(v.z); o.w = packsplit(v.w);
    houtp[(size_t)n * 32 + l] = o;
}

// ================= node layer 3 + log_softmax (H=1, F=40, fp32) =============
__global__ __launch_bounds__(256) void k_node_h1_lsm(
    const float4* __restrict__ gl4, const float4* __restrict__ gr4,
    const float* __restrict__ att,
    const int* __restrict__ off, const int* __restrict__ deg,
    const int* __restrict__ eidx, float* __restrict__ out)
{
    int l = threadIdx.x & 31;
    int sub = l >> 4;
    int ll = l & 15;
    unsigned mask = 0xFFFFu << (sub * 16);
    int n = blockIdx.x * 16 + (threadIdx.x >> 5) * 2 + sub;
    if (n >= N_NODES) return;

    float4 b = make_float4(0.f, 0.f, 0.f, 0.f), t = b;
    if (ll < 10) {
        b = gr4[(size_t)n * 10 + ll];
        t = __ldg(&((const float4*)att)[ll]);
    }

    float ax = 0.f, ay = 0.f, az = 0.f, aw = 0.f, dw = 0.f;

    int start = off[n], cnt = deg[n];
    for (int base = 0; base < cnt; base += 16) {
        int rem = cnt - base;
        int m = rem < 16 ? rem : 16;
        int eld = (ll < m) ? __ldg(&eidx[start + base + ll]) : 0;
        for (int j = 0; j < m; j++) {
            int s = __shfl_sync(mask, eld, j, 16);
            float4 a = make_float4(0.f, 0.f, 0.f, 0.f);
            float p = 0.f;
            if (ll < 10) {
                a = __ldg(&gl4[(size_t)s * 10 + ll]);
                float vx = a.x + b.x; vx = vx > 0.f ? vx : SLOPE * vx;
                float vy = a.y + b.y; vy = vy > 0.f ? vy : SLOPE * vy;
                float vz = a.z + b.z; vz = vz > 0.f ? vz : SLOPE * vz;
                float vw = a.w + b.w; vw = vw > 0.f ? vw : SLOPE * vw;
                p = vx * t.x + vy * t.y + vz * t.z + vw * t.w;
            }
            p += __shfl_xor_sync(mask, p, 8, 16);
            p += __shfl_xor_sync(mask, p, 4, 16);
            p += __shfl_xor_sync(mask, p, 2, 16);
            p += __shfl_xor_sync(mask, p, 1, 16);
            float w = __expf(p);
            ax += w * a.x; ay += w * a.y; az += w * a.z; aw += w * a.w;
            dw += w;
        }
    }

    float inv = 1.0f / (dw + 1e-16f);
    float4 v = make_float4(ax * inv, ay * inv, az * inv, aw * inv);

    float mx = (ll < 10) ? fmaxf(fmaxf(v.x, v.y), fmaxf(v.z, v.w)) : -FLT_MAX;
    #pragma unroll
    for (int o = 8; o > 0; o >>= 1) mx = fmaxf(mx, __shfl_xor_sync(mask, mx, o, 16));
    float ss = (ll < 10)
        ? (expf(v.x - mx) + expf(v.y - mx) + expf(v.z - mx) + expf(v.w - mx)) : 0.f;
    #pragma unroll
    for (int o = 8; o > 0; o >>= 1) ss += __shfl_xor_sync(mask, ss, o, 16);
    float lse = mx + logf(ss);
    if (ll < 10) {
        float4 r = make_float4(v.x - lse, v.y - lse, v.z - lse, v.w - lse);
        *(float4*)(out + (size_t)n * 40 + 4 * ll) = r;
    }
}

// ---------------- host -------------------------------------------------------
extern "C" void kernel_launch(void* const* d_in, const int* in_sizes, int n_in,
                              void* d_out, int out_size)
{
    const float* x    = (const float*)d_in[0];
    const float* Wl1  = (const float*)d_in[1];
    const float* Wr1  = (const float*)d_in[2];
    const float* att1 = (const float*)d_in[3];
    const float* Wl2  = (const float*)d_in[4];
    const float* Wr2  = (const float*)d_in[5];
    const float* att2 = (const float*)d_in[6];
    const float* Wl3  = (const float*)d_in[7];
    const float* Wr3  = (const float*)d_in[8];
    const float* att3 = (const float*)d_in[9];
    const int*   ei   = (const int*)d_in[10];
    const int* src = ei;
    const int* dst = ei + N_EDGES;
    float* out = (float*)d_out;

    float *gl, *gr;
    uint32_t *xs, *hs, *ws;
    int *deg, *off, *cur, *bsum, *eidx;
    cudaGetSymbolAddress((void**)&gl,   g_gl);
    cudaGetSymbolAddress((void**)&gr,   g_gr);
    cudaGetSymbolAddress((void**)&xs,   g_xs);
    cudaGetSymbolAddress((void**)&hs,   g_hs);
    cudaGetSymbolAddress((void**)&ws,   g_ws);
    cudaGetSymbolAddress((void**)&deg,  g_deg);
    cudaGetSymbolAddress((void**)&off,  g_off);
    cudaGetSymbolAddress((void**)&cur,  g_cur);
    cudaGetSymbolAddress((void**)&bsum, g_bsum);
    cudaGetSymbolAddress((void**)&eidx, g_eidx);

    __half* glh = (__half*)gl;
    __half* grh = (__half*)gr;

    const int GB = (N_NODES + 63) / 64;
    const dim3 g40(2, (N_NODES + 63) / 64);
    const int NB4 = (N_NODES + 7) / 8;
    const int NB1 = (N_NODES + 15) / 16;
    const int NSCAN = (N_NODES + 1023) / 1024;

    // splits + CSR front
    k_split_w<<<64, 256>>>(Wl1, Wr1, Wl2, Wr2, ws);
    k_split<<<(N_NODES * 128 / 4 + 255) / 256, 256>>>(x, xs, N_NODES * 128);
    cudaMemsetAsync(deg, 0, N_NODES * sizeof(int));
    k_hist<<<(N_EDGES + 255) / 256, 256>>>(dst, deg);
    k_scan_part<<<NSCAN, 1024>>>(deg, off, bsum);
    // layer-1 GEMM (independent of CSR)
    k_gemm_tc2<<<GB, 256>>>(xs, ws + 0 * 16384, ws + 1 * 16384, glh, grh, N_NODES);
    // CSR back
    k_scan_add<<<(N_NODES + 255) / 256, 256>>>(off, cur, bsum);
    k_scatter<<<(N_EDGES + 255) / 256, 256>>>(src, dst, cur, eidx);

    // ---- Layer 1 aggregate ----
    k_node_h4<<<NB4, 256>>>((const uint2*)glh, (const uint2*)grh, att1,
                            off, deg, eidx, (uint4*)hs, 1);
    // ---- Layer 2 ----
    k_gemm_tc2<<<GB, 256>>>(hs, ws + 2 * 16384, ws + 3 * 16384, glh, grh, N_NODES);
    k_node_h4<<<NB4, 256>>>((const uint2*)glh, (const uint2*)grh, att2,
                            off, deg, eidx, (uint4*)hs, 2);
    // ---- Layer 3 (fp32 end-to-end) ----
    k_gemm40_dual<<<g40, 256>>>(hs, Wl3, Wr3, gl, gr, N_NODES, 40);
    k_node_h1_lsm<<<NB1, 256>>>((const float4*)gl, (const float4*)gr, att3,
                                off, deg, eidx, out);
}

// round 10
// speedup vs baseline: 3.2722x; 1.0272x over previous
#include <cuda_runtime.h>
#include <cuda_bf16.h>
#include <cuda_fp16.h>
#include <math.h>
#include <float.h>
#include <stdint.h>

#define N_NODES 50000
#define N_EDGES 800000
#define SLOPE 0.2f

// ---------------- scratch (device globals; no allocation allowed) ----------
__device__ float    g_gl[N_NODES * 128];   // fp32 view (layer 3) / fp16 view (layers 1-2)
__device__ float    g_gr[N_NODES * 128];
__device__ uint32_t g_xs[N_NODES * 128];   // packed (hi,lo) bf16 split of x
__device__ uint32_t g_hs[N_NODES * 128];   // packed split of hidden h
__device__ uint32_t g_ws[4 * 16384];       // packed splits of Wl1,Wr1,Wl2,Wr2
__device__ int      g_deg[N_NODES];
__device__ int      g_off[N_NODES];
__device__ int      g_cur[N_NODES];
__device__ int      g_bsum[64];
__device__ int      g_eidx[N_EDGES];

// ---- bf16 hi/lo split pack -------------------------------------------------
__device__ __forceinline__ uint32_t packsplit(float x) {
    __nv_bfloat16 h = __float2bfloat16(x);
    __nv_bfloat16 l = __float2bfloat16(x - __bfloat162float(h));
    return ((uint32_t)__bfloat16_as_ushort(h) << 16) | (uint32_t)__bfloat16_as_ushort(l);
}
__device__ __forceinline__ float unpacksplit(uint32_t v) {
    __nv_bfloat16 h = __ushort_as_bfloat16((unsigned short)(v >> 16));
    __nv_bfloat16 l = __ushort_as_bfloat16((unsigned short)(v & 0xffff));
    return __bfloat162float(h) + __bfloat162float(l);
}

__global__ void k_split(const float* __restrict__ in, uint32_t* __restrict__ outp, int n) {
    int i = (blockIdx.x * blockDim.x + threadIdx.x) * 4;
    if (i >= n) return;
    float4 v = *(const float4*)(in + i);
    uint4 o;
    o.x = packsplit(v.x); o.y = packsplit(v.y);
    o.z = packsplit(v.z); o.w = packsplit(v.w);
    *(uint4*)(outp + i) = o;
}

__global__ void k_split_w(const float* __restrict__ w0, const float* __restrict__ w1,
                          const float* __restrict__ w2, const float* __restrict__ w3,
                          uint32_t* __restrict__ outp) {
    int i = (blockIdx.x * blockDim.x + threadIdx.x) * 4;
    int sel = i >> 14;
    int o4 = i & 16383;
    const float* w = (sel == 0) ? w0 : (sel == 1) ? w1 : (sel == 2) ? w2 : w3;
    float4 v = *(const float4*)(w + o4);
    uint4 o;
    o.x = packsplit(v.x); o.y = packsplit(v.y);
    o.z = packsplit(v.z); o.w = packsplit(v.w);
    *(uint4*)(outp + i) = o;
}

// ================= CSR construction ==========================================
__global__ void k_hist(const int* __restrict__ dst, int* __restrict__ deg) {
    int e = blockIdx.x * blockDim.x + threadIdx.x;
    if (e < N_EDGES) atomicAdd(&deg[dst[e]], 1);
}

__global__ __launch_bounds__(1024) void k_scan_part(
    const int* __restrict__ deg, int* __restrict__ off, int* __restrict__ bsum)
{
    __shared__ int sh[1024];
    int t = threadIdx.x;
    int i = blockIdx.x * 1024 + t;
    int v = (i < N_NODES) ? deg[i] : 0;
    sh[t] = v;
    __syncthreads();
    #pragma unroll
    for (int o = 1; o < 1024; o <<= 1) {
        int u = (t >= o) ? sh[t - o] : 0;
        __syncthreads();
        sh[t] += u;
        __syncthreads();
    }
    if (i < N_NODES) off[i] = sh[t] - v;
    if (t == 1023) bsum[blockIdx.x] = sh[t];
}

__global__ void k_scan_add(int* __restrict__ off, int* __restrict__ cur,
                           const int* __restrict__ bsum)
{
    __shared__ int base_sh;
    int i = blockIdx.x * blockDim.x + threadIdx.x;
    int b = (blockIdx.x * blockDim.x) >> 10;
    if (threadIdx.x == 0) {
        int s = 0;
        for (int j = 0; j < b; j++) s += bsum[j];
        base_sh = s;
    }
    __syncthreads();
    if (i >= N_NODES) return;
    int o = off[i] + base_sh;
    off[i] = o;
    cur[i] = o;
}

__global__ void k_scatter(const int* __restrict__ src, const int* __restrict__ dst,
                          int* __restrict__ cur, int* __restrict__ eidx)
{
    int e = blockIdx.x * blockDim.x + threadIdx.x;
    if (e >= N_EDGES) return;
    int p = atomicAdd(&cur[dst[e]], 1);
    eidx[p] = src[e];
}

// ================= tensor-core helpers =======================================
__device__ __forceinline__ uint32_t smem_u32(const void* p) {
    return (uint32_t)__cvta_generic_to_shared(p);
}
__device__ __forceinline__ void ldsm_x4(uint32_t& r0, uint32_t& r1, uint32_t& r2, uint32_t& r3, uint32_t addr) {
    asm volatile("ldmatrix.sync.aligned.m8n8.x4.shared.b16 {%0,%1,%2,%3},[%4];"
                 : "=r"(r0), "=r"(r1), "=r"(r2), "=r"(r3) : "r"(addr));
}
__device__ __forceinline__ void ldsm_x2_t(uint32_t& r0, uint32_t& r1, uint32_t addr) {
    asm volatile("ldmatrix.sync.aligned.m8n8.x2.trans.shared.b16 {%0,%1},[%2];"
                 : "=r"(r0), "=r"(r1) : "r"(addr));
}
__device__ __forceinline__ void mma_bf16c(float* d, const uint32_t* a, const uint32_t* b) {
    asm volatile("mma.sync.aligned.m16n8k16.row.col.f32.bf16.bf16.f32 "
                 "{%0,%1,%2,%3},{%4,%5,%6,%7},{%8,%9},{%0,%1,%2,%3};"
                 : "+f"(d[0]), "+f"(d[1]), "+f"(d[2]), "+f"(d[3])
                 : "r"(a[0]), "r"(a[1]), "r"(a[2]), "r"(a[3]), "r"(b[0]), "r"(b[1]));
}

// ================= TC dual GEMM, fp16 output =================================
__global__ __launch_bounds__(256, 2) void k_gemm_tc2(
    const uint32_t* __restrict__ Ap,
    const uint32_t* __restrict__ W1p, const uint32_t* __restrict__ W2p,
    __half* __restrict__ C1, __half* __restrict__ C2, int M)
{
    __shared__ __nv_bfloat16 Ah[64][40];
    __shared__ __nv_bfloat16 Al[64][40];
    __shared__ __nv_bfloat16 Wh[32][264];
    __shared__ __nv_bfloat16 Wl[32][264];

    const int tid = threadIdx.x, lane = tid & 31, wid = tid >> 5;
    const int wm = wid & 1;
    const int wn = wid >> 1;
    const int r0 = blockIdx.x * 64;

    float d[2][8][4];
    #pragma unroll
    for (int i = 0; i < 2; i++)
        #pragma unroll
        for (int j = 0; j < 8; j++)
            #pragma unroll
            for (int k = 0; k < 4; k++) d[i][j][k] = 0.f;

    for (int kt = 0; kt < 4; kt++) {
        #pragma unroll
        for (int i = 0; i < 2; i++) {
            int idx = tid + i * 256;
            int row = idx >> 3, q = idx & 7;
            uint4 p = make_uint4(0u, 0u, 0u, 0u);
            if (r0 + row < M)
                p = *(const uint4*)(Ap + (size_t)(r0 + row) * 128 + kt * 32 + q * 4);
            uint2 hi, lo;
            hi.x = __byte_perm(p.x, p.y, 0x7632); hi.y = __byte_perm(p.z, p.w, 0x7632);
            lo.x = __byte_perm(p.x, p.y, 0x5410); lo.y = __byte_perm(p.z, p.w, 0x5410);
            *(uint2*)&Ah[row][q * 4] = hi;
            *(uint2*)&Al[row][q * 4] = lo;
        }
        #pragma unroll
        for (int i = 0; i < 8; i++) {
            int idx = tid + i * 256;
            int k = idx >> 6, q = idx & 63;
            uint4 p = (q < 32)
                ? *(const uint4*)(W1p + (size_t)(kt * 32 + k) * 128 + q * 4)
                : *(const uint4*)(W2p + (size_t)(kt * 32 + k) * 128 + (q - 32) * 4);
            uint2 hi, lo;
            hi.x = __byte_perm(p.x, p.y, 0x7632); hi.y = __byte_perm(p.z, p.w, 0x7632);
            lo.x = __byte_perm(p.x, p.y, 0x5410); lo.y = __byte_perm(p.z, p.w, 0x5410);
            *(uint2*)&Wh[k][q * 4] = hi;
            *(uint2*)&Wl[k][q * 4] = lo;
        }
        __syncthreads();

        #pragma unroll
        for (int ph = 0; ph < 3; ph++) {
            const __nv_bfloat16 (*Asm)[40]  = (ph == 1) ? Al : Ah;
            const __nv_bfloat16 (*Wsm)[264] = (ph == 2) ? Wl : Wh;
            #pragma unroll
            for (int k16 = 0; k16 < 2; k16++) {
                uint32_t af[2][4], bfr[8][2];
                #pragma unroll
                for (int mf = 0; mf < 2; mf++) {
                    uint32_t addr = smem_u32(
                        &Asm[wm * 32 + mf * 16 + (lane & 15)][k16 * 16 + (lane >> 4) * 8]);
                    ldsm_x4(af[mf][0], af[mf][1], af[mf][2], af[mf][3], addr);
                }
                #pragma unroll
                for (int nf = 0; nf < 8; nf++) {
                    uint32_t addr = smem_u32(
                        &Wsm[k16 * 16 + (lane & 15)][wn * 64 + nf * 8]);
                    ldsm_x2_t(bfr[nf][0], bfr[nf][1], addr);
                }
                #pragma unroll
                for (int mf = 0; mf < 2; mf++)
                    #pragma unroll
                    for (int nf = 0; nf < 8; nf++)
                        mma_bf16c(d[mf][nf], af[mf], bfr[nf]);
            }
        }
        __syncthreads();
    }

    const int g = lane >> 2, t = lane & 3;
    __half* Cp = (wn < 2) ? C1 : C2;
    int cbase = (wn < 2) ? wn * 64 : (wn - 2) * 64;
    #pragma unroll
    for (int mf = 0; mf < 2; mf++) {
        #pragma unroll
        for (int nf = 0; nf < 8; nf++) {
            int row0 = r0 + wm * 32 + mf * 16 + g;
            int col = cbase + nf * 8 + t * 2;
            if (row0 < M)
                *(__half2*)(Cp + (size_t)row0 * 128 + col) =
                    __floats2half2_rn(d[mf][nf][0], d[mf][nf][1]);
            if (row0 + 8 < M)
                *(__half2*)(Cp + (size_t)(row0 + 8) * 128 + col) =
                    __floats2half2_rn(d[mf][nf][2], d[mf][nf][3]);
        }
    }
}

// ================= dual SGEMM (Ncols=40, FFMA, packed A, fp32 out) ==========
__global__ __launch_bounds__(256) void k_gemm40_dual(
    const uint32_t* __restrict__ Ap,
    const float* __restrict__ Wa, const float* __restrict__ Wb,
    float* __restrict__ Ca, float* __restrict__ Cb, int M, int Ncols)
{
    const float* W = blockIdx.x ? Wb : Wa;
    float* C = blockIdx.x ? Cb : Ca;

    __shared__ float As[64][68];
    __shared__ float Ws[64][64];

    const int tid = threadIdx.x;
    const int tx = tid & 15;
    const int ty = tid >> 4;
    const int r0 = blockIdx.y * 64;

    float acc[4][4] = {};

    for (int kk = 0; kk < 128; kk += 64) {
        __syncthreads();
        #pragma unroll
        for (int i = 0; i < 4; i++) {
            int f = tid + i * 256;
            int row = f >> 4;
            int k4 = f & 15;
            float4 a = make_float4(0.f, 0.f, 0.f, 0.f);
            int r = r0 + row;
            if (r < M) {
                uint4 p = *(const uint4*)(Ap + (size_t)r * 128 + kk + k4 * 4);
                a.x = unpacksplit(p.x); a.y = unpacksplit(p.y);
                a.z = unpacksplit(p.z); a.w = unpacksplit(p.w);
            }
            *(float4*)(&As[row][k4 * 4]) = a;
        }
        #pragma unroll
        for (int i = 0; i < 16; i++) {
            int f = tid + i * 256;
            int k = f >> 6, c = f & 63;
            Ws[k][c] = (c < Ncols) ? W[(size_t)(kk + k) * Ncols + c] : 0.f;
        }
        __syncthreads();

        #pragma unroll 16
        for (int k = 0; k < 64; k++) {
            float4 b = *(const float4*)(&Ws[k][tx * 4]);
            float a0 = As[ty * 4 + 0][k];
            float a1 = As[ty * 4 + 1][k];
            float a2 = As[ty * 4 + 2][k];
            float a3 = As[ty * 4 + 3][k];
            acc[0][0] += a0 * b.x; acc[0][1] += a0 * b.y; acc[0][2] += a0 * b.z; acc[0][3] += a0 * b.w;
            acc[1][0] += a1 * b.x; acc[1][1] += a1 * b.y; acc[1][2] += a1 * b.z; acc[1][3] += a1 * b.w;
            acc[2][0] += a2 * b.x; acc[2][1] += a2 * b.y; acc[2][2] += a2 * b.z; acc[2][3] += a2 * b.w;
            acc[3][0] += a3 * b.x; acc[3][1] += a3 * b.y; acc[3][2] += a3 * b.z; acc[3][3] += a3 * b.w;
        }
    }

    #pragma unroll
    for (int i = 0; i < 4; i++) {
        int r = r0 + ty * 4 + i;
        if (r >= M) continue;
        #pragma unroll
        for (int j = 0; j < 4; j++) {
            int c = tx * 4 + j;
            if (c < Ncols) C[(size_t)r * Ncols + c] = acc[i][j];
        }
    }
}

// ================= node aggregation (H=4, F=32), half2 math, 2 edges/warp ===
// warp per dst node. Lanes split into two 16-lane halves, each handling one
// edge of a pair (same node => uniform trip count, full-mask shfls legal).
// Lane ll (=lane&15) owns features 8*ll..8*ll+7 as 4x half2; head = ll>>2.
// Score math in half2 (lrelu = max(x, 0.2x)); accumulation in fp32.
__global__ __launch_bounds__(256) void k_node_h4(
    const uint4* __restrict__ glh, const uint4* __restrict__ grh,
    const float* __restrict__ att,
    const int* __restrict__ off, const int* __restrict__ deg,
    const int* __restrict__ eidx, uint4* __restrict__ houtp, int mode)
{
    int n = blockIdx.x * 8 + (threadIdx.x >> 5);
    if (n >= N_NODES) return;
    int lane = threadIdx.x & 31;
    int sub = lane >> 4;
    int ll = lane & 15;

    // gr features for this node (8 halfs)
    uint4 braw = grh[(size_t)n * 16 + ll];
    __half2 b2[4];
    b2[0] = *(__half2*)&braw.x; b2[1] = *(__half2*)&braw.y;
    b2[2] = *(__half2*)&braw.z; b2[3] = *(__half2*)&braw.w;

    // att (fp32 in gmem) -> half2, once per node
    float4 t0 = __ldg((const float4*)att + 2 * ll);
    float4 t1 = __ldg((const float4*)att + 2 * ll + 1);
    __half2 t2[4];
    t2[0] = __floats2half2_rn(t0.x, t0.y); t2[1] = __floats2half2_rn(t0.z, t0.w);
    t2[2] = __floats2half2_rn(t1.x, t1.y); t2[3] = __floats2half2_rn(t1.z, t1.w);

    const __half2 slope2 = __floats2half2_rn(SLOPE, SLOPE);

    float f[8];
    #pragma unroll
    for (int i = 0; i < 8; i++) f[i] = 0.f;
    float dw = 0.f;

    int start = off[n], cnt = deg[n];
    for (int base = 0; base < cnt; base += 32) {
        int rem = cnt - base;
        int m = rem < 32 ? rem : 32;
        int eld = (lane < m) ? __ldg(&eidx[start + base + lane]) : 0;
        int hm = (m + 1) >> 1;
        for (int j = 0; j < hm; j++) {
            int idx = 2 * j + sub;
            int s = __shfl_sync(0xffffffffu, eld, idx);
            uint4 araw = __ldg(&glh[(size_t)s * 16 + ll]);
            __half2 a2[4];
            a2[0] = *(__half2*)&araw.x; a2[1] = *(__half2*)&araw.y;
            a2[2] = *(__half2*)&araw.z; a2[3] = *(__half2*)&araw.w;

            __half2 acc = __floats2half2_rn(0.f, 0.f);
            #pragma unroll
            for (int i = 0; i < 4; i++) {
                __half2 s2 = __hadd2(a2[i], b2[i]);
                __half2 e2 = __hmax2(s2, __hmul2(s2, slope2));
                acc = __hfma2(e2, t2[i], acc);
            }
            float2 pf = __half22float2(acc);
            float p = pf.x + pf.y;
            p += __shfl_xor_sync(0xffffffffu, p, 2);
            p += __shfl_xor_sync(0xffffffffu, p, 1);
            float w = (idx < m) ? __expf(p) : 0.f;

            #pragma unroll
            for (int i = 0; i < 4; i++) {
                float2 af = __half22float2(a2[i]);
                f[2 * i]     += w * af.x;
                f[2 * i + 1] += w * af.y;
            }
            dw += w;
        }
    }

    // combine the two halves (each processed half the edges)
    #pragma unroll
    for (int i = 0; i < 8; i++) f[i] += __shfl_xor_sync(0xffffffffu, f[i], 16);
    dw += __shfl_xor_sync(0xffffffffu, dw, 16);

    if (sub == 0) {
        float inv = 1.0f / (dw + 1e-16f);
        uint32_t o[8];
        #pragma unroll
        for (int i = 0; i < 8; i++) {
            float v = f[i] * inv;
            if (mode == 1) v = v > 0.f ? v : expm1f(v);
            else           v = fmaxf(v, 0.f);
            o[i] = packsplit(v);
        }
        houtp[(size_t)n * 32 + 2 * ll]     = make_uint4(o[0], o[1], o[2], o[3]);
        houtp[(size_t)n * 32 + 2 * ll + 1] = make_uint4(o[4], o[5], o[6], o[7]);
    }
}

// ================= node layer 3 + log_softmax (H=1, F=40, fp32) =============
__global__ __launch_bounds__(256) void k_node_h1_lsm(
    const float4* __restrict__ gl4, const float4* __restrict__ gr4,
    const float* __restrict__ att,
    const int* __restrict__ off, const int* __restrict__ deg,
    const int* __restrict__ eidx, float* __restrict__ out)
{
    int l = threadIdx.x & 31;
    int sub = l >> 4;
    int ll = l & 15;
    unsigned mask = 0xFFFFu << (sub * 16);
    int n = blockIdx.x * 16 + (threadIdx.x >> 5) * 2 + sub;
    if (n >= N_NODES) return;

    float4 b = make_float4(0.f, 0.f, 0.f, 0.f), t = b;
    if (ll < 10) {
        b = gr4[(size_t)n * 10 + ll];
        t = __ldg(&((const float4*)att)[ll]);
    }

    float ax = 0.f, ay = 0.f, az = 0.f, aw = 0.f, dw = 0.f;

    int start = off[n], cnt = deg[n];
    for (int base = 0; base < cnt; base += 16) {
        int rem = cnt - base;
        int m = rem < 16 ? rem : 16;
        int eld = (ll < m) ? __ldg(&eidx[start + base + ll]) : 0;
        for (int j = 0; j < m; j++) {
            int s = __shfl_sync(mask, eld, j, 16);
            float4 a = make_float4(0.f, 0.f, 0.f, 0.f);
            float p = 0.f;
            if (ll < 10) {
                a = __ldg(&gl4[(size_t)s * 10 + ll]);
                float vx = a.x + b.x; vx = vx > 0.f ? vx : SLOPE * vx;
                float vy = a.y + b.y; vy = vy > 0.f ? vy : SLOPE * vy;
                float vz = a.z + b.z; vz = vz > 0.f ? vz : SLOPE * vz;
                float vw = a.w + b.w; vw = vw > 0.f ? vw : SLOPE * vw;
                p = vx * t.x + vy * t.y + vz * t.z + vw * t.w;
            }
            p += __shfl_xor_sync(mask, p, 8, 16);
            p += __shfl_xor_sync(mask, p, 4, 16);
            p += __shfl_xor_sync(mask, p, 2, 16);
            p += __shfl_xor_sync(mask, p, 1, 16);
            float w = __expf(p);
            ax += w * a.x; ay += w * a.y; az += w * a.z; aw += w * a.w;
            dw += w;
        }
    }

    float inv = 1.0f / (dw + 1e-16f);
    float4 v = make_float4(ax * inv, ay * inv, az * inv, aw * inv);

    float mx = (ll < 10) ? fmaxf(fmaxf(v.x, v.y), fmaxf(v.z, v.w)) : -FLT_MAX;
    #pragma unroll
    for (int o = 8; o > 0; o >>= 1) mx = fmaxf(mx, __shfl_xor_sync(mask, mx, o, 16));
    float ss = (ll < 10)
        ? (expf(v.x - mx) + expf(v.y - mx) + expf(v.z - mx) + expf(v.w - mx)) : 0.f;
    #pragma unroll
    for (int o = 8; o > 0; o >>= 1) ss += __shfl_xor_sync(mask, ss, o, 16);
    float lse = mx + logf(ss);
    if (ll < 10) {
        float4 r = make_float4(v.x - lse, v.y - lse, v.z - lse, v.w - lse);
        *(float4*)(out + (size_t)n * 40 + 4 * ll) = r;
    }
}

// ---------------- host -------------------------------------------------------
extern "C" void kernel_launch(void* const* d_in, const int* in_sizes, int n_in,
                              void* d_out, int out_size)
{
    const float* x    = (const float*)d_in[0];
    const float* Wl1  = (const float*)d_in[1];
    const float* Wr1  = (const float*)d_in[2];
    const float* att1 = (const float*)d_in[3];
    const float* Wl2  = (const float*)d_in[4];
    const float* Wr2  = (const float*)d_in[5];
    const float* att2 = (const float*)d_in[6];
    const float* Wl3  = (const float*)d_in[7];
    const float* Wr3  = (const float*)d_in[8];
    const float* att3 = (const float*)d_in[9];
    const int*   ei   = (const int*)d_in[10];
    const int* src = ei;
    const int* dst = ei + N_EDGES;
    float* out = (float*)d_out;

    float *gl, *gr;
    uint32_t *xs, *hs, *ws;
    int *deg, *off, *cur, *bsum, *eidx;
    cudaGetSymbolAddress((void**)&gl,   g_gl);
    cudaGetSymbolAddress((void**)&gr,   g_gr);
    cudaGetSymbolAddress((void**)&xs,   g_xs);
    cudaGetSymbolAddress((void**)&hs,   g_hs);
    cudaGetSymbolAddress((void**)&ws,   g_ws);
    cudaGetSymbolAddress((void**)&deg,  g_deg);
    cudaGetSymbolAddress((void**)&off,  g_off);
    cudaGetSymbolAddress((void**)&cur,  g_cur);
    cudaGetSymbolAddress((void**)&bsum, g_bsum);
    cudaGetSymbolAddress((void**)&eidx, g_eidx);

    __half* glh = (__half*)gl;
    __half* grh = (__half*)gr;

    const int GB = (N_NODES + 63) / 64;
    const dim3 g40(2, (N_NODES + 63) / 64);
    const int NB4 = (N_NODES + 7) / 8;
    const int NB1 = (N_NODES + 15) / 16;
    const int NSCAN = (N_NODES + 1023) / 1024;

    // splits + CSR front
    k_split_w<<<64, 256>>>(Wl1, Wr1, Wl2, Wr2, ws);
    k_split<<<(N_NODES * 128 / 4 + 255) / 256, 256>>>(x, xs, N_NODES * 128);
    cudaMemsetAsync(deg, 0, N_NODES * sizeof(int));
    k_hist<<<(N_EDGES + 255) / 256, 256>>>(dst, deg);
    k_scan_part<<<NSCAN, 1024>>>(deg, off, bsum);
    // layer-1 GEMM (independent of CSR)
    k_gemm_tc2<<<GB, 256>>>(xs, ws + 0 * 16384, ws + 1 * 16384, glh, grh, N_NODES);
    // CSR back
    k_scan_add<<<(N_NODES + 255) / 256, 256>>>(off, cur, bsum);
    k_scatter<<<(N_EDGES + 255) / 256, 256>>>(src, dst, cur, eidx);

    // ---- Layer 1 aggregate ----
    k_node_h4<<<NB4, 256>>>((const uint4*)glh, (const uint4*)grh, att1,
                            off, deg, eidx, (uint4*)hs, 1);
    // ---- Layer 2 ----
    k_gemm_tc2<<<GB, 256>>>(hs, ws + 2 * 16384, ws + 3 * 16384, glh, grh, N_NODES);
    k_node_h4<<<NB4, 256>>>((const uint4*)glh, (const uint4*)grh, att2,
                            off, deg, eidx, (uint4*)hs, 2);
    // ---- Layer 3 (fp32 end-to-end) ----
    k_gemm40_dual<<<g40, 256>>>(hs, Wl3, Wr3, gl, gr, N_NODES, 40);
    k_node_h1_lsm<<<NB1, 256>>>((const float4*)gl, (const float4*)gr, att3,
                                off, deg, eidx, out);
}

// round 11
// speedup vs baseline: 3.6629x; 1.1194x over previous
#include <cuda_runtime.h>
#include <cuda_bf16.h>
#include <cuda_fp16.h>
#include <math.h>
#include <float.h>
#include <stdint.h>

#define N_NODES 50000
#define N_EDGES 800000
#define SLOPE 0.2f

// ---------------- scratch (device globals; no allocation allowed) ----------
__device__ float    g_gl[N_NODES * 128];   // fp16 view (layers 1-2) / fp32 [N,40] (layer 3)
__device__ float    g_gr[N_NODES * 128];
__device__ uint32_t g_xs[N_NODES * 128];   // packed (hi,lo) bf16 split of x
__device__ uint32_t g_hs[N_NODES * 128];   // packed split of hidden h
__device__ uint32_t g_ws[4 * 16384];       // packed splits of Wl1,Wr1,Wl2,Wr2
__device__ uint32_t g_w3s[2 * 8192];       // packed splits of Wl3,Wr3 padded [128,64]
__device__ int      g_deg[N_NODES];
__device__ int      g_off[N_NODES];
__device__ int      g_cur[N_NODES];
__device__ int      g_bsum[64];
__device__ int      g_eidx[N_EDGES];

// ---- bf16 hi/lo split pack -------------------------------------------------
__device__ __forceinline__ uint32_t packsplit(float x) {
    __nv_bfloat16 h = __float2bfloat16(x);
    __nv_bfloat16 l = __float2bfloat16(x - __bfloat162float(h));
    return ((uint32_t)__bfloat16_as_ushort(h) << 16) | (uint32_t)__bfloat16_as_ushort(l);
}

__global__ void k_split(const float* __restrict__ in, uint32_t* __restrict__ outp, int n) {
    int i = (blockIdx.x * blockDim.x + threadIdx.x) * 4;
    if (i >= n) return;
    float4 v = *(const float4*)(in + i);
    uint4 o;
    o.x = packsplit(v.x); o.y = packsplit(v.y);
    o.z = packsplit(v.z); o.w = packsplit(v.w);
    *(uint4*)(outp + i) = o;
}

// fused split: blocks 0-63 pack Wl1,Wr1,Wl2,Wr2 into g_ws;
// blocks 64-79 pack Wl3,Wr3 (40 cols, zero-padded to 64) into g_w3s.
__global__ void k_split_w(const float* __restrict__ w0, const float* __restrict__ w1,
                          const float* __restrict__ w2, const float* __restrict__ w3,
                          uint32_t* __restrict__ outp,
                          const float* __restrict__ w3a, const float* __restrict__ w3b,
                          uint32_t* __restrict__ out3) {
    if (blockIdx.x < 64) {
        int i = (blockIdx.x * 256 + threadIdx.x) * 4;
        int sel = i >> 14;
        int o4 = i & 16383;
        const float* w = (sel == 0) ? w0 : (sel == 1) ? w1 : (sel == 2) ? w2 : w3;
        float4 v = *(const float4*)(w + o4);
        uint4 o;
        o.x = packsplit(v.x); o.y = packsplit(v.y);
        o.z = packsplit(v.z); o.w = packsplit(v.w);
        *(uint4*)(outp + i) = o;
    } else {
        int g = (blockIdx.x - 64) * 256 + threadIdx.x;   // 0..4095
        int sel = g >> 11;
        int gg = g & 2047;
        int e0 = gg * 4;
        int k = e0 >> 6, c = e0 & 63;
        const float* w = sel ? w3b : w3a;
        uint32_t o[4];
        #pragma unroll
        for (int j = 0; j < 4; j++) {
            float v = (c + j < 40) ? w[k * 40 + c + j] : 0.f;
            o[j] = packsplit(v);
        }
        *(uint4*)(out3 + sel * 8192 + k * 64 + c) = make_uint4(o[0], o[1], o[2], o[3]);
    }
}

// ================= CSR construction ==========================================
__global__ void k_hist(const int* __restrict__ dst, int* __restrict__ deg) {
    int e = blockIdx.x * blockDim.x + threadIdx.x;
    if (e < N_EDGES) atomicAdd(&deg[dst[e]], 1);
}

__global__ __launch_bounds__(1024) void k_scan_part(
    const int* __restrict__ deg, int* __restrict__ off, int* __restrict__ bsum)
{
    __shared__ int sh[1024];
    int t = threadIdx.x;
    int i = blockIdx.x * 1024 + t;
    int v = (i < N_NODES) ? deg[i] : 0;
    sh[t] = v;
    __syncthreads();
    #pragma unroll
    for (int o = 1; o < 1024; o <<= 1) {
        int u = (t >= o) ? sh[t - o] : 0;
        __syncthreads();
        sh[t] += u;
        __syncthreads();
    }
    if (i < N_NODES) off[i] = sh[t] - v;
    if (t == 1023) bsum[blockIdx.x] = sh[t];
}

__global__ void k_scan_add(int* __restrict__ off, int* __restrict__ cur,
                           const int* __restrict__ bsum)
{
    __shared__ int base_sh;
    int i = blockIdx.x * blockDim.x + threadIdx.x;
    int b = (blockIdx.x * blockDim.x) >> 10;
    if (threadIdx.x == 0) {
        int s = 0;
        for (int j = 0; j < b; j++) s += bsum[j];
        base_sh = s;
    }
    __syncthreads();
    if (i >= N_NODES) return;
    int o = off[i] + base_sh;
    off[i] = o;
    cur[i] = o;
}

__global__ void k_scatter(const int* __restrict__ src, const int* __restrict__ dst,
                          int* __restrict__ cur, int* __restrict__ eidx)
{
    int e = blockIdx.x * blockDim.x + threadIdx.x;
    if (e >= N_EDGES) return;
    int p = atomicAdd(&cur[dst[e]], 1);
    eidx[p] = src[e];
}

// ================= tensor-core helpers =======================================
__device__ __forceinline__ uint32_t smem_u32(const void* p) {
    return (uint32_t)__cvta_generic_to_shared(p);
}
__device__ __forceinline__ void ldsm_x4(uint32_t& r0, uint32_t& r1, uint32_t& r2, uint32_t& r3, uint32_t addr) {
    asm volatile("ldmatrix.sync.aligned.m8n8.x4.shared.b16 {%0,%1,%2,%3},[%4];"
                 : "=r"(r0), "=r"(r1), "=r"(r2), "=r"(r3) : "r"(addr));
}
__device__ __forceinline__ void ldsm_x2_t(uint32_t& r0, uint32_t& r1, uint32_t addr) {
    asm volatile("ldmatrix.sync.aligned.m8n8.x2.trans.shared.b16 {%0,%1},[%2];"
                 : "=r"(r0), "=r"(r1) : "r"(addr));
}
__device__ __forceinline__ void mma_bf16c(float* d, const uint32_t* a, const uint32_t* b) {
    asm volatile("mma.sync.aligned.m16n8k16.row.col.f32.bf16.bf16.f32 "
                 "{%0,%1,%2,%3},{%4,%5,%6,%7},{%8,%9},{%0,%1,%2,%3};"
                 : "+f"(d[0]), "+f"(d[1]), "+f"(d[2]), "+f"(d[3])
                 : "r"(a[0]), "r"(a[1]), "r"(a[2]), "r"(a[3]), "r"(b[0]), "r"(b[1]));
}

// ================= TC dual GEMM (layers 1-2), fp16 output ===================
__global__ __launch_bounds__(256, 2) void k_gemm_tc2(
    const uint32_t* __restrict__ Ap,
    const uint32_t* __restrict__ W1p, const uint32_t* __restrict__ W2p,
    __half* __restrict__ C1, __half* __restrict__ C2, int M)
{
    __shared__ __nv_bfloat16 Ah[64][40];
    __shared__ __nv_bfloat16 Al[64][40];
    __shared__ __nv_bfloat16 Wh[32][264];
    __shared__ __nv_bfloat16 Wl[32][264];

    const int tid = threadIdx.x, lane = tid & 31, wid = tid >> 5;
    const int wm = wid & 1;
    const int wn = wid >> 1;
    const int r0 = blockIdx.x * 64;

    float d[2][8][4];
    #pragma unroll
    for (int i = 0; i < 2; i++)
        #pragma unroll
        for (int j = 0; j < 8; j++)
            #pragma unroll
            for (int k = 0; k < 4; k++) d[i][j][k] = 0.f;

    for (int kt = 0; kt < 4; kt++) {
        #pragma unroll
        for (int i = 0; i < 2; i++) {
            int idx = tid + i * 256;
            int row = idx >> 3, q = idx & 7;
            uint4 p = make_uint4(0u, 0u, 0u, 0u);
            if (r0 + row < M)
                p = *(const uint4*)(Ap + (size_t)(r0 + row) * 128 + kt * 32 + q * 4);
            uint2 hi, lo;
            hi.x = __byte_perm(p.x, p.y, 0x7632); hi.y = __byte_perm(p.z, p.w, 0x7632);
            lo.x = __byte_perm(p.x, p.y, 0x5410); lo.y = __byte_perm(p.z, p.w, 0x5410);
            *(uint2*)&Ah[row][q * 4] = hi;
            *(uint2*)&Al[row][q * 4] = lo;
        }
        #pragma unroll
        for (int i = 0; i < 8; i++) {
            int idx = tid + i * 256;
            int k = idx >> 6, q = idx & 63;
            uint4 p = (q < 32)
                ? *(const uint4*)(W1p + (size_t)(kt * 32 + k) * 128 + q * 4)
                : *(const uint4*)(W2p + (size_t)(kt * 32 + k) * 128 + (q - 32) * 4);
            uint2 hi, lo;
            hi.x = __byte_perm(p.x, p.y, 0x7632); hi.y = __byte_perm(p.z, p.w, 0x7632);
            lo.x = __byte_perm(p.x, p.y, 0x5410); lo.y = __byte_perm(p.z, p.w, 0x5410);
            *(uint2*)&Wh[k][q * 4] = hi;
            *(uint2*)&Wl[k][q * 4] = lo;
        }
        __syncthreads();

        #pragma unroll
        for (int ph = 0; ph < 3; ph++) {
            const __nv_bfloat16 (*Asm)[40]  = (ph == 1) ? Al : Ah;
            const __nv_bfloat16 (*Wsm)[264] = (ph == 2) ? Wl : Wh;
            #pragma unroll
            for (int k16 = 0; k16 < 2; k16++) {
                uint32_t af[2][4], bfr[8][2];
                #pragma unroll
                for (int mf = 0; mf < 2; mf++) {
                    uint32_t addr = smem_u32(
                        &Asm[wm * 32 + mf * 16 + (lane & 15)][k16 * 16 + (lane >> 4) * 8]);
                    ldsm_x4(af[mf][0], af[mf][1], af[mf][2], af[mf][3], addr);
                }
                #pragma unroll
                for (int nf = 0; nf < 8; nf++) {
                    uint32_t addr = smem_u32(
                        &Wsm[k16 * 16 + (lane & 15)][wn * 64 + nf * 8]);
                    ldsm_x2_t(bfr[nf][0], bfr[nf][1], addr);
                }
                #pragma unroll
                for (int mf = 0; mf < 2; mf++)
                    #pragma unroll
                    for (int nf = 0; nf < 8; nf++)
                        mma_bf16c(d[mf][nf], af[mf], bfr[nf]);
            }
        }
        __syncthreads();
    }

    const int g = lane >> 2, t = lane & 3;
    __half* Cp = (wn < 2) ? C1 : C2;
    int cbase = (wn < 2) ? wn * 64 : (wn - 2) * 64;
    #pragma unroll
    for (int mf = 0; mf < 2; mf++) {
        #pragma unroll
        for (int nf = 0; nf < 8; nf++) {
            int row0 = r0 + wm * 32 + mf * 16 + g;
            int col = cbase + nf * 8 + t * 2;
            if (row0 < M)
                *(__half2*)(Cp + (size_t)row0 * 128 + col) =
                    __floats2half2_rn(d[mf][nf][0], d[mf][nf][1]);
            if (row0 + 8 < M)
                *(__half2*)(Cp + (size_t)(row0 + 8) * 128 + col) =
                    __floats2half2_rn(d[mf][nf][2], d[mf][nf][3]);
        }
    }
}

// ================= TC dual GEMM layer 3 (N=40 padded to 64, fp32 out) =======
// W3p = packed splits [2][128][64]; C1/C2 are [M,40] fp32.
__global__ __launch_bounds__(256, 2) void k_gemm_tc3(
    const uint32_t* __restrict__ Ap, const uint32_t* __restrict__ W3p,
    float* __restrict__ C1, float* __restrict__ C2, int M)
{
    __shared__ __nv_bfloat16 Ah[64][40];
    __shared__ __nv_bfloat16 Al[64][40];
    __shared__ __nv_bfloat16 Wh[32][136];
    __shared__ __nv_bfloat16 Wl[32][136];

    const int tid = threadIdx.x, lane = tid & 31, wid = tid >> 5;
    const int wm = wid & 1;
    const int wn = wid >> 1;       // 32-col group within combined 128
    const int r0 = blockIdx.x * 64;

    float d[2][4][4];
    #pragma unroll
    for (int i = 0; i < 2; i++)
        #pragma unroll
        for (int j = 0; j < 4; j++)
            #pragma unroll
            for (int k = 0; k < 4; k++) d[i][j][k] = 0.f;

    for (int kt = 0; kt < 4; kt++) {
        #pragma unroll
        for (int i = 0; i < 2; i++) {
            int idx = tid + i * 256;
            int row = idx >> 3, q = idx & 7;
            uint4 p = make_uint4(0u, 0u, 0u, 0u);
            if (r0 + row < M)
                p = *(const uint4*)(Ap + (size_t)(r0 + row) * 128 + kt * 32 + q * 4);
            uint2 hi, lo;
            hi.x = __byte_perm(p.x, p.y, 0x7632); hi.y = __byte_perm(p.z, p.w, 0x7632);
            lo.x = __byte_perm(p.x, p.y, 0x5410); lo.y = __byte_perm(p.z, p.w, 0x5410);
            *(uint2*)&Ah[row][q * 4] = hi;
            *(uint2*)&Al[row][q * 4] = lo;
        }
        // W tile: 32 k x 128 combined cols (2x64) -> 1024 uint4, 4/thread
        #pragma unroll
        for (int i = 0; i < 4; i++) {
            int idx = tid + i * 256;
            int k = idx >> 5, q = idx & 31;
            const uint32_t* src = W3p + ((q >= 16) ? 8192 : 0)
                                + (size_t)(kt * 32 + k) * 64 + (q & 15) * 4;
            uint4 p = *(const uint4*)src;
            uint2 hi, lo;
            hi.x = __byte_perm(p.x, p.y, 0x7632); hi.y = __byte_perm(p.z, p.w, 0x7632);
            lo.x = __byte_perm(p.x, p.y, 0x5410); lo.y = __byte_perm(p.z, p.w, 0x5410);
            *(uint2*)&Wh[k][q * 4] = hi;
            *(uint2*)&Wl[k][q * 4] = lo;
        }
        __syncthreads();

        #pragma unroll
        for (int ph = 0; ph < 3; ph++) {
            const __nv_bfloat16 (*Asm)[40]  = (ph == 1) ? Al : Ah;
            const __nv_bfloat16 (*Wsm)[136] = (ph == 2) ? Wl : Wh;
            #pragma unroll
            for (int k16 = 0; k16 < 2; k16++) {
                uint32_t af[2][4], bfr[4][2];
                #pragma unroll
                for (int mf = 0; mf < 2; mf++) {
                    uint32_t addr = smem_u32(
                        &Asm[wm * 32 + mf * 16 + (lane & 15)][k16 * 16 + (lane >> 4) * 8]);
                    ldsm_x4(af[mf][0], af[mf][1], af[mf][2], af[mf][3], addr);
                }
                #pragma unroll
                for (int nf = 0; nf < 4; nf++) {
                    uint32_t addr = smem_u32(
                        &Wsm[k16 * 16 + (lane & 15)][wn * 32 + nf * 8]);
                    ldsm_x2_t(bfr[nf][0], bfr[nf][1], addr);
                }
                #pragma unroll
                for (int mf = 0; mf < 2; mf++)
                    #pragma unroll
                    for (int nf = 0; nf < 4; nf++)
                        mma_bf16c(d[mf][nf], af[mf], bfr[nf]);
            }
        }
        __syncthreads();
    }

    const int g = lane >> 2, t = lane & 3;
    float* Cp = (wn < 2) ? C1 : C2;
    int cbase = (wn & 1) * 32;
    #pragma unroll
    for (int mf = 0; mf < 2; mf++) {
        #pragma unroll
        for (int nf = 0; nf < 4; nf++) {
            int row0 = r0 + wm * 32 + mf * 16 + g;
            int col = cbase + nf * 8 + t * 2;
            if (col >= 40) continue;
            if (row0 < M)
                *(float2*)(Cp + (size_t)row0 * 40 + col) = make_float2(d[mf][nf][0], d[mf][nf][1]);
            if (row0 + 8 < M)
                *(float2*)(Cp + (size_t)(row0 + 8) * 40 + col) = make_float2(d[mf][nf][2], d[mf][nf][3]);
        }
    }
}

// ================= node aggregation (H=4, F=32), half2 math, 2 edges/warp ===
__global__ __launch_bounds__(256) void k_node_h4(
    const uint4* __restrict__ glh, const uint4* __restrict__ grh,
    const float* __restrict__ att,
    const int* __restrict__ off, const int* __restrict__ deg,
    const int* __restrict__ eidx, uint4* __restrict__ houtp, int mode)
{
    int n = blockIdx.x * 8 + (threadIdx.x >> 5);
    if (n >= N_NODES) return;
    int lane = threadIdx.x & 31;
    int sub = lane >> 4;
    int ll = lane & 15;

    uint4 braw = grh[(size_t)n * 16 + ll];
    __half2 b2[4];
    b2[0] = *(__half2*)&braw.x; b2[1] = *(__half2*)&braw.y;
    b2[2] = *(__half2*)&braw.z; b2[3] = *(__half2*)&braw.w;

    float4 t0 = __ldg((const float4*)att + 2 * ll);
    float4 t1 = __ldg((const float4*)att + 2 * ll + 1);
    __half2 t2[4];
    t2[0] = __floats2half2_rn(t0.x, t0.y); t2[1] = __floats2half2_rn(t0.z, t0.w);
    t2[2] = __floats2half2_rn(t1.x, t1.y); t2[3] = __floats2half2_rn(t1.z, t1.w);

    const __half2 slope2 = __floats2half2_rn(SLOPE, SLOPE);

    float f[8];
    #pragma unroll
    for (int i = 0; i < 8; i++) f[i] = 0.f;
    float dw = 0.f;

    int start = off[n], cnt = deg[n];
    for (int base = 0; base < cnt; base += 32) {
        int rem = cnt - base;
        int m = rem < 32 ? rem : 32;
        int eld = (lane < m) ? __ldg(&eidx[start + base + lane]) : 0;
        int hm = (m + 1) >> 1;
        for (int j = 0; j < hm; j++) {
            int idx = 2 * j + sub;
            int s = __shfl_sync(0xffffffffu, eld, idx);
            uint4 araw = __ldg(&glh[(size_t)s * 16 + ll]);
            __half2 a2[4];
            a2[0] = *(__half2*)&araw.x; a2[1] = *(__half2*)&araw.y;
            a2[2] = *(__half2*)&araw.z; a2[3] = *(__half2*)&araw.w;

            __half2 acc = __floats2half2_rn(0.f, 0.f);
            #pragma unroll
            for (int i = 0; i < 4; i++) {
                __half2 s2 = __hadd2(a2[i], b2[i]);
                __half2 e2 = __hmax2(s2, __hmul2(s2, slope2));
                acc = __hfma2(e2, t2[i], acc);
            }
            float2 pf = __half22float2(acc);
            float p = pf.x + pf.y;
            p += __shfl_xor_sync(0xffffffffu, p, 2);
            p += __shfl_xor_sync(0xffffffffu, p, 1);
            float w = (idx < m) ? __expf(p) : 0.f;

            #pragma unroll
            for (int i = 0; i < 4; i++) {
                float2 af = __half22float2(a2[i]);
                f[2 * i]     += w * af.x;
                f[2 * i + 1] += w * af.y;
            }
            dw += w;
        }
    }

    #pragma unroll
    for (int i = 0; i < 8; i++) f[i] += __shfl_xor_sync(0xffffffffu, f[i], 16);
    dw += __shfl_xor_sync(0xffffffffu, dw, 16);

    if (sub == 0) {
        float inv = 1.0f / (dw + 1e-16f);
        uint32_t o[8];
        #pragma unroll
        for (int i = 0; i < 8; i++) {
            float v = f[i] * inv;
            if (mode == 1) v = v > 0.f ? v : expm1f(v);
            else           v = fmaxf(v, 0.f);
            o[i] = packsplit(v);
        }
        houtp[(size_t)n * 32 + 2 * ll]     = make_uint4(o[0], o[1], o[2], o[3]);
        houtp[(size_t)n * 32 + 2 * ll + 1] = make_uint4(o[4], o[5], o[6], o[7]);
    }
}

// ================= node layer 3 + log_softmax (H=1, F=40, fp32) =============
// warp per node; two 16-lane halves process alternate edges of the SAME node
// -> uniform trip count, fully converged, full-mask shuffles.
__global__ __launch_bounds__(256) void k_node_h1_lsm(
    const float4* __restrict__ gl4, const float4* __restrict__ gr4,
    const float* __restrict__ att,
    const int* __restrict__ off, const int* __restrict__ deg,
    const int* __restrict__ eidx, float* __restrict__ out)
{
    int n = blockIdx.x * 8 + (threadIdx.x >> 5);
    if (n >= N_NODES) return;
    int lane = threadIdx.x & 31;
    int sub = lane >> 4;
    int ll = lane & 15;

    float4 b = make_float4(0.f, 0.f, 0.f, 0.f), t = b;
    if (ll < 10) {
        b = gr4[(size_t)n * 10 + ll];
        t = __ldg(&((const float4*)att)[ll]);
    }

    float ax = 0.f, ay = 0.f, az = 0.f, aw = 0.f, dw = 0.f;

    int start = off[n], cnt = deg[n];
    for (int base = 0; base < cnt; base += 32) {
        int rem = cnt - base;
        int m = rem < 32 ? rem : 32;
        int eld = (lane < m) ? __ldg(&eidx[start + base + lane]) : 0;
        int hm = (m + 1) >> 1;
        for (int j = 0; j < hm; j++) {
            int idx = 2 * j + sub;
            int s = __shfl_sync(0xffffffffu, eld, idx);
            float4 a = make_float4(0.f, 0.f, 0.f, 0.f);
            float p = 0.f;
            if (ll < 10) {
                a = __ldg(&gl4[(size_t)s * 10 + ll]);
                float vx = a.x + b.x; vx = vx > 0.f ? vx : SLOPE * vx;
                float vy = a.y + b.y; vy = vy > 0.f ? vy : SLOPE * vy;
                float vz = a.z + b.z; vz = vz > 0.f ? vz : SLOPE * vz;
                float vw = a.w + b.w; vw = vw > 0.f ? vw : SLOPE * vw;
                p = vx * t.x + vy * t.y + vz * t.z + vw * t.w;
            }
            p += __shfl_xor_sync(0xffffffffu, p, 8, 16);
            p += __shfl_xor_sync(0xffffffffu, p, 4, 16);
            p += __shfl_xor_sync(0xffffffffu, p, 2, 16);
            p += __shfl_xor_sync(0xffffffffu, p, 1, 16);
            float w = (idx < m) ? __expf(p) : 0.f;
            ax += w * a.x; ay += w * a.y; az += w * a.z; aw += w * a.w;
            dw += w;
        }
    }

    // combine halves (result identical in both halves after xor-16)
    ax += __shfl_xor_sync(0xffffffffu, ax, 16);
    ay += __shfl_xor_sync(0xffffffffu, ay, 16);
    az += __shfl_xor_sync(0xffffffffu, az, 16);
    aw += __shfl_xor_sync(0xffffffffu, aw, 16);
    dw += __shfl_xor_sync(0xffffffffu, dw, 16);

    float inv = 1.0f / (dw + 1e-16f);
    float4 v = make_float4(ax * inv, ay * inv, az * inv, aw * inv);

    float mx = (ll < 10) ? fmaxf(fmaxf(v.x, v.y), fmaxf(v.z, v.w)) : -FLT_MAX;
    #pragma unroll
    for (int o = 8; o > 0; o >>= 1) mx = fmaxf(mx, __shfl_xor_sync(0xffffffffu, mx, o, 16));
    float ss = (ll < 10)
        ? (expf(v.x - mx) + expf(v.y - mx) + expf(v.z - mx) + expf(v.w - mx)) : 0.f;
    #pragma unroll
    for (int o = 8; o > 0; o >>= 1) ss += __shfl_xor_sync(0xffffffffu, ss, o, 16);
    float lse = mx + logf(ss);
    if (sub == 0 && ll < 10) {
        float4 r = make_float4(v.x - lse, v.y - lse, v.z - lse, v.w - lse);
        *(float4*)(out + (size_t)n * 40 + 4 * ll) = r;
    }
}

// ---------------- host -------------------------------------------------------
extern "C" void kernel_launch(void* const* d_in, const int* in_sizes, int n_in,
                              void* d_out, int out_size)
{
    const float* x    = (const float*)d_in[0];
    const float* Wl1  = (const float*)d_in[1];
    const float* Wr1  = (const float*)d_in[2];
    const float* att1 = (const float*)d_in[3];
    const float* Wl2  = (const float*)d_in[4];
    const float* Wr2  = (const float*)d_in[5];
    const float* att2 = (const float*)d_in[6];
    const float* Wl3  = (const float*)d_in[7];
    const float* Wr3  = (const float*)d_in[8];
    const float* att3 = (const float*)d_in[9];
    const int*   ei   = (const int*)d_in[10];
    const int* src = ei;
    const int* dst = ei + N_EDGES;
    float* out = (float*)d_out;

    float *gl, *gr;
    uint32_t *xs, *hs, *ws, *w3s;
    int *deg, *off, *cur, *bsum, *eidx;
    cudaGetSymbolAddress((void**)&gl,   g_gl);
    cudaGetSymbolAddress((void**)&gr,   g_gr);
    cudaGetSymbolAddress((void**)&xs,   g_xs);
    cudaGetSymbolAddress((void**)&hs,   g_hs);
    cudaGetSymbolAddress((void**)&ws,   g_ws);
    cudaGetSymbolAddress((void**)&w3s,  g_w3s);
    cudaGetSymbolAddress((void**)&deg,  g_deg);
    cudaGetSymbolAddress((void**)&off,  g_off);
    cudaGetSymbolAddress((void**)&cur,  g_cur);
    cudaGetSymbolAddress((void**)&bsum, g_bsum);
    cudaGetSymbolAddress((void**)&eidx, g_eidx);

    __half* glh = (__half*)gl;
    __half* grh = (__half*)gr;

    const int GB = (N_NODES + 63) / 64;
    const int NB = (N_NODES + 7) / 8;
    const int NSCAN = (N_NODES + 1023) / 1024;

    // splits + CSR front
    k_split_w<<<80, 256>>>(Wl1, Wr1, Wl2, Wr2, ws, Wl3, Wr3, w3s);
    k_split<<<(N_NODES * 128 / 4 + 255) / 256, 256>>>(x, xs, N_NODES * 128);
    cudaMemsetAsync(deg, 0, N_NODES * sizeof(int));
    k_hist<<<(N_EDGES + 255) / 256, 256>>>(dst, deg);
    k_scan_part<<<NSCAN, 1024>>>(deg, off, bsum);
    // layer-1 GEMM (independent of CSR)
    k_gemm_tc2<<<GB, 256>>>(xs, ws + 0 * 16384, ws + 1 * 16384, glh, grh, N_NODES);
    // CSR back
    k_scan_add<<<(N_NODES + 255) / 256, 256>>>(off, cur, bsum);
    k_scatter<<<(N_EDGES + 255) / 256, 256>>>(src, dst, cur, eidx);

    // ---- Layer 1 aggregate ----
    k_node_h4<<<NB, 256>>>((const uint4*)glh, (const uint4*)grh, att1,
                           off, deg, eidx, (uint4*)hs, 1);
    // ---- Layer 2 ----
    k_gemm_tc2<<<GB, 256>>>(hs, ws + 2 * 16384, ws + 3 * 16384, glh, grh, N_NODES);
    k_node_h4<<<NB, 256>>>((const uint4*)glh, (const uint4*)grh, att2,
                           off, deg, eidx, (uint4*)hs, 2);
    // ---- Layer 3 (TC GEMM, fp32 out; fused aggregate + log_softmax) ----
    k_gemm_tc3<<<GB, 256>>>(hs, w3s, gl, gr, N_NODES);
    k_node_h1_lsm<<<NB, 256>>>((const float4*)gl, (const float4*)gr, att3,
                               off, deg, eidx, out);
}

// round 12
// speedup vs baseline: 3.8753x; 1.0580x over previous
#include <cuda_runtime.h>
#include <cuda_bf16.h>
#include <cuda_fp16.h>
#include <math.h>
#include <float.h>
#include <stdint.h>

#define N_NODES 50000
#define N_EDGES 800000
#define SLOPE 0.2f

// ---------------- scratch (device globals; no allocation allowed) ----------
__device__ float    g_gl[N_NODES * 128];   // fp16 view (layers 1-2) / fp32 [N,40] (layer 3)
__device__ float    g_gr[N_NODES * 128];
__device__ uint32_t g_hs[N_NODES * 128];   // packed split of hidden h
__device__ uint32_t g_ws[4 * 16384];       // packed splits of Wl1,Wr1,Wl2,Wr2
__device__ uint32_t g_w3s[2 * 8192];       // packed splits of Wl3,Wr3 padded [128,64]
__device__ int      g_deg[N_NODES];
__device__ int      g_off[N_NODES];
__device__ int      g_cur[N_NODES];
__device__ int      g_bsum[64];
__device__ int      g_eidx[N_EDGES];

// ---- bf16 hi/lo split pack -------------------------------------------------
__device__ __forceinline__ uint32_t packsplit(float x) {
    __nv_bfloat16 h = __float2bfloat16(x);
    __nv_bfloat16 l = __float2bfloat16(x - __bfloat162float(h));
    return ((uint32_t)__bfloat16_as_ushort(h) << 16) | (uint32_t)__bfloat16_as_ushort(l);
}

// fused split: blocks 0-63 pack Wl1,Wr1,Wl2,Wr2 into g_ws;
// blocks 64-79 pack Wl3,Wr3 (40 cols, zero-padded to 64) into g_w3s.
__global__ void k_split_w(const float* __restrict__ w0, const float* __restrict__ w1,
                          const float* __restrict__ w2, const float* __restrict__ w3,
                          uint32_t* __restrict__ outp,
                          const float* __restrict__ w3a, const float* __restrict__ w3b,
                          uint32_t* __restrict__ out3) {
    if (blockIdx.x < 64) {
        int i = (blockIdx.x * 256 + threadIdx.x) * 4;
        int sel = i >> 14;
        int o4 = i & 16383;
        const float* w = (sel == 0) ? w0 : (sel == 1) ? w1 : (sel == 2) ? w2 : w3;
        float4 v = *(const float4*)(w + o4);
        uint4 o;
        o.x = packsplit(v.x); o.y = packsplit(v.y);
        o.z = packsplit(v.z); o.w = packsplit(v.w);
        *(uint4*)(outp + i) = o;
    } else {
        int g = (blockIdx.x - 64) * 256 + threadIdx.x;   // 0..4095
        int sel = g >> 11;
        int gg = g & 2047;
        int e0 = gg * 4;
        int k = e0 >> 6, c = e0 & 63;
        const float* w = sel ? w3b : w3a;
        uint32_t o[4];
        #pragma unroll
        for (int j = 0; j < 4; j++) {
            float v = (c + j < 40) ? w[k * 40 + c + j] : 0.f;
            o[j] = packsplit(v);
        }
        *(uint4*)(out3 + sel * 8192 + k * 64 + c) = make_uint4(o[0], o[1], o[2], o[3]);
    }
}

// ================= CSR construction ==========================================
__global__ void k_hist(const int* __restrict__ dst, int* __restrict__ deg) {
    int e = blockIdx.x * blockDim.x + threadIdx.x;
    if (e < N_EDGES) atomicAdd(&deg[dst[e]], 1);
}

__global__ __launch_bounds__(1024) void k_scan_part(
    const int* __restrict__ deg, int* __restrict__ off, int* __restrict__ bsum)
{
    __shared__ int sh[1024];
    int t = threadIdx.x;
    int i = blockIdx.x * 1024 + t;
    int v = (i < N_NODES) ? deg[i] : 0;
    sh[t] = v;
    __syncthreads();
    #pragma unroll
    for (int o = 1; o < 1024; o <<= 1) {
        int u = (t >= o) ? sh[t - o] : 0;
        __syncthreads();
        sh[t] += u;
        __syncthreads();
    }
    if (i < N_NODES) off[i] = sh[t] - v;
    if (t == 1023) bsum[blockIdx.x] = sh[t];
}

__global__ void k_scan_add(int* __restrict__ off, int* __restrict__ cur,
                           const int* __restrict__ bsum)
{
    __shared__ int base_sh;
    int i = blockIdx.x * blockDim.x + threadIdx.x;
    int b = (blockIdx.x * blockDim.x) >> 10;
    if (threadIdx.x == 0) {
        int s = 0;
        for (int j = 0; j < b; j++) s += bsum[j];
        base_sh = s;
    }
    __syncthreads();
    if (i >= N_NODES) return;
    int o = off[i] + base_sh;
    off[i] = o;
    cur[i] = o;
}

__global__ void k_scatter(const int* __restrict__ src, const int* __restrict__ dst,
                          int* __restrict__ cur, int* __restrict__ eidx)
{
    int e = blockIdx.x * blockDim.x + threadIdx.x;
    if (e >= N_EDGES) return;
    int p = atomicAdd(&cur[dst[e]], 1);
    eidx[p] = src[e];
}

// ================= tensor-core helpers =======================================
__device__ __forceinline__ uint32_t smem_u32(const void* p) {
    return (uint32_t)__cvta_generic_to_shared(p);
}
__device__ __forceinline__ void ldsm_x4(uint32_t& r0, uint32_t& r1, uint32_t& r2, uint32_t& r3, uint32_t addr) {
    asm volatile("ldmatrix.sync.aligned.m8n8.x4.shared.b16 {%0,%1,%2,%3},[%4];"
                 : "=r"(r0), "=r"(r1), "=r"(r2), "=r"(r3) : "r"(addr));
}
__device__ __forceinline__ void ldsm_x2_t(uint32_t& r0, uint32_t& r1, uint32_t addr) {
    asm volatile("ldmatrix.sync.aligned.m8n8.x2.trans.shared.b16 {%0,%1},[%2];"
                 : "=r"(r0), "=r"(r1) : "r"(addr));
}
__device__ __forceinline__ void mma_bf16c(float* d, const uint32_t* a, const uint32_t* b) {
    asm volatile("mma.sync.aligned.m16n8k16.row.col.f32.bf16.bf16.f32 "
                 "{%0,%1,%2,%3},{%4,%5,%6,%7},{%8,%9},{%0,%1,%2,%3};"
                 : "+f"(d[0]), "+f"(d[1]), "+f"(d[2]), "+f"(d[3])
                 : "r"(a[0]), "r"(a[1]), "r"(a[2]), "r"(a[3]), "r"(b[0]), "r"(b[1]));
}

// ================= TC dual GEMM (layers 1-2), fp16 output ===================
// RAW=true: A is raw fp32 [M,128], split in-register (layer 1, deletes k_split).
// RAW=false: A is pre-packed hi/lo uint32 (layer 2, written by k_node_h4).
template <bool RAW>
__global__ __launch_bounds__(256, 2) void k_gemm_tc2(
    const uint32_t* __restrict__ Ap, const float* __restrict__ Araw,
    const uint32_t* __restrict__ W1p, const uint32_t* __restrict__ W2p,
    __half* __restrict__ C1, __half* __restrict__ C2, int M)
{
    __shared__ __nv_bfloat16 Ah[64][40];
    __shared__ __nv_bfloat16 Al[64][40];
    __shared__ __nv_bfloat16 Wh[32][264];
    __shared__ __nv_bfloat16 Wl[32][264];

    const int tid = threadIdx.x, lane = tid & 31, wid = tid >> 5;
    const int wm = wid & 1;
    const int wn = wid >> 1;
    const int r0 = blockIdx.x * 64;

    float d[2][8][4];
    #pragma unroll
    for (int i = 0; i < 2; i++)
        #pragma unroll
        for (int j = 0; j < 8; j++)
            #pragma unroll
            for (int k = 0; k < 4; k++) d[i][j][k] = 0.f;

    for (int kt = 0; kt < 4; kt++) {
        #pragma unroll
        for (int i = 0; i < 2; i++) {
            int idx = tid + i * 256;
            int row = idx >> 3, q = idx & 7;
            if (RAW) {
                float4 v = make_float4(0.f, 0.f, 0.f, 0.f);
                if (r0 + row < M)
                    v = *(const float4*)(Araw + (size_t)(r0 + row) * 128 + kt * 32 + q * 4);
                float ar[4] = {v.x, v.y, v.z, v.w};
                __nv_bfloat16 h[4], lo[4];
                #pragma unroll
                for (int j = 0; j < 4; j++) {
                    h[j] = __float2bfloat16(ar[j]);
                    lo[j] = __float2bfloat16(ar[j] - __bfloat162float(h[j]));
                }
                *(uint2*)&Ah[row][q * 4] = *(uint2*)h;
                *(uint2*)&Al[row][q * 4] = *(uint2*)lo;
            } else {
                uint4 p = make_uint4(0u, 0u, 0u, 0u);
                if (r0 + row < M)
                    p = *(const uint4*)(Ap + (size_t)(r0 + row) * 128 + kt * 32 + q * 4);
                uint2 hi, lo;
                hi.x = __byte_perm(p.x, p.y, 0x7632); hi.y = __byte_perm(p.z, p.w, 0x7632);
                lo.x = __byte_perm(p.x, p.y, 0x5410); lo.y = __byte_perm(p.z, p.w, 0x5410);
                *(uint2*)&Ah[row][q * 4] = hi;
                *(uint2*)&Al[row][q * 4] = lo;
            }
        }
        #pragma unroll
        for (int i = 0; i < 8; i++) {
            int idx = tid + i * 256;
            int k = idx >> 6, q = idx & 63;
            uint4 p = (q < 32)
                ? *(const uint4*)(W1p + (size_t)(kt * 32 + k) * 128 + q * 4)
                : *(const uint4*)(W2p + (size_t)(kt * 32 + k) * 128 + (q - 32) * 4);
            uint2 hi, lo;
            hi.x = __byte_perm(p.x, p.y, 0x7632); hi.y = __byte_perm(p.z, p.w, 0x7632);
            lo.x = __byte_perm(p.x, p.y, 0x5410); lo.y = __byte_perm(p.z, p.w, 0x5410);
            *(uint2*)&Wh[k][q * 4] = hi;
            *(uint2*)&Wl[k][q * 4] = lo;
        }
        __syncthreads();

        #pragma unroll
        for (int ph = 0; ph < 3; ph++) {
            const __nv_bfloat16 (*Asm)[40]  = (ph == 1) ? Al : Ah;
            const __nv_bfloat16 (*Wsm)[264] = (ph == 2) ? Wl : Wh;
            #pragma unroll
            for (int k16 = 0; k16 < 2; k16++) {
                uint32_t af[2][4], bfr[8][2];
                #pragma unroll
                for (int mf = 0; mf < 2; mf++) {
                    uint32_t addr = smem_u32(
                        &Asm[wm * 32 + mf * 16 + (lane & 15)][k16 * 16 + (lane >> 4) * 8]);
                    ldsm_x4(af[mf][0], af[mf][1], af[mf][2], af[mf][3], addr);
                }
                #pragma unroll
                for (int nf = 0; nf < 8; nf++) {
                    uint32_t addr = smem_u32(
                        &Wsm[k16 * 16 + (lane & 15)][wn * 64 + nf * 8]);
                    ldsm_x2_t(bfr[nf][0], bfr[nf][1], addr);
                }
                #pragma unroll
                for (int mf = 0; mf < 2; mf++)
                    #pragma unroll
                    for (int nf = 0; nf < 8; nf++)
                        mma_bf16c(d[mf][nf], af[mf], bfr[nf]);
            }
        }
        __syncthreads();
    }

    const int g = lane >> 2, t = lane & 3;
    __half* Cp = (wn < 2) ? C1 : C2;
    int cbase = (wn < 2) ? wn * 64 : (wn - 2) * 64;
    #pragma unroll
    for (int mf = 0; mf < 2; mf++) {
        #pragma unroll
        for (int nf = 0; nf < 8; nf++) {
            int row0 = r0 + wm * 32 + mf * 16 + g;
            int col = cbase + nf * 8 + t * 2;
            if (row0 < M)
                *(__half2*)(Cp + (size_t)row0 * 128 + col) =
                    __floats2half2_rn(d[mf][nf][0], d[mf][nf][1]);
            if (row0 + 8 < M)
                *(__half2*)(Cp + (size_t)(row0 + 8) * 128 + col) =
                    __floats2half2_rn(d[mf][nf][2], d[mf][nf][3]);
        }
    }
}

// ================= TC dual GEMM layer 3 (N=40 padded to 64, fp32 out) =======
__global__ __launch_bounds__(256, 2) void k_gemm_tc3(
    const uint32_t* __restrict__ Ap, const uint32_t* __restrict__ W3p,
    float* __restrict__ C1, float* __restrict__ C2, int M)
{
    __shared__ __nv_bfloat16 Ah[64][40];
    __shared__ __nv_bfloat16 Al[64][40];
    __shared__ __nv_bfloat16 Wh[32][136];
    __shared__ __nv_bfloat16 Wl[32][136];

    const int tid = threadIdx.x, lane = tid & 31, wid = tid >> 5;
    const int wm = wid & 1;
    const int wn = wid >> 1;
    const int r0 = blockIdx.x * 64;

    float d[2][4][4];
    #pragma unroll
    for (int i = 0; i < 2; i++)
        #pragma unroll
        for (int j = 0; j < 4; j++)
            #pragma unroll
            for (int k = 0; k < 4; k++) d[i][j][k] = 0.f;

    for (int kt = 0; kt < 4; kt++) {
        #pragma unroll
        for (int i = 0; i < 2; i++) {
            int idx = tid + i * 256;
            int row = idx >> 3, q = idx & 7;
            uint4 p = make_uint4(0u, 0u, 0u, 0u);
            if (r0 + row < M)
                p = *(const uint4*)(Ap + (size_t)(r0 + row) * 128 + kt * 32 + q * 4);
            uint2 hi, lo;
            hi.x = __byte_perm(p.x, p.y, 0x7632); hi.y = __byte_perm(p.z, p.w, 0x7632);
            lo.x = __byte_perm(p.x, p.y, 0x5410); lo.y = __byte_perm(p.z, p.w, 0x5410);
            *(uint2*)&Ah[row][q * 4] = hi;
            *(uint2*)&Al[row][q * 4] = lo;
        }
        #pragma unroll
        for (int i = 0; i < 4; i++) {
            int idx = tid + i * 256;
            int k = idx >> 5, q = idx & 31;
            const uint32_t* src = W3p + ((q >= 16) ? 8192 : 0)
                                + (size_t)(kt * 32 + k) * 64 + (q & 15) * 4;
            uint4 p = *(const uint4*)src;
            uint2 hi, lo;
            hi.x = __byte_perm(p.x, p.y, 0x7632); hi.y = __byte_perm(p.z, p.w, 0x7632);
            lo.x = __byte_perm(p.x, p.y, 0x5410); lo.y = __byte_perm(p.z, p.w, 0x5410);
            *(uint2*)&Wh[k][q * 4] = hi;
            *(uint2*)&Wl[k][q * 4] = lo;
        }
        __syncthreads();

        #pragma unroll
        for (int ph = 0; ph < 3; ph++) {
            const __nv_bfloat16 (*Asm)[40]  = (ph == 1) ? Al : Ah;
            const __nv_bfloat16 (*Wsm)[136] = (ph == 2) ? Wl : Wh;
            #pragma unroll
            for (int k16 = 0; k16 < 2; k16++) {
                uint32_t af[2][4], bfr[4][2];
                #pragma unroll
                for (int mf = 0; mf < 2; mf++) {
                    uint32_t addr = smem_u32(
                        &Asm[wm * 32 + mf * 16 + (lane & 15)][k16 * 16 + (lane >> 4) * 8]);
                    ldsm_x4(af[mf][0], af[mf][1], af[mf][2], af[mf][3], addr);
                }
                #pragma unroll
                for (int nf = 0; nf < 4; nf++) {
                    uint32_t addr = smem_u32(
                        &Wsm[k16 * 16 + (lane & 15)][wn * 32 + nf * 8]);
                    ldsm_x2_t(bfr[nf][0], bfr[nf][1], addr);
                }
                #pragma unroll
                for (int mf = 0; mf < 2; mf++)
                    #pragma unroll
                    for (int nf = 0; nf < 4; nf++)
                        mma_bf16c(d[mf][nf], af[mf], bfr[nf]);
            }
        }
        __syncthreads();
    }

    const int g = lane >> 2, t = lane & 3;
    float* Cp = (wn < 2) ? C1 : C2;
    int cbase = (wn & 1) * 32;
    #pragma unroll
    for (int mf = 0; mf < 2; mf++) {
        #pragma unroll
        for (int nf = 0; nf < 4; nf++) {
            int row0 = r0 + wm * 32 + mf * 16 + g;
            int col = cbase + nf * 8 + t * 2;
            if (col >= 40) continue;
            if (row0 < M)
                *(float2*)(Cp + (size_t)row0 * 40 + col) = make_float2(d[mf][nf][0], d[mf][nf][1]);
            if (row0 + 8 < M)
                *(float2*)(Cp + (size_t)(row0 + 8) * 40 + col) = make_float2(d[mf][nf][2], d[mf][nf][3]);
        }
    }
}

// ================= node aggregation (H=4, F=32), half2 math, 2 edges/warp ===
__global__ __launch_bounds__(256) void k_node_h4(
    const uint4* __restrict__ glh, const uint4* __restrict__ grh,
    const float* __restrict__ att,
    const int* __restrict__ off, const int* __restrict__ deg,
    const int* __restrict__ eidx, uint4* __restrict__ houtp, int mode)
{
    int n = blockIdx.x * 8 + (threadIdx.x >> 5);
    if (n >= N_NODES) return;
    int lane = threadIdx.x & 31;
    int sub = lane >> 4;
    int ll = lane & 15;

    uint4 braw = grh[(size_t)n * 16 + ll];
    __half2 b2[4];
    b2[0] = *(__half2*)&braw.x; b2[1] = *(__half2*)&braw.y;
    b2[2] = *(__half2*)&braw.z; b2[3] = *(__half2*)&braw.w;

    float4 t0 = __ldg((const float4*)att + 2 * ll);
    float4 t1 = __ldg((const float4*)att + 2 * ll + 1);
    __half2 t2[4];
    t2[0] = __floats2half2_rn(t0.x, t0.y); t2[1] = __floats2half2_rn(t0.z, t0.w);
    t2[2] = __floats2half2_rn(t1.x, t1.y); t2[3] = __floats2half2_rn(t1.z, t1.w);

    const __half2 slope2 = __floats2half2_rn(SLOPE, SLOPE);

    float f[8];
    #pragma unroll
    for (int i = 0; i < 8; i++) f[i] = 0.f;
    float dw = 0.f;

    int start = off[n], cnt = deg[n];
    for (int base = 0; base < cnt; base += 32) {
        int rem = cnt - base;
        int m = rem < 32 ? rem : 32;
        int eld = (lane < m) ? __ldg(&eidx[start + base + lane]) : 0;
        int hm = (m + 1) >> 1;
        for (int j = 0; j < hm; j++) {
            int idx = 2 * j + sub;
            int s = __shfl_sync(0xffffffffu, eld, idx);
            uint4 araw = __ldg(&glh[(size_t)s * 16 + ll]);
            __half2 a2[4];
            a2[0] = *(__half2*)&araw.x; a2[1] = *(__half2*)&araw.y;
            a2[2] = *(__half2*)&araw.z; a2[3] = *(__half2*)&araw.w;

            __half2 acc = __floats2half2_rn(0.f, 0.f);
            #pragma unroll
            for (int i = 0; i < 4; i++) {
                __half2 s2 = __hadd2(a2[i], b2[i]);
                __half2 e2 = __hmax2(s2, __hmul2(s2, slope2));
                acc = __hfma2(e2, t2[i], acc);
            }
            float2 pf = __half22float2(acc);
            float p = pf.x + pf.y;
            p += __shfl_xor_sync(0xffffffffu, p, 2);
            p += __shfl_xor_sync(0xffffffffu, p, 1);
            float w = (idx < m) ? __expf(p) : 0.f;

            #pragma unroll
            for (int i = 0; i < 4; i++) {
                float2 af = __half22float2(a2[i]);
                f[2 * i]     += w * af.x;
                f[2 * i + 1] += w * af.y;
            }
            dw += w;
        }
    }

    #pragma unroll
    for (int i = 0; i < 8; i++) f[i] += __shfl_xor_sync(0xffffffffu, f[i], 16);
    dw += __shfl_xor_sync(0xffffffffu, dw, 16);

    if (sub == 0) {
        float inv = 1.0f / (dw + 1e-16f);
        uint32_t o[8];
        #pragma unroll
        for (int i = 0; i < 8; i++) {
            float v = f[i] * inv;
            if (mode == 1) v = v > 0.f ? v : expm1f(v);
            else           v = fmaxf(v, 0.f);
            o[i] = packsplit(v);
        }
        houtp[(size_t)n * 32 + 2 * ll]     = make_uint4(o[0], o[1], o[2], o[3]);
        houtp[(size_t)n * 32 + 2 * ll + 1] = make_uint4(o[4], o[5], o[6], o[7]);
    }
}

// ================= node layer 3 + log_softmax (H=1, F=40, fp32) =============
__global__ __launch_bounds__(256) void k_node_h1_lsm(
    const float4* __restrict__ gl4, const float4* __restrict__ gr4,
    const float* __restrict__ att,
    const int* __restrict__ off, const int* __restrict__ deg,
    const int* __restrict__ eidx, float* __restrict__ out)
{
    int n = blockIdx.x * 8 + (threadIdx.x >> 5);
    if (n >= N_NODES) return;
    int lane = threadIdx.x & 31;
    int sub = lane >> 4;
    int ll = lane & 15;

    float4 b = make_float4(0.f, 0.f, 0.f, 0.f), t = b;
    if (ll < 10) {
        b = gr4[(size_t)n * 10 + ll];
        t = __ldg(&((const float4*)att)[ll]);
    }

    float ax = 0.f, ay = 0.f, az = 0.f, aw = 0.f, dw = 0.f;

    int start = off[n], cnt = deg[n];
    for (int base = 0; base < cnt; base += 32) {
        int rem = cnt - base;
        int m = rem < 32 ? rem : 32;
        int eld = (lane < m) ? __ldg(&eidx[start + base + lane]) : 0;
        int hm = (m + 1) >> 1;
        for (int j = 0; j < hm; j++) {
            int idx = 2 * j + sub;
            int s = __shfl_sync(0xffffffffu, eld, idx);
            float4 a = make_float4(0.f, 0.f, 0.f, 0.f);
            float p = 0.f;
            if (ll < 10) {
                a = __ldg(&gl4[(size_t)s * 10 + ll]);
                float vx = a.x + b.x; vx = vx > 0.f ? vx : SLOPE * vx;
                float vy = a.y + b.y; vy = vy > 0.f ? vy : SLOPE * vy;
                float vz = a.z + b.z; vz = vz > 0.f ? vz : SLOPE * vz;
                float vw = a.w + b.w; vw = vw > 0.f ? vw : SLOPE * vw;
                p = vx * t.x + vy * t.y + vz * t.z + vw * t.w;
            }
            p += __shfl_xor_sync(0xffffffffu, p, 8, 16);
            p += __shfl_xor_sync(0xffffffffu, p, 4, 16);
            p += __shfl_xor_sync(0xffffffffu, p, 2, 16);
            p += __shfl_xor_sync(0xffffffffu, p, 1, 16);
            float w = (idx < m) ? __expf(p) : 0.f;
            ax += w * a.x; ay += w * a.y; az += w * a.z; aw += w * a.w;
            dw += w;
        }
    }

    ax += __shfl_xor_sync(0xffffffffu, ax, 16);
    ay += __shfl_xor_sync(0xffffffffu, ay, 16);
    az += __shfl_xor_sync(0xffffffffu, az, 16);
    aw += __shfl_xor_sync(0xffffffffu, aw, 16);
    dw += __shfl_xor_sync(0xffffffffu, dw, 16);

    float inv = 1.0f / (dw + 1e-16f);
    float4 v = make_float4(ax * inv, ay * inv, az * inv, aw * inv);

    float mx = (ll < 10) ? fmaxf(fmaxf(v.x, v.y), fmaxf(v.z, v.w)) : -FLT_MAX;
    #pragma unroll
    for (int o = 8; o > 0; o >>= 1) mx = fmaxf(mx, __shfl_xor_sync(0xffffffffu, mx, o, 16));
    float ss = (ll < 10)
        ? (expf(v.x - mx) + expf(v.y - mx) + expf(v.z - mx) + expf(v.w - mx)) : 0.f;
    #pragma unroll
    for (int o = 8; o > 0; o >>= 1) ss += __shfl_xor_sync(0xffffffffu, ss, o, 16);
    float lse = mx + logf(ss);
    if (sub == 0 && ll < 10) {
        float4 r = make_float4(v.x - lse, v.y - lse, v.z - lse, v.w - lse);
        *(float4*)(out + (size_t)n * 40 + 4 * ll) = r;
    }
}

// ---------------- host -------------------------------------------------------
extern "C" void kernel_launch(void* const* d_in, const int* in_sizes, int n_in,
                              void* d_out, int out_size)
{
    const float* x    = (const float*)d_in[0];
    const float* Wl1  = (const float*)d_in[1];
    const float* Wr1  = (const float*)d_in[2];
    const float* att1 = (const float*)d_in[3];
    const float* Wl2  = (const float*)d_in[4];
    const float* Wr2  = (const float*)d_in[5];
    const float* att2 = (const float*)d_in[6];
    const float* Wl3  = (const float*)d_in[7];
    const float* Wr3  = (const float*)d_in[8];
    const float* att3 = (const float*)d_in[9];
    const int*   ei   = (const int*)d_in[10];
    const int* src = ei;
    const int* dst = ei + N_EDGES;
    float* out = (float*)d_out;

    float *gl, *gr;
    uint32_t *hs, *ws, *w3s;
    int *deg, *off, *cur, *bsum, *eidx;
    cudaGetSymbolAddress((void**)&gl,   g_gl);
    cudaGetSymbolAddress((void**)&gr,   g_gr);
    cudaGetSymbolAddress((void**)&hs,   g_hs);
    cudaGetSymbolAddress((void**)&ws,   g_ws);
    cudaGetSymbolAddress((void**)&w3s,  g_w3s);
    cudaGetSymbolAddress((void**)&deg,  g_deg);
    cudaGetSymbolAddress((void**)&off,  g_off);
    cudaGetSymbolAddress((void**)&cur,  g_cur);
    cudaGetSymbolAddress((void**)&bsum, g_bsum);
    cudaGetSymbolAddress((void**)&eidx, g_eidx);

    __half* glh = (__half*)gl;
    __half* grh = (__half*)gr;

    const int GB = (N_NODES + 63) / 64;
    const int NB = (N_NODES + 7) / 8;
    const int NSCAN = (N_NODES + 1023) / 1024;

    // one-time stream/event resources (resource creation only; captured work
    // is identical on every call)
    static cudaStream_t s2 = nullptr;
    static cudaEvent_t evFork = nullptr, evJoin = nullptr;
    if (!s2) {
        cudaStreamCreateWithFlags(&s2, cudaStreamNonBlocking);
        cudaEventCreateWithFlags(&evFork, cudaEventDisableTiming);
        cudaEventCreateWithFlags(&evJoin, cudaEventDisableTiming);
    }

    // ---- fork: CSR build on s2, concurrent with weight split + layer-1 GEMM
    cudaEventRecord(evFork, 0);
    cudaStreamWaitEvent(s2, evFork, 0);
    cudaMemsetAsync(deg, 0, N_NODES * sizeof(int), s2);
    k_hist<<<(N_EDGES + 255) / 256, 256, 0, s2>>>(dst, deg);
    k_scan_part<<<NSCAN, 1024, 0, s2>>>(deg, off, bsum);
    k_scan_add<<<(N_NODES + 255) / 256, 256, 0, s2>>>(off, cur, bsum);
    k_scatter<<<(N_EDGES + 255) / 256, 256, 0, s2>>>(src, dst, cur, eidx);
    cudaEventRecord(evJoin, s2);

    // main stream: weight splits + layer-1 GEMM (reads raw fp32 x directly)
    k_split_w<<<80, 256>>>(Wl1, Wr1, Wl2, Wr2, ws, Wl3, Wr3, w3s);
    k_gemm_tc2<true><<<GB, 256>>>(nullptr, x, ws + 0 * 16384, ws + 1 * 16384,
                                  glh, grh, N_NODES);
    cudaStreamWaitEvent(0, evJoin, 0);

    // ---- Layer 1 aggregate ----
    k_node_h4<<<NB, 256>>>((const uint4*)glh, (const uint4*)grh, att1,
                           off, deg, eidx, (uint4*)hs, 1);
    // ---- Layer 2 ----
    k_gemm_tc2<false><<<GB, 256>>>(hs, nullptr, ws + 2 * 16384, ws + 3 * 16384,
                                   glh, grh, N_NODES);
    k_node_h4<<<NB, 256>>>((const uint4*)glh, (const uint4*)grh, att2,
                           off, deg, eidx, (uint4*)hs, 2);
    // ---- Layer 3 (TC GEMM, fp32 out; fused aggregate + log_softmax) ----
    k_gemm_tc3<<<GB, 256>>>(hs, w3s, gl, gr, N_NODES);
    k_node_h1_lsm<<<NB, 256>>>((const float4*)gl, (const float4*)gr, att3,
                               off, deg, eidx, out);
}

// round 13
// speedup vs baseline: 4.1572x; 1.0727x over previous
#include <cuda_runtime.h>
#include <cuda_bf16.h>
#include <cuda_fp16.h>
#include <math.h>
#include <float.h>
#include <stdint.h>

#define N_NODES 50000
#define N_EDGES 800000
#define SLOPE 0.2f

// ---------------- scratch (device globals; no allocation allowed) ----------
__device__ float    g_gl[N_NODES * 128];   // fp16 view (layers 1-2) / fp32 [N,40] (layer 3)
__device__ float    g_gr[N_NODES * 128];
__device__ uint32_t g_hs[N_NODES * 128];   // packed split of hidden h
__device__ uint32_t g_ws[4 * 16384];       // packed splits of Wl1,Wr1,Wl2,Wr2
__device__ uint32_t g_w3s[2 * 8192];       // packed splits of Wl3,Wr3 padded [128,64]
__device__ int      g_deg[N_NODES];
__device__ int      g_off[N_NODES];
__device__ int      g_cur[N_NODES];
__device__ int      g_bsum[64];
__device__ int      g_eidx[N_EDGES];

// ---- bf16 hi/lo split pack -------------------------------------------------
__device__ __forceinline__ uint32_t packsplit(float x) {
    __nv_bfloat16 h = __float2bfloat16(x);
    __nv_bfloat16 l = __float2bfloat16(x - __bfloat162float(h));
    return ((uint32_t)__bfloat16_as_ushort(h) << 16) | (uint32_t)__bfloat16_as_ushort(l);
}

// fused split: blocks 0-63 pack Wl1,Wr1,Wl2,Wr2 into g_ws;
// blocks 64-79 pack Wl3,Wr3 (40 cols, zero-padded to 64) into g_w3s.
__global__ void k_split_w(const float* __restrict__ w0, const float* __restrict__ w1,
                          const float* __restrict__ w2, const float* __restrict__ w3,
                          uint32_t* __restrict__ outp,
                          const float* __restrict__ w3a, const float* __restrict__ w3b,
                          uint32_t* __restrict__ out3) {
    if (blockIdx.x < 64) {
        int i = (blockIdx.x * 256 + threadIdx.x) * 4;
        int sel = i >> 14;
        int o4 = i & 16383;
        const float* w = (sel == 0) ? w0 : (sel == 1) ? w1 : (sel == 2) ? w2 : w3;
        float4 v = *(const float4*)(w + o4);
        uint4 o;
        o.x = packsplit(v.x); o.y = packsplit(v.y);
        o.z = packsplit(v.z); o.w = packsplit(v.w);
        *(uint4*)(outp + i) = o;
    } else {
        int g = (blockIdx.x - 64) * 256 + threadIdx.x;   // 0..4095
        int sel = g >> 11;
        int gg = g & 2047;
        int e0 = gg * 4;
        int k = e0 >> 6, c = e0 & 63;
        const float* w = sel ? w3b : w3a;
        uint32_t o[4];
        #pragma unroll
        for (int j = 0; j < 4; j++) {
            float v = (c + j < 40) ? w[k * 40 + c + j] : 0.f;
            o[j] = packsplit(v);
        }
        *(uint4*)(out3 + sel * 8192 + k * 64 + c) = make_uint4(o[0], o[1], o[2], o[3]);
    }
}

// ================= CSR construction ==========================================
__global__ void k_hist(const int* __restrict__ dst, int* __restrict__ deg) {
    int e = blockIdx.x * blockDim.x + threadIdx.x;
    if (e < N_EDGES) atomicAdd(&deg[dst[e]], 1);
}

__global__ __launch_bounds__(1024) void k_scan_part(
    const int* __restrict__ deg, int* __restrict__ off, int* __restrict__ bsum)
{
    __shared__ int sh[1024];
    int t = threadIdx.x;
    int i = blockIdx.x * 1024 + t;
    int v = (i < N_NODES) ? deg[i] : 0;
    sh[t] = v;
    __syncthreads();
    #pragma unroll
    for (int o = 1; o < 1024; o <<= 1) {
        int u = (t >= o) ? sh[t - o] : 0;
        __syncthreads();
        sh[t] += u;
        __syncthreads();
    }
    if (i < N_NODES) off[i] = sh[t] - v;
    if (t == 1023) bsum[blockIdx.x] = sh[t];
}

__global__ void k_scan_add(int* __restrict__ off, int* __restrict__ cur,
                           const int* __restrict__ bsum)
{
    __shared__ int base_sh;
    int i = blockIdx.x * blockDim.x + threadIdx.x;
    int b = (blockIdx.x * blockDim.x) >> 10;
    if (threadIdx.x == 0) {
        int s = 0;
        for (int j = 0; j < b; j++) s += bsum[j];
        base_sh = s;
    }
    __syncthreads();
    if (i >= N_NODES) return;
    int o = off[i] + base_sh;
    off[i] = o;
    cur[i] = o;
}

__global__ void k_scatter(const int* __restrict__ src, const int* __restrict__ dst,
                          int* __restrict__ cur, int* __restrict__ eidx)
{
    int e = blockIdx.x * blockDim.x + threadIdx.x;
    if (e >= N_EDGES) return;
    int p = atomicAdd(&cur[dst[e]], 1);
    eidx[p] = src[e];
}

// ================= tensor-core helpers =======================================
__device__ __forceinline__ uint32_t smem_u32(const void* p) {
    return (uint32_t)__cvta_generic_to_shared(p);
}
__device__ __forceinline__ void ldsm_x4(uint32_t& r0, uint32_t& r1, uint32_t& r2, uint32_t& r3, uint32_t addr) {
    asm volatile("ldmatrix.sync.aligned.m8n8.x4.shared.b16 {%0,%1,%2,%3},[%4];"
                 : "=r"(r0), "=r"(r1), "=r"(r2), "=r"(r3) : "r"(addr));
}
__device__ __forceinline__ void ldsm_x2_t(uint32_t& r0, uint32_t& r1, uint32_t addr) {
    asm volatile("ldmatrix.sync.aligned.m8n8.x2.trans.shared.b16 {%0,%1},[%2];"
                 : "=r"(r0), "=r"(r1) : "r"(addr));
}
__device__ __forceinline__ void mma_bf16c(float* d, const uint32_t* a, const uint32_t* b) {
    asm volatile("mma.sync.aligned.m16n8k16.row.col.f32.bf16.bf16.f32 "
                 "{%0,%1,%2,%3},{%4,%5,%6,%7},{%8,%9},{%0,%1,%2,%3};"
                 : "+f"(d[0]), "+f"(d[1]), "+f"(d[2]), "+f"(d[3])
                 : "r"(a[0]), "r"(a[1]), "r"(a[2]), "r"(a[3]), "r"(b[0]), "r"(b[1]));
}

// ================= TC dual GEMM (layers 1-2), fp16 output ===================
// 2-product error-compensated: ah*wh + al*wh (A fully corrected; W keeps
// bf16-rn rounding ~2^-10 rms, attenuated ~70x downstream).
// RAW=true: A raw fp32, split in-register (layer 1). RAW=false: packed A.
template <bool RAW>
__global__ __launch_bounds__(256, 2) void k_gemm_tc2(
    const uint32_t* __restrict__ Ap, const float* __restrict__ Araw,
    const uint32_t* __restrict__ W1p, const uint32_t* __restrict__ W2p,
    __half* __restrict__ C1, __half* __restrict__ C2, int M)
{
    __shared__ __nv_bfloat16 Ah[64][40];
    __shared__ __nv_bfloat16 Al[64][40];
    __shared__ __nv_bfloat16 Wh[32][264];

    const int tid = threadIdx.x, lane = tid & 31, wid = tid >> 5;
    const int wm = wid & 1;
    const int wn = wid >> 1;
    const int r0 = blockIdx.x * 64;

    float d[2][8][4];
    #pragma unroll
    for (int i = 0; i < 2; i++)
        #pragma unroll
        for (int j = 0; j < 8; j++)
            #pragma unroll
            for (int k = 0; k < 4; k++) d[i][j][k] = 0.f;

    for (int kt = 0; kt < 4; kt++) {
        #pragma unroll
        for (int i = 0; i < 2; i++) {
            int idx = tid + i * 256;
            int row = idx >> 3, q = idx & 7;
            if (RAW) {
                float4 v = make_float4(0.f, 0.f, 0.f, 0.f);
                if (r0 + row < M)
                    v = *(const float4*)(Araw + (size_t)(r0 + row) * 128 + kt * 32 + q * 4);
                float ar[4] = {v.x, v.y, v.z, v.w};
                __nv_bfloat16 h[4], lo[4];
                #pragma unroll
                for (int j = 0; j < 4; j++) {
                    h[j] = __float2bfloat16(ar[j]);
                    lo[j] = __float2bfloat16(ar[j] - __bfloat162float(h[j]));
                }
                *(uint2*)&Ah[row][q * 4] = *(uint2*)h;
                *(uint2*)&Al[row][q * 4] = *(uint2*)lo;
            } else {
                uint4 p = make_uint4(0u, 0u, 0u, 0u);
                if (r0 + row < M)
                    p = *(const uint4*)(Ap + (size_t)(r0 + row) * 128 + kt * 32 + q * 4);
                uint2 hi, lo;
                hi.x = __byte_perm(p.x, p.y, 0x7632); hi.y = __byte_perm(p.z, p.w, 0x7632);
                lo.x = __byte_perm(p.x, p.y, 0x5410); lo.y = __byte_perm(p.z, p.w, 0x5410);
                *(uint2*)&Ah[row][q * 4] = hi;
                *(uint2*)&Al[row][q * 4] = lo;
            }
        }
        #pragma unroll
        for (int i = 0; i < 8; i++) {
            int idx = tid + i * 256;
            int k = idx >> 6, q = idx & 63;
            uint4 p = (q < 32)
                ? *(const uint4*)(W1p + (size_t)(kt * 32 + k) * 128 + q * 4)
                : *(const uint4*)(W2p + (size_t)(kt * 32 + k) * 128 + (q - 32) * 4);
            uint2 hi;
            hi.x = __byte_perm(p.x, p.y, 0x7632); hi.y = __byte_perm(p.z, p.w, 0x7632);
            *(uint2*)&Wh[k][q * 4] = hi;
        }
        __syncthreads();

        #pragma unroll
        for (int ph = 0; ph < 2; ph++) {
            const __nv_bfloat16 (*Asm)[40] = (ph == 1) ? Al : Ah;
            #pragma unroll
            for (int k16 = 0; k16 < 2; k16++) {
                uint32_t af[2][4], bfr[8][2];
                #pragma unroll
                for (int mf = 0; mf < 2; mf++) {
                    uint32_t addr = smem_u32(
                        &Asm[wm * 32 + mf * 16 + (lane & 15)][k16 * 16 + (lane >> 4) * 8]);
                    ldsm_x4(af[mf][0], af[mf][1], af[mf][2], af[mf][3], addr);
                }
                #pragma unroll
                for (int nf = 0; nf < 8; nf++) {
                    uint32_t addr = smem_u32(
                        &Wh[k16 * 16 + (lane & 15)][wn * 64 + nf * 8]);
                    ldsm_x2_t(bfr[nf][0], bfr[nf][1], addr);
                }
                #pragma unroll
                for (int mf = 0; mf < 2; mf++)
                    #pragma unroll
                    for (int nf = 0; nf < 8; nf++)
                        mma_bf16c(d[mf][nf], af[mf], bfr[nf]);
            }
        }
        __syncthreads();
    }

    const int g = lane >> 2, t = lane & 3;
    __half* Cp = (wn < 2) ? C1 : C2;
    int cbase = (wn < 2) ? wn * 64 : (wn - 2) * 64;
    #pragma unroll
    for (int mf = 0; mf < 2; mf++) {
        #pragma unroll
        for (int nf = 0; nf < 8; nf++) {
            int row0 = r0 + wm * 32 + mf * 16 + g;
            int col = cbase + nf * 8 + t * 2;
            if (row0 < M)
                *(__half2*)(Cp + (size_t)row0 * 128 + col) =
                    __floats2half2_rn(d[mf][nf][0], d[mf][nf][1]);
            if (row0 + 8 < M)
                *(__half2*)(Cp + (size_t)(row0 + 8) * 128 + col) =
                    __floats2half2_rn(d[mf][nf][2], d[mf][nf][3]);
        }
    }
}

// ================= TC dual GEMM layer 3 (N=40 padded to 64, fp32 out) =======
__global__ __launch_bounds__(256, 2) void k_gemm_tc3(
    const uint32_t* __restrict__ Ap, const uint32_t* __restrict__ W3p,
    float* __restrict__ C1, float* __restrict__ C2, int M)
{
    __shared__ __nv_bfloat16 Ah[64][40];
    __shared__ __nv_bfloat16 Al[64][40];
    __shared__ __nv_bfloat16 Wh[32][136];

    const int tid = threadIdx.x, lane = tid & 31, wid = tid >> 5;
    const int wm = wid & 1;
    const int wn = wid >> 1;
    const int r0 = blockIdx.x * 64;

    float d[2][4][4];
    #pragma unroll
    for (int i = 0; i < 2; i++)
        #pragma unroll
        for (int j = 0; j < 4; j++)
            #pragma unroll
            for (int k = 0; k < 4; k++) d[i][j][k] = 0.f;

    for (int kt = 0; kt < 4; kt++) {
        #pragma unroll
        for (int i = 0; i < 2; i++) {
            int idx = tid + i * 256;
            int row = idx >> 3, q = idx & 7;
            uint4 p = make_uint4(0u, 0u, 0u, 0u);
            if (r0 + row < M)
                p = *(const uint4*)(Ap + (size_t)(r0 + row) * 128 + kt * 32 + q * 4);
            uint2 hi, lo;
            hi.x = __byte_perm(p.x, p.y, 0x7632); hi.y = __byte_perm(p.z, p.w, 0x7632);
            lo.x = __byte_perm(p.x, p.y, 0x5410); lo.y = __byte_perm(p.z, p.w, 0x5410);
            *(uint2*)&Ah[row][q * 4] = hi;
            *(uint2*)&Al[row][q * 4] = lo;
        }
        #pragma unroll
        for (int i = 0; i < 4; i++) {
            int idx = tid + i * 256;
            int k = idx >> 5, q = idx & 31;
            const uint32_t* src = W3p + ((q >= 16) ? 8192 : 0)
                                + (size_t)(kt * 32 + k) * 64 + (q & 15) * 4;
            uint4 p = *(const uint4*)src;
            uint2 hi;
            hi.x = __byte_perm(p.x, p.y, 0x7632); hi.y = __byte_perm(p.z, p.w, 0x7632);
            *(uint2*)&Wh[k][q * 4] = hi;
        }
        __syncthreads();

        #pragma unroll
        for (int ph = 0; ph < 2; ph++) {
            const __nv_bfloat16 (*Asm)[40] = (ph == 1) ? Al : Ah;
            #pragma unroll
            for (int k16 = 0; k16 < 2; k16++) {
                uint32_t af[2][4], bfr[4][2];
                #pragma unroll
                for (int mf = 0; mf < 2; mf++) {
                    uint32_t addr = smem_u32(
                        &Asm[wm * 32 + mf * 16 + (lane & 15)][k16 * 16 + (lane >> 4) * 8]);
                    ldsm_x4(af[mf][0], af[mf][1], af[mf][2], af[mf][3], addr);
                }
                #pragma unroll
                for (int nf = 0; nf < 4; nf++) {
                    uint32_t addr = smem_u32(
                        &Wh[k16 * 16 + (lane & 15)][wn * 32 + nf * 8]);
                    ldsm_x2_t(bfr[nf][0], bfr[nf][1], addr);
                }
                #pragma unroll
                for (int mf = 0; mf < 2; mf++)
                    #pragma unroll
                    for (int nf = 0; nf < 4; nf++)
                        mma_bf16c(d[mf][nf], af[mf], bfr[nf]);
            }
        }
        __syncthreads();
    }

    const int g = lane >> 2, t = lane & 3;
    float* Cp = (wn < 2) ? C1 : C2;
    int cbase = (wn & 1) * 32;
    #pragma unroll
    for (int mf = 0; mf < 2; mf++) {
        #pragma unroll
        for (int nf = 0; nf < 4; nf++) {
            int row0 = r0 + wm * 32 + mf * 16 + g;
            int col = cbase + nf * 8 + t * 2;
            if (col >= 40) continue;
            if (row0 < M)
                *(float2*)(Cp + (size_t)row0 * 40 + col) = make_float2(d[mf][nf][0], d[mf][nf][1]);
            if (row0 + 8 < M)
                *(float2*)(Cp + (size_t)(row0 + 8) * 40 + col) = make_float2(d[mf][nf][2], d[mf][nf][3]);
        }
    }
}

// ================= node aggregation (H=4, F=32), half2 math, 2 edges/warp ===
__global__ __launch_bounds__(256) void k_node_h4(
    const uint4* __restrict__ glh, const uint4* __restrict__ grh,
    const float* __restrict__ att,
    const int* __restrict__ off, const int* __restrict__ deg,
    const int* __restrict__ eidx, uint4* __restrict__ houtp, int mode)
{
    int n = blockIdx.x * 8 + (threadIdx.x >> 5);
    if (n >= N_NODES) return;
    int lane = threadIdx.x & 31;
    int sub = lane >> 4;
    int ll = lane & 15;

    uint4 braw = grh[(size_t)n * 16 + ll];
    __half2 b2[4];
    b2[0] = *(__half2*)&braw.x; b2[1] = *(__half2*)&braw.y;
    b2[2] = *(__half2*)&braw.z; b2[3] = *(__half2*)&braw.w;

    float4 t0 = __ldg((const float4*)att + 2 * ll);
    float4 t1 = __ldg((const float4*)att + 2 * ll + 1);
    __half2 t2[4];
    t2[0] = __floats2half2_rn(t0.x, t0.y); t2[1] = __floats2half2_rn(t0.z, t0.w);
    t2[2] = __floats2half2_rn(t1.x, t1.y); t2[3] = __floats2half2_rn(t1.z, t1.w);

    const __half2 slope2 = __floats2half2_rn(SLOPE, SLOPE);

    float f[8];
    #pragma unroll
    for (int i = 0; i < 8; i++) f[i] = 0.f;
    float dw = 0.f;

    int start = off[n], cnt = deg[n];
    for (int base = 0; base < cnt; base += 32) {
        int rem = cnt - base;
        int m = rem < 32 ? rem : 32;
        int eld = (lane < m) ? __ldg(&eidx[start + base + lane]) : 0;
        int hm = (m + 1) >> 1;
        for (int j = 0; j < hm; j++) {
            int idx = 2 * j + sub;
            int s = __shfl_sync(0xffffffffu, eld, idx);
            uint4 araw = __ldg(&glh[(size_t)s * 16 + ll]);
            __half2 a2[4];
            a2[0] = *(__half2*)&araw.x; a2[1] = *(__half2*)&araw.y;
            a2[2] = *(__half2*)&araw.z; a2[3] = *(__half2*)&araw.w;

            __half2 acc = __floats2half2_rn(0.f, 0.f);
            #pragma unroll
            for (int i = 0; i < 4; i++) {
                __half2 s2 = __hadd2(a2[i], b2[i]);
                __half2 e2 = __hmax2(s2, __hmul2(s2, slope2));
                acc = __hfma2(e2, t2[i], acc);
            }
            float2 pf = __half22float2(acc);
            float p = pf.x + pf.y;
            p += __shfl_xor_sync(0xffffffffu, p, 2);
            p += __shfl_xor_sync(0xffffffffu, p, 1);
            float w = (idx < m) ? __expf(p) : 0.f;

            #pragma unroll
            for (int i = 0; i < 4; i++) {
                float2 af = __half22float2(a2[i]);
                f[2 * i]     += w * af.x;
                f[2 * i + 1] += w * af.y;
            }
            dw += w;
        }
    }

    #pragma unroll
    for (int i = 0; i < 8; i++) f[i] += __shfl_xor_sync(0xffffffffu, f[i], 16);
    dw += __shfl_xor_sync(0xffffffffu, dw, 16);

    if (sub == 0) {
        float inv = 1.0f / (dw + 1e-16f);
        uint32_t o[8];
        #pragma unroll
        for (int i = 0; i < 8; i++) {
            float v = f[i] * inv;
            if (mode == 1) v = v > 0.f ? v : expm1f(v);
            else           v = fmaxf(v, 0.f);
            o[i] = packsplit(v);
        }
        houtp[(size_t)n * 32 + 2 * ll]     = make_uint4(o[0], o[1], o[2], o[3]);
        houtp[(size_t)n * 32 + 2 * ll + 1] = make_uint4(o[4], o[5], o[6], o[7]);
    }
}

// ================= node layer 3 + log_softmax (H=1, F=40, fp32) =============
__global__ __launch_bounds__(256) void k_node_h1_lsm(
    const float4* __restrict__ gl4, const float4* __restrict__ gr4,
    const float* __restrict__ att,
    const int* __restrict__ off, const int* __restrict__ deg,
    const int* __restrict__ eidx, float* __restrict__ out)
{
    int n = blockIdx.x * 8 + (threadIdx.x >> 5);
    if (n >= N_NODES) return;
    int lane = threadIdx.x & 31;
    int sub = lane >> 4;
    int ll = lane & 15;

    float4 b = make_float4(0.f, 0.f, 0.f, 0.f), t = b;
    if (ll < 10) {
        b = gr4[(size_t)n * 10 + ll];
        t = __ldg(&((const float4*)att)[ll]);
    }

    float ax = 0.f, ay = 0.f, az = 0.f, aw = 0.f, dw = 0.f;

    int start = off[n], cnt = deg[n];
    for (int base = 0; base < cnt; base += 32) {
        int rem = cnt - base;
        int m = rem < 32 ? rem : 32;
        int eld = (lane < m) ? __ldg(&eidx[start + base + lane]) : 0;
        int hm = (m + 1) >> 1;
        for (int j = 0; j < hm; j++) {
            int idx = 2 * j + sub;
            int s = __shfl_sync(0xffffffffu, eld, idx);
            float4 a = make_float4(0.f, 0.f, 0.f, 0.f);
            float p = 0.f;
            if (ll < 10) {
                a = __ldg(&gl4[(size_t)s * 10 + ll]);
                float vx = a.x + b.x; vx = vx > 0.f ? vx : SLOPE * vx;
                float vy = a.y + b.y; vy = vy > 0.f ? vy : SLOPE * vy;
                float vz = a.z + b.z; vz = vz > 0.f ? vz : SLOPE * vz;
                float vw = a.w + b.w; vw = vw > 0.f ? vw : SLOPE * vw;
                p = vx * t.x + vy * t.y + vz * t.z + vw * t.w;
            }
            p += __shfl_xor_sync(0xffffffffu, p, 8, 16);
            p += __shfl_xor_sync(0xffffffffu, p, 4, 16);
            p += __shfl_xor_sync(0xffffffffu, p, 2, 16);
            p += __shfl_xor_sync(0xffffffffu, p, 1, 16);
            float w = (idx < m) ? __expf(p) : 0.f;
            ax += w * a.x; ay += w * a.y; az += w * a.z; aw += w * a.w;
            dw += w;
        }
    }

    ax += __shfl_xor_sync(0xffffffffu, ax, 16);
    ay += __shfl_xor_sync(0xffffffffu, ay, 16);
    az += __shfl_xor_sync(0xffffffffu, az, 16);
    aw += __shfl_xor_sync(0xffffffffu, aw, 16);
    dw += __shfl_xor_sync(0xffffffffu, dw, 16);

    float inv = 1.0f / (dw + 1e-16f);
    float4 v = make_float4(ax * inv, ay * inv, az * inv, aw * inv);

    float mx = (ll < 10) ? fmaxf(fmaxf(v.x, v.y), fmaxf(v.z, v.w)) : -FLT_MAX;
    #pragma unroll
    for (int o = 8; o > 0; o >>= 1) mx = fmaxf(mx, __shfl_xor_sync(0xffffffffu, mx, o, 16));
    float ss = (ll < 10)
        ? (expf(v.x - mx) + expf(v.y - mx) + expf(v.z - mx) + expf(v.w - mx)) : 0.f;
    #pragma unroll
    for (int o = 8; o > 0; o >>= 1) ss += __shfl_xor_sync(0xffffffffu, ss, o, 16);
    float lse = mx + logf(ss);
    if (sub == 0 && ll < 10) {
        float4 r = make_float4(v.x - lse, v.y - lse, v.z - lse, v.w - lse);
        *(float4*)(out + (size_t)n * 40 + 4 * ll) = r;
    }
}

// ---------------- host -------------------------------------------------------
extern "C" void kernel_launch(void* const* d_in, const int* in_sizes, int n_in,
                              void* d_out, int out_size)
{
    const float* x    = (const float*)d_in[0];
    const float* Wl1  = (const float*)d_in[1];
    const float* Wr1  = (const float*)d_in[2];
    const float* att1 = (const float*)d_in[3];
    const float* Wl2  = (const float*)d_in[4];
    const float* Wr2  = (const float*)d_in[5];
    const float* att2 = (const float*)d_in[6];
    const float* Wl3  = (const float*)d_in[7];
    const float* Wr3  = (const float*)d_in[8];
    const float* att3 = (const float*)d_in[9];
    const int*   ei   = (const int*)d_in[10];
    const int* src = ei;
    const int* dst = ei + N_EDGES;
    float* out = (float*)d_out;

    float *gl, *gr;
    uint32_t *hs, *ws, *w3s;
    int *deg, *off, *cur, *bsum, *eidx;
    cudaGetSymbolAddress((void**)&gl,   g_gl);
    cudaGetSymbolAddress((void**)&gr,   g_gr);
    cudaGetSymbolAddress((void**)&hs,   g_hs);
    cudaGetSymbolAddress((void**)&ws,   g_ws);
    cudaGetSymbolAddress((void**)&w3s,  g_w3s);
    cudaGetSymbolAddress((void**)&deg,  g_deg);
    cudaGetSymbolAddress((void**)&off,  g_off);
    cudaGetSymbolAddress((void**)&cur,  g_cur);
    cudaGetSymbolAddress((void**)&bsum, g_bsum);
    cudaGetSymbolAddress((void**)&eidx, g_eidx);

    __half* glh = (__half*)gl;
    __half* grh = (__half*)gr;

    const int GB = (N_NODES + 63) / 64;
    const int NB = (N_NODES + 7) / 8;
    const int NSCAN = (N_NODES + 1023) / 1024;

    static cudaStream_t s2 = nullptr;
    static cudaEvent_t evFork = nullptr, evJoin = nullptr;
    if (!s2) {
        cudaStreamCreateWithFlags(&s2, cudaStreamNonBlocking);
        cudaEventCreateWithFlags(&evFork, cudaEventDisableTiming);
        cudaEventCreateWithFlags(&evJoin, cudaEventDisableTiming);
    }

    // ---- fork: CSR build on s2, concurrent with weight split + layer-1 GEMM
    cudaEventRecord(evFork, 0);
    cudaStreamWaitEvent(s2, evFork, 0);
    cudaMemsetAsync(deg, 0, N_NODES * sizeof(int), s2);
    k_hist<<<(N_EDGES + 255) / 256, 256, 0, s2>>>(dst, deg);
    k_scan_part<<<NSCAN, 1024, 0, s2>>>(deg, off, bsum);
    k_scan_add<<<(N_NODES + 255) / 256, 256, 0, s2>>>(off, cur, bsum);
    k_scatter<<<(N_EDGES + 255) / 256, 256, 0, s2>>>(src, dst, cur, eidx);
    cudaEventRecord(evJoin, s2);

    // main stream: weight splits + layer-1 GEMM (reads raw fp32 x directly)
    k_split_w<<<80, 256>>>(Wl1, Wr1, Wl2, Wr2, ws, Wl3, Wr3, w3s);
    k_gemm_tc2<true><<<GB, 256>>>(nullptr, x, ws + 0 * 16384, ws + 1 * 16384,
                                  glh, grh, N_NODES);
    cudaStreamWaitEvent(0, evJoin, 0);

    // ---- Layer 1 aggregate ----
    k_node_h4<<<NB, 256>>>((const uint4*)glh, (const uint4*)grh, att1,
                           off, deg, eidx, (uint4*)hs, 1);
    // ---- Layer 2 ----
    k_gemm_tc2<false><<<GB, 256>>>(hs, nullptr, ws + 2 * 16384, ws + 3 * 16384,
                                   glh, grh, N_NODES);
    k_node_h4<<<NB, 256>>>((const uint4*)glh, (const uint4*)grh, att2,
                           off, deg, eidx, (uint4*)hs, 2);
    // ---- Layer 3 (TC GEMM, fp32 out; fused aggregate + log_softmax) ----
    k_gemm_tc3<<<GB, 256>>>(hs, w3s, gl, gr, N_NODES);
    k_node_h1_lsm<<<NB, 256>>>((const float4*)gl, (const float4*)gr, att3,
                               off, deg, eidx, out);
}